// round 11
// baseline (speedup 1.0000x reference)
#include <cuda_runtime.h>
#include <cuda_bf16.h>
#include <math.h>
#include <stdint.h>

#define NTOK 8192
#define DIN  1024
#define HID  4096
#define TOPKC 103
#define KTP  128
#define THRESH 2048

typedef __nv_bfloat16 bf16;

// ---------------- scratch ----------------------------------------------------
__device__ __align__(16) bf16 g_xhi[(size_t)NTOK*DIN];
__device__ __align__(16) bf16 g_xlo[(size_t)NTOK*DIN];
__device__ __align__(16) bf16 g_xq [(size_t)NTOK*DIN];
__device__ __align__(16) bf16 g_whi[(size_t)HID*DIN];   // permuted rows
__device__ __align__(16) bf16 g_wlo[(size_t)HID*DIN];   // permuted rows
__device__ __align__(16) bf16 g_wq [(size_t)HID*DIN];   // permuted rows
__device__ __align__(16) bf16 g_xthi[(size_t)NTOK*KTP];
__device__ __align__(16) bf16 g_xtlo[(size_t)NTOK*KTP];
__device__ __align__(16) bf16 g_wthi[(size_t)HID*KTP];
__device__ __align__(16) bf16 g_wtlo[(size_t)HID*KTP];
__device__ __align__(16) bf16 g_w2hi[(size_t)DIN*HID];  // permuted cols
__device__ __align__(16) bf16 g_w2lo[(size_t)DIN*HID];  // permuted cols
__device__ __align__(16) bf16 g_hhi[(size_t)NTOK*HID];  // permuted cols
__device__ __align__(16) bf16 g_hlo[(size_t)NTOK*HID];  // permuted cols
__device__ float g_sx[NTOK];
__device__ float g_qb[HID];
__device__ int   g_counts[HID];
__device__ int   g_nfp;
__device__ int   g_perm[HID];
__device__ int   g_inv[HID];
__device__ float g_b1p[HID], g_swp[HID], g_qbp[HID];
__device__ int   g_cntp[HID];

// ---------------- helpers ------------------------------------------------------
__device__ __forceinline__ uint32_t smem_u32(const void* p) {
    uint32_t a;
    asm("{ .reg .u64 t; cvta.to.shared.u64 t, %1; cvt.u32.u64 %0, t; }" : "=r"(a) : "l"(p));
    return a;
}
__device__ __forceinline__ void cpa(uint32_t s, const void* g) {
    asm volatile("cp.async.cg.shared.global [%0], [%1], 16;" :: "r"(s), "l"(g));
}
#define CP_COMMIT() asm volatile("cp.async.commit_group;" ::: "memory")
#define CP_WAIT(N)  asm volatile("cp.async.wait_group %0;" :: "n"(N) : "memory")

__device__ __forceinline__ void ldsm4(uint32_t* r, uint32_t addr) {
    asm volatile("ldmatrix.sync.aligned.m8n8.x4.shared.b16 {%0,%1,%2,%3}, [%4];"
        : "=r"(r[0]), "=r"(r[1]), "=r"(r[2]), "=r"(r[3]) : "r"(addr));
}
__device__ __forceinline__ void mma_bf16(float* c, const uint32_t* a, const uint32_t* b) {
    asm volatile("mma.sync.aligned.m16n8k16.row.col.f32.bf16.bf16.f32 "
        "{%0,%1,%2,%3}, {%4,%5,%6,%7}, {%8,%9}, {%0,%1,%2,%3};"
        : "+f"(c[0]), "+f"(c[1]), "+f"(c[2]), "+f"(c[3])
        : "r"(a[0]), "r"(a[1]), "r"(a[2]), "r"(a[3]), "r"(b[0]), "r"(b[1]));
}
__device__ __forceinline__ float gelu_exact(float v) {
    return 0.5f * v * (1.0f + erff(v * 0.70710678118654752440f));
}

#define ROWB 144
#define BUF  (128 * ROWB)      // BK=64 bf16 tiles (topk, g2)
#define ROWB32 80
#define BUF32  (128 * ROWB32)  // BK=32 bf16 tiles (g1)

// ================= G1: 3-stage pipeline, pass-major MMA ordering ================
// CTA 128(M) x 128(N), 8 warps (4m x 2n), warp tile 32x64, BK=32
__global__ void __launch_bounds__(256, 1)
g1_kernel() {
    extern __shared__ char dsm[];
    uint32_t sbase = (smem_u32(dsm) + 127u) & ~127u;
    const int i0 = blockIdx.y * 128, n0 = blockIdx.x * 128;
    const int tid = threadIdx.x, w = tid >> 5, lane = tid & 31;
    const int wm = w & 3, wn = w >> 2;
    const int NT = DIN / 32;          // 32
    const int STG = 6 * BUF32;        // 61440

    const int nfp = g_nfp;
    const bool tfp = (n0 < nfp);
    const bool tq  = (n0 + 128 > nfp);

    auto load_tile = [&](int kt, int st) {
        uint32_t sb = sbase + st * STG;
#pragma unroll
        for (int c = 0; c < 2; c++) {
            int idx = tid + c * 256, row = idx >> 2, c16 = idx & 3;
            uint32_t so = (uint32_t)(row * ROWB32 + c16 * 16);
            size_t ga = (size_t)(i0 + row) * DIN + kt * 32 + c16 * 8;
            size_t gb = (size_t)(n0 + row) * DIN + kt * 32 + c16 * 8;
            if (tfp) {
                cpa(sb + 0 * BUF32 + so, g_xhi + ga);
                cpa(sb + 1 * BUF32 + so, g_xlo + ga);
                cpa(sb + 3 * BUF32 + so, g_whi + gb);
                cpa(sb + 4 * BUF32 + so, g_wlo + gb);
            }
            if (tq) {
                cpa(sb + 2 * BUF32 + so, g_xq + ga);
                cpa(sb + 5 * BUF32 + so, g_wq + gb);
            }
        }
        CP_COMMIT();
    };

    uint32_t aRow[2], bRow[4];
#pragma unroll
    for (int mt = 0; mt < 2; mt++)
        aRow[mt] = (uint32_t)((wm * 32 + mt * 16 + (lane & 15)) * ROWB32);
#pragma unroll
    for (int p = 0; p < 4; p++)
        bRow[p] = (uint32_t)((wn * 64 + p * 16 + ((lane >> 4) << 3) + (lane & 7)) * ROWB32);
    uint32_t aK = (uint32_t)((lane >> 4) * 16);
    uint32_t bK = (uint32_t)(((lane >> 3) & 1) * 16);

    float accF[2][8][4], accQ[2][8][4];
#pragma unroll
    for (int mt = 0; mt < 2; mt++)
#pragma unroll
        for (int nt = 0; nt < 8; nt++)
#pragma unroll
            for (int r = 0; r < 4; r++) { accF[mt][nt][r] = 0.f; accQ[mt][nt][r] = 0.f; }

    load_tile(0, 0);
    load_tile(1, 1);
    int st = 0, stL = 2;
    for (int kt = 0; kt < NT; kt++) {
        if (kt + 1 < NT) CP_WAIT(1); else CP_WAIT(0);
        __syncthreads();
        if (kt + 2 < NT) load_tile(kt + 2, stL);
        uint32_t sb = sbase + st * STG;
#pragma unroll
        for (int kk = 0; kk < 2; kk++) {
            uint32_t ka = aK + kk * 32;
            uint32_t kb = bK + kk * 32;
            if (tfp) {
                uint32_t ah[2][4], al[2][4];
#pragma unroll
                for (int mt = 0; mt < 2; mt++) {
                    ldsm4(ah[mt], sb + 0 * BUF32 + aRow[mt] + ka);
                    ldsm4(al[mt], sb + 1 * BUF32 + aRow[mt] + ka);
                }
                uint32_t bh[8][2], bl[8][2];
#pragma unroll
                for (int p = 0; p < 4; p++) {
                    uint32_t t[4];
                    ldsm4(t, sb + 3 * BUF32 + bRow[p] + kb);
                    bh[2*p][0]=t[0]; bh[2*p][1]=t[1]; bh[2*p+1][0]=t[2]; bh[2*p+1][1]=t[3];
                    ldsm4(t, sb + 4 * BUF32 + bRow[p] + kb);
                    bl[2*p][0]=t[0]; bl[2*p][1]=t[1]; bl[2*p+1][0]=t[2]; bl[2*p+1][1]=t[3];
                }
                // pass-major: 16 independent MMAs between accumulator reuses
#pragma unroll
                for (int mt = 0; mt < 2; mt++)
#pragma unroll
                    for (int nt = 0; nt < 8; nt++)
                        mma_bf16(accF[mt][nt], ah[mt], bh[nt]);
#pragma unroll
                for (int mt = 0; mt < 2; mt++)
#pragma unroll
                    for (int nt = 0; nt < 8; nt++)
                        mma_bf16(accF[mt][nt], ah[mt], bl[nt]);
#pragma unroll
                for (int mt = 0; mt < 2; mt++)
#pragma unroll
                    for (int nt = 0; nt < 8; nt++)
                        mma_bf16(accF[mt][nt], al[mt], bh[nt]);
            }
            if (tq) {
                uint32_t aq[2][4];
#pragma unroll
                for (int mt = 0; mt < 2; mt++)
                    ldsm4(aq[mt], sb + 2 * BUF32 + aRow[mt] + ka);
                uint32_t bq[8][2];
#pragma unroll
                for (int p = 0; p < 4; p++) {
                    uint32_t t[4];
                    ldsm4(t, sb + 5 * BUF32 + bRow[p] + kb);
                    bq[2*p][0]=t[0]; bq[2*p][1]=t[1]; bq[2*p+1][0]=t[2]; bq[2*p+1][1]=t[3];
                }
#pragma unroll
                for (int mt = 0; mt < 2; mt++)
#pragma unroll
                    for (int nt = 0; nt < 8; nt++)
                        mma_bf16(accQ[mt][nt], aq[mt], bq[nt]);
            }
        }
        st = (st == 2) ? 0 : st + 1;
        stL = (stL == 2) ? 0 : stL + 1;
    }
    __syncthreads();

    __shared__ float sb1[128], ssw[128], sqb[128], ssx[128];
    __shared__ int scnt[128];
    if (tid < 128) {
        int h = n0 + tid;
        sb1[tid] = g_b1p[h]; ssw[tid] = g_swp[h]; sqb[tid] = g_qbp[h];
        scnt[tid] = g_cntp[h];
        ssx[tid] = g_sx[i0 + tid];
    }
    __syncthreads();

    int gq = lane >> 2, q4 = lane & 3;
#pragma unroll
    for (int mt = 0; mt < 2; mt++)
#pragma unroll
        for (int half = 0; half < 2; half++) {
            int rl = wm * 32 + mt * 16 + gq + half * 8;
            float sxv = ssx[rl];
            size_t ro = (size_t)(i0 + rl) * HID + n0;
#pragma unroll
            for (int nt = 0; nt < 8; nt++) {
                int cl = wn * 64 + nt * 8 + q4 * 2;
                float f0 = accF[mt][nt][half*2+0], f1 = accF[mt][nt][half*2+1];
                float q0 = accQ[mt][nt][half*2+0], q1 = accQ[mt][nt][half*2+1];
                float v0 = (scnt[cl]   > THRESH) ? (f0 + sb1[cl])
                          : fmaf(sxv * ssw[cl],   q0, sqb[cl]);
                float v1 = (scnt[cl+1] > THRESH) ? (f1 + sb1[cl+1])
                          : fmaf(sxv * ssw[cl+1], q1, sqb[cl+1]);
                float g0 = gelu_exact(v0), g1 = gelu_exact(v1);
                __nv_bfloat162 hi, lo;
                hi.x = __float2bfloat16(g0); hi.y = __float2bfloat16(g1);
                lo.x = __float2bfloat16(g0 - __bfloat162float(hi.x));
                lo.y = __float2bfloat16(g1 - __bfloat162float(hi.y));
                *(uint32_t*)(g_hhi + ro + cl) = *(uint32_t*)&hi;
                *(uint32_t*)(g_hlo + ro + cl) = *(uint32_t*)&lo;
            }
        }
}

// ================= topk: pass-major MMA ordering ================================
__global__ void __launch_bounds__(256, 1)
topk_kernel(const float* __restrict__ b1) {
    extern __shared__ char dsm[];
    uint32_t sbase = (smem_u32(dsm) + 127u) & ~127u;
    const int i0 = blockIdx.y * 128, n0 = blockIdx.x * 128;
    const int tid = threadIdx.x, w = tid >> 5, lane = tid & 31;
    const int wm = w & 3, wn = w >> 2;
    const int NT = 2;
    const int STG = 4 * BUF;

    auto load_tile = [&](int kt, int st) {
        uint32_t sb = sbase + st * STG;
#pragma unroll
        for (int c = 0; c < 4; c++) {
            int idx = tid + c * 256, row = idx >> 3, c16 = idx & 7;
            uint32_t so = (uint32_t)(row * ROWB + c16 * 16);
            size_t ga = (size_t)(i0 + row) * KTP + kt * 64 + c16 * 8;
            size_t gb = (size_t)(n0 + row) * KTP + kt * 64 + c16 * 8;
            cpa(sb + 0 * BUF + so, g_xthi + ga);
            cpa(sb + 1 * BUF + so, g_xtlo + ga);
            cpa(sb + 2 * BUF + so, g_wthi + gb);
            cpa(sb + 3 * BUF + so, g_wtlo + gb);
        }
        CP_COMMIT();
    };

    uint32_t aRow[2], bRow[4];
#pragma unroll
    for (int mt = 0; mt < 2; mt++)
        aRow[mt] = (uint32_t)((wm * 32 + mt * 16 + (lane & 15)) * ROWB);
#pragma unroll
    for (int p = 0; p < 4; p++)
        bRow[p] = (uint32_t)((wn * 64 + p * 16 + ((lane >> 4) << 3) + (lane & 7)) * ROWB);
    uint32_t aK = (uint32_t)((lane >> 4) * 16);
    uint32_t bK = (uint32_t)(((lane >> 3) & 1) * 16);

    float acc[2][8][4];
#pragma unroll
    for (int mt = 0; mt < 2; mt++)
#pragma unroll
        for (int nt = 0; nt < 8; nt++)
#pragma unroll
            for (int r = 0; r < 4; r++) acc[mt][nt][r] = 0.f;

    load_tile(0, 0);
    load_tile(1, 1);
    for (int kt = 0; kt < NT; kt++) {
        int st = kt & 1;
        CP_WAIT(0);
        __syncthreads();
        uint32_t sb = sbase + st * STG;
#pragma unroll
        for (int kk = 0; kk < 4; kk++) {
            uint32_t ka = aK + kk * 32;
            uint32_t kb = bK + kk * 32;
            uint32_t ah[2][4], al[2][4];
#pragma unroll
            for (int mt = 0; mt < 2; mt++) {
                ldsm4(ah[mt], sb + 0 * BUF + aRow[mt] + ka);
                ldsm4(al[mt], sb + 1 * BUF + aRow[mt] + ka);
            }
            uint32_t bh[8][2], bl[8][2];
#pragma unroll
            for (int p = 0; p < 4; p++) {
                uint32_t t[4];
                ldsm4(t, sb + 2 * BUF + bRow[p] + kb);
                bh[2*p][0]=t[0]; bh[2*p][1]=t[1]; bh[2*p+1][0]=t[2]; bh[2*p+1][1]=t[3];
                ldsm4(t, sb + 3 * BUF + bRow[p] + kb);
                bl[2*p][0]=t[0]; bl[2*p][1]=t[1]; bl[2*p+1][0]=t[2]; bl[2*p+1][1]=t[3];
            }
#pragma unroll
            for (int mt = 0; mt < 2; mt++)
#pragma unroll
                for (int nt = 0; nt < 8; nt++)
                    mma_bf16(acc[mt][nt], ah[mt], bh[nt]);
#pragma unroll
            for (int mt = 0; mt < 2; mt++)
#pragma unroll
                for (int nt = 0; nt < 8; nt++)
                    mma_bf16(acc[mt][nt], ah[mt], bl[nt]);
#pragma unroll
            for (int mt = 0; mt < 2; mt++)
#pragma unroll
                for (int nt = 0; nt < 8; nt++)
                    mma_bf16(acc[mt][nt], al[mt], bh[nt]);
        }
        __syncthreads();
    }

    __shared__ float sb1[128];
    __shared__ int scnt[128];
    if (tid < 128) { sb1[tid] = b1[n0 + tid]; scnt[tid] = 0; }
    __syncthreads();

    int q4 = lane & 3;
#pragma unroll
    for (int nt = 0; nt < 8; nt++) {
        int cl = wn * 64 + nt * 8 + q4 * 2;
        int c0 = 0, c1 = 0;
#pragma unroll
        for (int mt = 0; mt < 2; mt++)
#pragma unroll
            for (int half = 0; half < 2; half++) {
                c0 += (acc[mt][nt][half*2+0] + sb1[cl]   > 0.f);
                c1 += (acc[mt][nt][half*2+1] + sb1[cl+1] > 0.f);
            }
        atomicAdd(&scnt[cl],     c0);
        atomicAdd(&scnt[cl + 1], c1);
    }
    __syncthreads();
    if (tid < 128) atomicAdd(&g_counts[n0 + tid], scnt[tid]);
}

// ================= G2: 3-stage, pass-major MMA ordering ========================
__global__ void __launch_bounds__(256, 1)
g2_kernel(const float* __restrict__ b2, float* __restrict__ out) {
    extern __shared__ char dsm[];
    uint32_t sbase = (smem_u32(dsm) + 127u) & ~127u;
    const int i0 = blockIdx.y * 128, d0 = blockIdx.x * 128;
    const int tid = threadIdx.x, w = tid >> 5, lane = tid & 31;
    const int wm = w & 3, wn = w >> 2;
    const int NT = HID / 64;
    const int STG = 4 * BUF;

    auto load_tile = [&](int kt, int st) {
        uint32_t sb = sbase + st * STG;
#pragma unroll
        for (int c = 0; c < 4; c++) {
            int idx = tid + c * 256, row = idx >> 3, c16 = idx & 7;
            uint32_t so = (uint32_t)(row * ROWB + c16 * 16);
            size_t ga = (size_t)(i0 + row) * HID + kt * 64 + c16 * 8;
            size_t gb = (size_t)(d0 + row) * HID + kt * 64 + c16 * 8;
            cpa(sb + 0 * BUF + so, g_hhi  + ga);
            cpa(sb + 1 * BUF + so, g_hlo  + ga);
            cpa(sb + 2 * BUF + so, g_w2hi + gb);
            cpa(sb + 3 * BUF + so, g_w2lo + gb);
        }
        CP_COMMIT();
    };

    uint32_t aRow[2], bRow[4];
#pragma unroll
    for (int mt = 0; mt < 2; mt++)
        aRow[mt] = (uint32_t)((wm * 32 + mt * 16 + (lane & 15)) * ROWB);
#pragma unroll
    for (int p = 0; p < 4; p++)
        bRow[p] = (uint32_t)((wn * 64 + p * 16 + ((lane >> 4) << 3) + (lane & 7)) * ROWB);
    uint32_t aK = (uint32_t)((lane >> 4) * 16);
    uint32_t bK = (uint32_t)(((lane >> 3) & 1) * 16);

    float acc[2][8][4];
#pragma unroll
    for (int mt = 0; mt < 2; mt++)
#pragma unroll
        for (int nt = 0; nt < 8; nt++)
#pragma unroll
            for (int r = 0; r < 4; r++) acc[mt][nt][r] = 0.f;

    load_tile(0, 0);
    load_tile(1, 1);
    int st = 0, stL = 2;
    for (int kt = 0; kt < NT; kt++) {
        if (kt + 1 < NT) CP_WAIT(1); else CP_WAIT(0);
        __syncthreads();
        if (kt + 2 < NT) load_tile(kt + 2, stL);
        uint32_t sb = sbase + st * STG;
#pragma unroll
        for (int kk = 0; kk < 4; kk++) {
            uint32_t ka = aK + kk * 32;
            uint32_t kb = bK + kk * 32;
            uint32_t ah[2][4], al[2][4];
#pragma unroll
            for (int mt = 0; mt < 2; mt++) {
                ldsm4(ah[mt], sb + 0 * BUF + aRow[mt] + ka);
                ldsm4(al[mt], sb + 1 * BUF + aRow[mt] + ka);
            }
            uint32_t bh[8][2], bl[8][2];
#pragma unroll
            for (int p = 0; p < 4; p++) {
                uint32_t t[4];
                ldsm4(t, sb + 2 * BUF + bRow[p] + kb);
                bh[2*p][0]=t[0]; bh[2*p][1]=t[1]; bh[2*p+1][0]=t[2]; bh[2*p+1][1]=t[3];
                ldsm4(t, sb + 3 * BUF + bRow[p] + kb);
                bl[2*p][0]=t[0]; bl[2*p][1]=t[1]; bl[2*p+1][0]=t[2]; bl[2*p+1][1]=t[3];
            }
#pragma unroll
            for (int mt = 0; mt < 2; mt++)
#pragma unroll
                for (int nt = 0; nt < 8; nt++)
                    mma_bf16(acc[mt][nt], ah[mt], bh[nt]);
#pragma unroll
            for (int mt = 0; mt < 2; mt++)
#pragma unroll
                for (int nt = 0; nt < 8; nt++)
                    mma_bf16(acc[mt][nt], ah[mt], bl[nt]);
#pragma unroll
            for (int mt = 0; mt < 2; mt++)
#pragma unroll
                for (int nt = 0; nt < 8; nt++)
                    mma_bf16(acc[mt][nt], al[mt], bh[nt]);
        }
        st = (st == 2) ? 0 : st + 1;
        stL = (stL == 2) ? 0 : stL + 1;
    }
    __syncthreads();

    __shared__ float sbb[128];
    if (tid < 128) sbb[tid] = b2[d0 + tid];
    __syncthreads();

    int gq = lane >> 2, q4 = lane & 3;
#pragma unroll
    for (int mt = 0; mt < 2; mt++)
#pragma unroll
        for (int half = 0; half < 2; half++) {
            int rl = wm * 32 + mt * 16 + gq + half * 8;
            float* dst = out + (size_t)(i0 + rl) * DIN + d0;
#pragma unroll
            for (int nt = 0; nt < 8; nt++) {
                int cl = wn * 64 + nt * 8 + q4 * 2;
                float2 o = make_float2(acc[mt][nt][half*2+0] + sbb[cl],
                                       acc[mt][nt][half*2+1] + sbb[cl+1]);
                *(float2*)(dst + cl) = o;
            }
        }
}

// ---------------- prep kernels (identical to passing R10) -----------------------
__global__ void prep_x_kernel(const float* __restrict__ src) {
    int row = blockIdx.x, tid = threadIdx.x;
    const float* r = src + (size_t)row * DIN;
    float4 v = ((const float4*)r)[tid];
    float amax = fmaxf(fmaxf(fabsf(v.x), fabsf(v.y)), fmaxf(fabsf(v.z), fabsf(v.w)));
    __shared__ float red[256];
    red[tid] = amax; __syncthreads();
    for (int s = 128; s; s >>= 1) {
        if (tid < s) red[tid] = fmaxf(red[tid], red[tid + s]);
        __syncthreads();
    }
    float scale = fmaxf(red[0], 1e-5f) / 127.f;
    if (tid == 0) g_sx[row] = scale;
    float e[4] = {v.x, v.y, v.z, v.w};
    __nv_bfloat162 h2[2], l2[2], q2[2];
#pragma unroll
    for (int k = 0; k < 4; k++) {
        bf16 hb = __float2bfloat16(e[k]);
        bf16 lb = __float2bfloat16(e[k] - __bfloat162float(hb));
        float qq = fminf(127.f, fmaxf(-128.f, rintf(e[k] / scale)));
        bf16 qv = __float2bfloat16(qq);
        if (k & 1) { h2[k>>1].y = hb; l2[k>>1].y = lb; q2[k>>1].y = qv; }
        else       { h2[k>>1].x = hb; l2[k>>1].x = lb; q2[k>>1].x = qv; }
    }
    size_t o = (size_t)row * DIN + tid * 4;
    *(uint2*)(g_xhi + o) = make_uint2(*(uint32_t*)&h2[0], *(uint32_t*)&h2[1]);
    *(uint2*)(g_xlo + o) = make_uint2(*(uint32_t*)&l2[0], *(uint32_t*)&l2[1]);
    *(uint2*)(g_xq  + o) = make_uint2(*(uint32_t*)&q2[0], *(uint32_t*)&q2[1]);
    if (tid < KTP) {
        float val = (tid < TOPKC) ? r[tid] : 0.f;
        bf16 hb = __float2bfloat16(val);
        g_xthi[(size_t)row * KTP + tid] = hb;
        g_xtlo[(size_t)row * KTP + tid] = __float2bfloat16(val - __bfloat162float(hb));
    }
}

__global__ void prep_w1t_kernel(const float* __restrict__ W1) {
    int row = blockIdx.x, tid = threadIdx.x;  // 128 threads
    float val = (tid < TOPKC) ? W1[(size_t)row * DIN + tid] : 0.f;
    bf16 hb = __float2bfloat16(val);
    g_wthi[(size_t)row * KTP + tid] = hb;
    g_wtlo[(size_t)row * KTP + tid] = __float2bfloat16(val - __bfloat162float(hb));
}

__global__ void perm_build_kernel() {
    __shared__ int warpsum[32];
    int tid = threadIdx.x;
    int base = tid * 4;
    int f[4], s = 0;
#pragma unroll
    for (int k = 0; k < 4; k++) { f[k] = g_counts[base + k] > THRESH; s += f[k]; }
    int lane = tid & 31, wid = tid >> 5;
    int v = s;
#pragma unroll
    for (int o = 1; o < 32; o <<= 1) {
        int t = __shfl_up_sync(0xFFFFFFFF, v, o);
        if (lane >= o) v += t;
    }
    if (lane == 31) warpsum[wid] = v;
    __syncthreads();
    if (wid == 0) {
        int wv = warpsum[lane];
#pragma unroll
        for (int o = 1; o < 32; o <<= 1) {
            int t = __shfl_up_sync(0xFFFFFFFF, wv, o);
            if (lane >= o) wv += t;
        }
        warpsum[lane] = wv;
    }
    __syncthreads();
    int excl = v - s + (wid ? warpsum[wid - 1] : 0);
    int total = warpsum[31];
    if (tid == 0) g_nfp = total;
    int run = excl;
#pragma unroll
    for (int k = 0; k < 4; k++) {
        int r = base + k;
        int p = f[k] ? run : total + (r - run);
        g_perm[r] = p;
        g_inv[p] = r;
        run += f[k];
    }
}

__global__ void prep_w1_kernel(const float* __restrict__ W1, const float* __restrict__ b1) {
    int row = blockIdx.x, tid = threadIdx.x;
    int p = g_perm[row];
    const float* r = W1 + (size_t)row * DIN;
    float4 v = ((const float4*)r)[tid];
    float amax = fmaxf(fmaxf(fabsf(v.x), fabsf(v.y)), fmaxf(fabsf(v.z), fabsf(v.w)));
    __shared__ float red[256];
    red[tid] = amax; __syncthreads();
    for (int s = 128; s; s >>= 1) {
        if (tid < s) red[tid] = fmaxf(red[tid], red[tid + s]);
        __syncthreads();
    }
    float scale = fmaxf(red[0], 1e-5f) / 127.f;
    if (tid == 0) {
        g_swp[p] = scale;
        g_b1p[p] = b1[row];
        g_qbp[p] = g_qb[row];
        g_cntp[p] = g_counts[row];
    }
    float e[4] = {v.x, v.y, v.z, v.w};
    __nv_bfloat162 h2[2], l2[2], q2[2];
#pragma unroll
    for (int k = 0; k < 4; k++) {
        bf16 hb = __float2bfloat16(e[k]);
        bf16 lb = __float2bfloat16(e[k] - __bfloat162float(hb));
        float qq = fminf(127.f, fmaxf(-128.f, rintf(e[k] / scale)));
        bf16 qv = __float2bfloat16(qq);
        if (k & 1) { h2[k>>1].y = hb; l2[k>>1].y = lb; q2[k>>1].y = qv; }
        else       { h2[k>>1].x = hb; l2[k>>1].x = lb; q2[k>>1].x = qv; }
    }
    size_t o = (size_t)p * DIN + tid * 4;
    *(uint2*)(g_whi + o) = make_uint2(*(uint32_t*)&h2[0], *(uint32_t*)&h2[1]);
    *(uint2*)(g_wlo + o) = make_uint2(*(uint32_t*)&l2[0], *(uint32_t*)&l2[1]);
    *(uint2*)(g_wq  + o) = make_uint2(*(uint32_t*)&q2[0], *(uint32_t*)&q2[1]);
}

__global__ void prep_w2_kernel(const float* __restrict__ W2) {
    int row = blockIdx.x, tid = threadIdx.x;
    const float* r = W2 + (size_t)row * HID;
#pragma unroll
    for (int j = 0; j < 4; j++) {
        int nc = (tid + 256 * j) * 4;
        float e[4];
#pragma unroll
        for (int k = 0; k < 4; k++) e[k] = r[g_inv[nc + k]];
        __nv_bfloat162 h2[2], l2[2];
#pragma unroll
        for (int k = 0; k < 4; k++) {
            bf16 hb = __float2bfloat16(e[k]);
            bf16 lb = __float2bfloat16(e[k] - __bfloat162float(hb));
            if (k & 1) { h2[k>>1].y = hb; l2[k>>1].y = lb; }
            else       { h2[k>>1].x = hb; l2[k>>1].x = lb; }
        }
        size_t o = (size_t)row * HID + nc;
        *(uint2*)(g_w2hi + o) = make_uint2(*(uint32_t*)&h2[0], *(uint32_t*)&h2[1]);
        *(uint2*)(g_w2lo + o) = make_uint2(*(uint32_t*)&l2[0], *(uint32_t*)&l2[1]);
    }
}

__global__ void prep_b1_kernel(const float* __restrict__ b1) {
    __shared__ float red[256];
    int tid = threadIdx.x;
    float amax = 0.f;
    for (int i = tid; i < HID; i += 256) amax = fmaxf(amax, fabsf(b1[i]));
    red[tid] = amax; __syncthreads();
    for (int s = 128; s; s >>= 1) {
        if (tid < s) red[tid] = fmaxf(red[tid], red[tid + s]);
        __syncthreads();
    }
    float scale = fmaxf(red[0], 1e-5f) / 127.f;
    for (int i = tid; i < HID; i += 256) {
        g_qb[i] = fminf(127.f, fmaxf(-128.f, rintf(b1[i] / scale))) * scale;
        g_counts[i] = 0;
    }
}

// ---------------- launch -----------------------------------------------------------
extern "C" void kernel_launch(void* const* d_in, const int* in_sizes, int n_in,
                              void* d_out, int out_size) {
    const float* x  = (const float*)d_in[0];
    const float* W1 = (const float*)d_in[1];
    const float* b1 = (const float*)d_in[2];
    const float* W2 = (const float*)d_in[3];
    const float* b2 = (const float*)d_in[4];
    float* out = (float*)d_out;

    const int SM_G1 = 3 * 6 * BUF32 + 256;   // 184576
    const int SM_TK = 2 * 4 * BUF + 256;     // 147712
    const int SM_G2 = 3 * 4 * BUF + 256;     // 221440
    cudaFuncSetAttribute(g1_kernel,   cudaFuncAttributeMaxDynamicSharedMemorySize, SM_G1);
    cudaFuncSetAttribute(topk_kernel, cudaFuncAttributeMaxDynamicSharedMemorySize, SM_TK);
    cudaFuncSetAttribute(g2_kernel,   cudaFuncAttributeMaxDynamicSharedMemorySize, SM_G2);

    prep_b1_kernel<<<1, 256>>>(b1);
    prep_x_kernel<<<NTOK, 256>>>(x);
    prep_w1t_kernel<<<HID, 128>>>(W1);

    dim3 gt(HID / 128, NTOK / 128);          // (32, 64)
    topk_kernel<<<gt, 256, SM_TK>>>(b1);

    perm_build_kernel<<<1, 1024>>>();
    prep_w1_kernel<<<HID, 256>>>(W1, b1);
    prep_w2_kernel<<<DIN, 256>>>(W2);

    g1_kernel<<<gt, 256, SM_G1>>>();
    dim3 gg2(DIN / 128, NTOK / 128);         // (8, 64)
    g2_kernel<<<gg2, 256, SM_G2>>>(b2, out);
}

// round 12
// speedup vs baseline: 1.0343x; 1.0343x over previous
#include <cuda_runtime.h>
#include <cuda_bf16.h>
#include <math.h>
#include <stdint.h>

#define NTOK 8192
#define DIN  1024
#define HID  4096
#define TOPKC 103
#define KTP  128
#define THRESH 2048

typedef __nv_bfloat16 bf16;

// ---------------- scratch ----------------------------------------------------
__device__ __align__(16) bf16 g_xhi[(size_t)NTOK*DIN];
__device__ __align__(16) bf16 g_xlo[(size_t)NTOK*DIN];
__device__ __align__(16) bf16 g_xq [(size_t)NTOK*DIN];
__device__ __align__(16) bf16 g_whi[(size_t)HID*DIN];   // permuted rows
__device__ __align__(16) bf16 g_wlo[(size_t)HID*DIN];
__device__ __align__(16) bf16 g_wq [(size_t)HID*DIN];
__device__ __align__(16) bf16 g_xthi[(size_t)NTOK*KTP];
__device__ __align__(16) bf16 g_xtlo[(size_t)NTOK*KTP];
__device__ __align__(16) bf16 g_wthi[(size_t)HID*KTP];
__device__ __align__(16) bf16 g_wtlo[(size_t)HID*KTP];
__device__ __align__(16) bf16 g_w2hi[(size_t)DIN*HID];  // permuted cols
__device__ __align__(16) bf16 g_w2lo[(size_t)DIN*HID];
__device__ __align__(16) bf16 g_hhi[(size_t)NTOK*HID];  // permuted cols
__device__ __align__(16) bf16 g_hlo[(size_t)NTOK*HID];
__device__ float g_sx[NTOK];
__device__ float g_qb[HID];
__device__ int   g_counts[HID];
__device__ int   g_nfp;
__device__ int   g_perm[HID];
__device__ int   g_inv[HID];
__device__ float g_b1p[HID], g_swp[HID], g_qbp[HID];
__device__ int   g_cntp[HID];

// ---------------- helpers ------------------------------------------------------
__device__ __forceinline__ uint32_t smem_u32(const void* p) {
    uint32_t a;
    asm("{ .reg .u64 t; cvta.to.shared.u64 t, %1; cvt.u32.u64 %0, t; }" : "=r"(a) : "l"(p));
    return a;
}
__device__ __forceinline__ void cpa(uint32_t s, const void* g) {
    asm volatile("cp.async.cg.shared.global [%0], [%1], 16;" :: "r"(s), "l"(g));
}
#define CP_COMMIT() asm volatile("cp.async.commit_group;" ::: "memory")
#define CP_WAIT(N)  asm volatile("cp.async.wait_group %0;" :: "n"(N) : "memory")

__device__ __forceinline__ void ldsm4(uint32_t* r, uint32_t addr) {
    asm volatile("ldmatrix.sync.aligned.m8n8.x4.shared.b16 {%0,%1,%2,%3}, [%4];"
        : "=r"(r[0]), "=r"(r[1]), "=r"(r[2]), "=r"(r[3]) : "r"(addr));
}
__device__ __forceinline__ void mma_bf16(float* c, const uint32_t* a, const uint32_t* b) {
    asm volatile("mma.sync.aligned.m16n8k16.row.col.f32.bf16.bf16.f32 "
        "{%0,%1,%2,%3}, {%4,%5,%6,%7}, {%8,%9}, {%0,%1,%2,%3};"
        : "+f"(c[0]), "+f"(c[1]), "+f"(c[2]), "+f"(c[3])
        : "r"(a[0]), "r"(a[1]), "r"(a[2]), "r"(a[3]), "r"(b[0]), "r"(b[1]));
}
__device__ __forceinline__ float gelu_exact(float v) {
    return 0.5f * v * (1.0f + erff(v * 0.70710678118654752440f));
}

#define ROWB 144
#define BUF  (128 * ROWB)      // BK=64 bf16 tiles (topk, g2)
#define ROWB32 80
#define BUF32  (128 * ROWB32)  // BK=32 bf16 tiles (g1)

// ================= G1: 512 threads, 16 warps (4m x 4n), warp tile 32x32 =========
__global__ void __launch_bounds__(512, 1)
g1_kernel() {
    extern __shared__ char dsm[];
    uint32_t sbase = (smem_u32(dsm) + 127u) & ~127u;
    const int i0 = blockIdx.y * 128, n0 = blockIdx.x * 128;
    const int tid = threadIdx.x, w = tid >> 5, lane = tid & 31;
    const int wm = w & 3, wn = w >> 2;
    const int NT = DIN / 32;          // 32
    const int STG = 6 * BUF32;        // 61440

    const int nfp = g_nfp;
    const bool tfp = (n0 < nfp);
    const bool tq  = (n0 + 128 > nfp);

    auto load_tile = [&](int kt, int st) {
        uint32_t sb = sbase + st * STG;
        // one bf16 BK=32 buffer = 128 rows x 64B = 512 x 16B chunks = 512 threads x 1
        int row = tid >> 2, c16 = tid & 3;
        uint32_t so = (uint32_t)(row * ROWB32 + c16 * 16);
        size_t ga = (size_t)(i0 + row) * DIN + kt * 32 + c16 * 8;
        size_t gb = (size_t)(n0 + row) * DIN + kt * 32 + c16 * 8;
        if (tfp) {
            cpa(sb + 0 * BUF32 + so, g_xhi + ga);
            cpa(sb + 1 * BUF32 + so, g_xlo + ga);
            cpa(sb + 3 * BUF32 + so, g_whi + gb);
            cpa(sb + 4 * BUF32 + so, g_wlo + gb);
        }
        if (tq) {
            cpa(sb + 2 * BUF32 + so, g_xq + ga);
            cpa(sb + 5 * BUF32 + so, g_wq + gb);
        }
        CP_COMMIT();
    };

    uint32_t aRow[2], bRow[2];
#pragma unroll
    for (int mt = 0; mt < 2; mt++)
        aRow[mt] = (uint32_t)((wm * 32 + mt * 16 + (lane & 15)) * ROWB32);
#pragma unroll
    for (int p = 0; p < 2; p++)
        bRow[p] = (uint32_t)((wn * 32 + p * 16 + ((lane >> 4) << 3) + (lane & 7)) * ROWB32);
    uint32_t aK = (uint32_t)((lane >> 4) * 16);
    uint32_t bK = (uint32_t)(((lane >> 3) & 1) * 16);

    float accF[2][4][4], accQ[2][4][4];
#pragma unroll
    for (int mt = 0; mt < 2; mt++)
#pragma unroll
        for (int nt = 0; nt < 4; nt++)
#pragma unroll
            for (int r = 0; r < 4; r++) { accF[mt][nt][r] = 0.f; accQ[mt][nt][r] = 0.f; }

    load_tile(0, 0);
    load_tile(1, 1);
    int st = 0, stL = 2;
    for (int kt = 0; kt < NT; kt++) {
        if (kt + 1 < NT) CP_WAIT(1); else CP_WAIT(0);
        __syncthreads();
        if (kt + 2 < NT) load_tile(kt + 2, stL);
        uint32_t sb = sbase + st * STG;
#pragma unroll
        for (int kk = 0; kk < 2; kk++) {
            uint32_t ka = aK + kk * 32;
            uint32_t kb = bK + kk * 32;
            if (tfp) {
                uint32_t ah[2][4], al[2][4];
#pragma unroll
                for (int mt = 0; mt < 2; mt++) {
                    ldsm4(ah[mt], sb + 0 * BUF32 + aRow[mt] + ka);
                    ldsm4(al[mt], sb + 1 * BUF32 + aRow[mt] + ka);
                }
                uint32_t bh[4][2], bl[4][2];
#pragma unroll
                for (int p = 0; p < 2; p++) {
                    uint32_t t[4];
                    ldsm4(t, sb + 3 * BUF32 + bRow[p] + kb);
                    bh[2*p][0]=t[0]; bh[2*p][1]=t[1]; bh[2*p+1][0]=t[2]; bh[2*p+1][1]=t[3];
                    ldsm4(t, sb + 4 * BUF32 + bRow[p] + kb);
                    bl[2*p][0]=t[0]; bl[2*p][1]=t[1]; bl[2*p+1][0]=t[2]; bl[2*p+1][1]=t[3];
                }
#pragma unroll
                for (int mt = 0; mt < 2; mt++)
#pragma unroll
                    for (int nt = 0; nt < 4; nt++)
                        mma_bf16(accF[mt][nt], ah[mt], bh[nt]);
#pragma unroll
                for (int mt = 0; mt < 2; mt++)
#pragma unroll
                    for (int nt = 0; nt < 4; nt++)
                        mma_bf16(accF[mt][nt], ah[mt], bl[nt]);
#pragma unroll
                for (int mt = 0; mt < 2; mt++)
#pragma unroll
                    for (int nt = 0; nt < 4; nt++)
                        mma_bf16(accF[mt][nt], al[mt], bh[nt]);
            }
            if (tq) {
                uint32_t aq[2][4];
#pragma unroll
                for (int mt = 0; mt < 2; mt++)
                    ldsm4(aq[mt], sb + 2 * BUF32 + aRow[mt] + ka);
                uint32_t bq[4][2];
#pragma unroll
                for (int p = 0; p < 2; p++) {
                    uint32_t t[4];
                    ldsm4(t, sb + 5 * BUF32 + bRow[p] + kb);
                    bq[2*p][0]=t[0]; bq[2*p][1]=t[1]; bq[2*p+1][0]=t[2]; bq[2*p+1][1]=t[3];
                }
#pragma unroll
                for (int mt = 0; mt < 2; mt++)
#pragma unroll
                    for (int nt = 0; nt < 4; nt++)
                        mma_bf16(accQ[mt][nt], aq[mt], bq[nt]);
            }
        }
        st = (st == 2) ? 0 : st + 1;
        stL = (stL == 2) ? 0 : stL + 1;
    }
    __syncthreads();

    __shared__ float sb1[128], ssw[128], sqb[128], ssx[128];
    __shared__ int scnt[128];
    if (tid < 128) {
        int h = n0 + tid;
        sb1[tid] = g_b1p[h]; ssw[tid] = g_swp[h]; sqb[tid] = g_qbp[h];
        scnt[tid] = g_cntp[h];
        ssx[tid] = g_sx[i0 + tid];
    }
    __syncthreads();

    int gq = lane >> 2, q4 = lane & 3;
#pragma unroll
    for (int mt = 0; mt < 2; mt++)
#pragma unroll
        for (int half = 0; half < 2; half++) {
            int rl = wm * 32 + mt * 16 + gq + half * 8;
            float sxv = ssx[rl];
            size_t ro = (size_t)(i0 + rl) * HID + n0;
#pragma unroll
            for (int nt = 0; nt < 4; nt++) {
                int cl = wn * 32 + nt * 8 + q4 * 2;
                float f0 = accF[mt][nt][half*2+0], f1 = accF[mt][nt][half*2+1];
                float q0 = accQ[mt][nt][half*2+0], q1 = accQ[mt][nt][half*2+1];
                float v0 = (scnt[cl]   > THRESH) ? (f0 + sb1[cl])
                          : fmaf(sxv * ssw[cl],   q0, sqb[cl]);
                float v1 = (scnt[cl+1] > THRESH) ? (f1 + sb1[cl+1])
                          : fmaf(sxv * ssw[cl+1], q1, sqb[cl+1]);
                float g0 = gelu_exact(v0), g1 = gelu_exact(v1);
                __nv_bfloat162 hi, lo;
                hi.x = __float2bfloat16(g0); hi.y = __float2bfloat16(g1);
                lo.x = __float2bfloat16(g0 - __bfloat162float(hi.x));
                lo.y = __float2bfloat16(g1 - __bfloat162float(hi.y));
                *(uint32_t*)(g_hhi + ro + cl) = *(uint32_t*)&hi;
                *(uint32_t*)(g_hlo + ro + cl) = *(uint32_t*)&lo;
            }
        }
}

// ================= topk: 512 threads, 16 warps ================================
__global__ void __launch_bounds__(512, 1)
topk_kernel(const float* __restrict__ b1) {
    extern __shared__ char dsm[];
    uint32_t sbase = (smem_u32(dsm) + 127u) & ~127u;
    const int i0 = blockIdx.y * 128, n0 = blockIdx.x * 128;
    const int tid = threadIdx.x, w = tid >> 5, lane = tid & 31;
    const int wm = w & 3, wn = w >> 2;
    const int NT = 2;
    const int STG = 4 * BUF;

    auto load_tile = [&](int kt, int st) {
        uint32_t sb = sbase + st * STG;
#pragma unroll
        for (int c = 0; c < 2; c++) {
            int idx = tid + c * 512, row = idx >> 3, c16 = idx & 7;
            uint32_t so = (uint32_t)(row * ROWB + c16 * 16);
            size_t ga = (size_t)(i0 + row) * KTP + kt * 64 + c16 * 8;
            size_t gb = (size_t)(n0 + row) * KTP + kt * 64 + c16 * 8;
            cpa(sb + 0 * BUF + so, g_xthi + ga);
            cpa(sb + 1 * BUF + so, g_xtlo + ga);
            cpa(sb + 2 * BUF + so, g_wthi + gb);
            cpa(sb + 3 * BUF + so, g_wtlo + gb);
        }
        CP_COMMIT();
    };

    uint32_t aRow[2], bRow[2];
#pragma unroll
    for (int mt = 0; mt < 2; mt++)
        aRow[mt] = (uint32_t)((wm * 32 + mt * 16 + (lane & 15)) * ROWB);
#pragma unroll
    for (int p = 0; p < 2; p++)
        bRow[p] = (uint32_t)((wn * 32 + p * 16 + ((lane >> 4) << 3) + (lane & 7)) * ROWB);
    uint32_t aK = (uint32_t)((lane >> 4) * 16);
    uint32_t bK = (uint32_t)(((lane >> 3) & 1) * 16);

    float acc[2][4][4];
#pragma unroll
    for (int mt = 0; mt < 2; mt++)
#pragma unroll
        for (int nt = 0; nt < 4; nt++)
#pragma unroll
            for (int r = 0; r < 4; r++) acc[mt][nt][r] = 0.f;

    load_tile(0, 0);
    load_tile(1, 1);
    for (int kt = 0; kt < NT; kt++) {
        int st = kt & 1;
        CP_WAIT(0);
        __syncthreads();
        uint32_t sb = sbase + st * STG;
#pragma unroll
        for (int kk = 0; kk < 4; kk++) {
            uint32_t ka = aK + kk * 32;
            uint32_t kb = bK + kk * 32;
            uint32_t ah[2][4], al[2][4];
#pragma unroll
            for (int mt = 0; mt < 2; mt++) {
                ldsm4(ah[mt], sb + 0 * BUF + aRow[mt] + ka);
                ldsm4(al[mt], sb + 1 * BUF + aRow[mt] + ka);
            }
            uint32_t bh[4][2], bl[4][2];
#pragma unroll
            for (int p = 0; p < 2; p++) {
                uint32_t t[4];
                ldsm4(t, sb + 2 * BUF + bRow[p] + kb);
                bh[2*p][0]=t[0]; bh[2*p][1]=t[1]; bh[2*p+1][0]=t[2]; bh[2*p+1][1]=t[3];
                ldsm4(t, sb + 3 * BUF + bRow[p] + kb);
                bl[2*p][0]=t[0]; bl[2*p][1]=t[1]; bl[2*p+1][0]=t[2]; bl[2*p+1][1]=t[3];
            }
#pragma unroll
            for (int mt = 0; mt < 2; mt++)
#pragma unroll
                for (int nt = 0; nt < 4; nt++)
                    mma_bf16(acc[mt][nt], ah[mt], bh[nt]);
#pragma unroll
            for (int mt = 0; mt < 2; mt++)
#pragma unroll
                for (int nt = 0; nt < 4; nt++)
                    mma_bf16(acc[mt][nt], ah[mt], bl[nt]);
#pragma unroll
            for (int mt = 0; mt < 2; mt++)
#pragma unroll
                for (int nt = 0; nt < 4; nt++)
                    mma_bf16(acc[mt][nt], al[mt], bh[nt]);
        }
        __syncthreads();
    }

    __shared__ float sb1[128];
    __shared__ int scnt[128];
    if (tid < 128) { sb1[tid] = b1[n0 + tid]; scnt[tid] = 0; }
    __syncthreads();

    int q4 = lane & 3;
#pragma unroll
    for (int nt = 0; nt < 4; nt++) {
        int cl = wn * 32 + nt * 8 + q4 * 2;
        int c0 = 0, c1 = 0;
#pragma unroll
        for (int mt = 0; mt < 2; mt++)
#pragma unroll
            for (int half = 0; half < 2; half++) {
                c0 += (acc[mt][nt][half*2+0] + sb1[cl]   > 0.f);
                c1 += (acc[mt][nt][half*2+1] + sb1[cl+1] > 0.f);
            }
        atomicAdd(&scnt[cl],     c0);
        atomicAdd(&scnt[cl + 1], c1);
    }
    __syncthreads();
    if (tid < 128) atomicAdd(&g_counts[n0 + tid], scnt[tid]);
}

// ================= G2: 512 threads, 16 warps ===================================
__global__ void __launch_bounds__(512, 1)
g2_kernel(const float* __restrict__ b2, float* __restrict__ out) {
    extern __shared__ char dsm[];
    uint32_t sbase = (smem_u32(dsm) + 127u) & ~127u;
    const int i0 = blockIdx.y * 128, d0 = blockIdx.x * 128;
    const int tid = threadIdx.x, w = tid >> 5, lane = tid & 31;
    const int wm = w & 3, wn = w >> 2;
    const int NT = HID / 64;
    const int STG = 4 * BUF;

    auto load_tile = [&](int kt, int st) {
        uint32_t sb = sbase + st * STG;
#pragma unroll
        for (int c = 0; c < 2; c++) {
            int idx = tid + c * 512, row = idx >> 3, c16 = idx & 7;
            uint32_t so = (uint32_t)(row * ROWB + c16 * 16);
            size_t ga = (size_t)(i0 + row) * HID + kt * 64 + c16 * 8;
            size_t gb = (size_t)(d0 + row) * HID + kt * 64 + c16 * 8;
            cpa(sb + 0 * BUF + so, g_hhi  + ga);
            cpa(sb + 1 * BUF + so, g_hlo  + ga);
            cpa(sb + 2 * BUF + so, g_w2hi + gb);
            cpa(sb + 3 * BUF + so, g_w2lo + gb);
        }
        CP_COMMIT();
    };

    uint32_t aRow[2], bRow[2];
#pragma unroll
    for (int mt = 0; mt < 2; mt++)
        aRow[mt] = (uint32_t)((wm * 32 + mt * 16 + (lane & 15)) * ROWB);
#pragma unroll
    for (int p = 0; p < 2; p++)
        bRow[p] = (uint32_t)((wn * 32 + p * 16 + ((lane >> 4) << 3) + (lane & 7)) * ROWB);
    uint32_t aK = (uint32_t)((lane >> 4) * 16);
    uint32_t bK = (uint32_t)(((lane >> 3) & 1) * 16);

    float acc[2][4][4];
#pragma unroll
    for (int mt = 0; mt < 2; mt++)
#pragma unroll
        for (int nt = 0; nt < 4; nt++)
#pragma unroll
            for (int r = 0; r < 4; r++) acc[mt][nt][r] = 0.f;

    load_tile(0, 0);
    load_tile(1, 1);
    int st = 0, stL = 2;
    for (int kt = 0; kt < NT; kt++) {
        if (kt + 1 < NT) CP_WAIT(1); else CP_WAIT(0);
        __syncthreads();
        if (kt + 2 < NT) load_tile(kt + 2, stL);
        uint32_t sb = sbase + st * STG;
#pragma unroll
        for (int kk = 0; kk < 4; kk++) {
            uint32_t ka = aK + kk * 32;
            uint32_t kb = bK + kk * 32;
            uint32_t ah[2][4], al[2][4];
#pragma unroll
            for (int mt = 0; mt < 2; mt++) {
                ldsm4(ah[mt], sb + 0 * BUF + aRow[mt] + ka);
                ldsm4(al[mt], sb + 1 * BUF + aRow[mt] + ka);
            }
            uint32_t bh[4][2], bl[4][2];
#pragma unroll
            for (int p = 0; p < 2; p++) {
                uint32_t t[4];
                ldsm4(t, sb + 2 * BUF + bRow[p] + kb);
                bh[2*p][0]=t[0]; bh[2*p][1]=t[1]; bh[2*p+1][0]=t[2]; bh[2*p+1][1]=t[3];
                ldsm4(t, sb + 3 * BUF + bRow[p] + kb);
                bl[2*p][0]=t[0]; bl[2*p][1]=t[1]; bl[2*p+1][0]=t[2]; bl[2*p+1][1]=t[3];
            }
#pragma unroll
            for (int mt = 0; mt < 2; mt++)
#pragma unroll
                for (int nt = 0; nt < 4; nt++)
                    mma_bf16(acc[mt][nt], ah[mt], bh[nt]);
#pragma unroll
            for (int mt = 0; mt < 2; mt++)
#pragma unroll
                for (int nt = 0; nt < 4; nt++)
                    mma_bf16(acc[mt][nt], ah[mt], bl[nt]);
#pragma unroll
            for (int mt = 0; mt < 2; mt++)
#pragma unroll
                for (int nt = 0; nt < 4; nt++)
                    mma_bf16(acc[mt][nt], al[mt], bh[nt]);
        }
        st = (st == 2) ? 0 : st + 1;
        stL = (stL == 2) ? 0 : stL + 1;
    }
    __syncthreads();

    __shared__ float sbb[128];
    if (tid < 128) sbb[tid] = b2[d0 + tid];
    __syncthreads();

    int gq = lane >> 2, q4 = lane & 3;
#pragma unroll
    for (int mt = 0; mt < 2; mt++)
#pragma unroll
        for (int half = 0; half < 2; half++) {
            int rl = wm * 32 + mt * 16 + gq + half * 8;
            float* dst = out + (size_t)(i0 + rl) * DIN + d0;
#pragma unroll
            for (int nt = 0; nt < 4; nt++) {
                int cl = wn * 32 + nt * 8 + q4 * 2;
                float2 o = make_float2(acc[mt][nt][half*2+0] + sbb[cl],
                                       acc[mt][nt][half*2+1] + sbb[cl+1]);
                *(float2*)(dst + cl) = o;
            }
        }
}

// ---------------- prep kernels (identical to passing R10/R11) -------------------
__global__ void prep_x_kernel(const float* __restrict__ src) {
    int row = blockIdx.x, tid = threadIdx.x;
    const float* r = src + (size_t)row * DIN;
    float4 v = ((const float4*)r)[tid];
    float amax = fmaxf(fmaxf(fabsf(v.x), fabsf(v.y)), fmaxf(fabsf(v.z), fabsf(v.w)));
    __shared__ float red[256];
    red[tid] = amax; __syncthreads();
    for (int s = 128; s; s >>= 1) {
        if (tid < s) red[tid] = fmaxf(red[tid], red[tid + s]);
        __syncthreads();
    }
    float scale = fmaxf(red[0], 1e-5f) / 127.f;
    if (tid == 0) g_sx[row] = scale;
    float e[4] = {v.x, v.y, v.z, v.w};
    __nv_bfloat162 h2[2], l2[2], q2[2];
#pragma unroll
    for (int k = 0; k < 4; k++) {
        bf16 hb = __float2bfloat16(e[k]);
        bf16 lb = __float2bfloat16(e[k] - __bfloat162float(hb));
        float qq = fminf(127.f, fmaxf(-128.f, rintf(e[k] / scale)));
        bf16 qv = __float2bfloat16(qq);
        if (k & 1) { h2[k>>1].y = hb; l2[k>>1].y = lb; q2[k>>1].y = qv; }
        else       { h2[k>>1].x = hb; l2[k>>1].x = lb; q2[k>>1].x = qv; }
    }
    size_t o = (size_t)row * DIN + tid * 4;
    *(uint2*)(g_xhi + o) = make_uint2(*(uint32_t*)&h2[0], *(uint32_t*)&h2[1]);
    *(uint2*)(g_xlo + o) = make_uint2(*(uint32_t*)&l2[0], *(uint32_t*)&l2[1]);
    *(uint2*)(g_xq  + o) = make_uint2(*(uint32_t*)&q2[0], *(uint32_t*)&q2[1]);
    if (tid < KTP) {
        float val = (tid < TOPKC) ? r[tid] : 0.f;
        bf16 hb = __float2bfloat16(val);
        g_xthi[(size_t)row * KTP + tid] = hb;
        g_xtlo[(size_t)row * KTP + tid] = __float2bfloat16(val - __bfloat162float(hb));
    }
}

__global__ void prep_w1t_kernel(const float* __restrict__ W1) {
    int row = blockIdx.x, tid = threadIdx.x;  // 128 threads
    float val = (tid < TOPKC) ? W1[(size_t)row * DIN + tid] : 0.f;
    bf16 hb = __float2bfloat16(val);
    g_wthi[(size_t)row * KTP + tid] = hb;
    g_wtlo[(size_t)row * KTP + tid] = __float2bfloat16(val - __bfloat162float(hb));
}

__global__ void perm_build_kernel() {
    __shared__ int warpsum[32];
    int tid = threadIdx.x;
    int base = tid * 4;
    int f[4], s = 0;
#pragma unroll
    for (int k = 0; k < 4; k++) { f[k] = g_counts[base + k] > THRESH; s += f[k]; }
    int lane = tid & 31, wid = tid >> 5;
    int v = s;
#pragma unroll
    for (int o = 1; o < 32; o <<= 1) {
        int t = __shfl_up_sync(0xFFFFFFFF, v, o);
        if (lane >= o) v += t;
    }
    if (lane == 31) warpsum[wid] = v;
    __syncthreads();
    if (wid == 0) {
        int wv = warpsum[lane];
#pragma unroll
        for (int o = 1; o < 32; o <<= 1) {
            int t = __shfl_up_sync(0xFFFFFFFF, wv, o);
            if (lane >= o) wv += t;
        }
        warpsum[lane] = wv;
    }
    __syncthreads();
    int excl = v - s + (wid ? warpsum[wid - 1] : 0);
    int total = warpsum[31];
    if (tid == 0) g_nfp = total;
    int run = excl;
#pragma unroll
    for (int k = 0; k < 4; k++) {
        int r = base + k;
        int p = f[k] ? run : total + (r - run);
        g_perm[r] = p;
        g_inv[p] = r;
        run += f[k];
    }
}

__global__ void prep_w1_kernel(const float* __restrict__ W1, const float* __restrict__ b1) {
    int row = blockIdx.x, tid = threadIdx.x;
    int p = g_perm[row];
    const float* r = W1 + (size_t)row * DIN;
    float4 v = ((const float4*)r)[tid];
    float amax = fmaxf(fmaxf(fabsf(v.x), fabsf(v.y)), fmaxf(fabsf(v.z), fabsf(v.w)));
    __shared__ float red[256];
    red[tid] = amax; __syncthreads();
    for (int s = 128; s; s >>= 1) {
        if (tid < s) red[tid] = fmaxf(red[tid], red[tid + s]);
        __syncthreads();
    }
    float scale = fmaxf(red[0], 1e-5f) / 127.f;
    if (tid == 0) {
        g_swp[p] = scale;
        g_b1p[p] = b1[row];
        g_qbp[p] = g_qb[row];
        g_cntp[p] = g_counts[row];
    }
    float e[4] = {v.x, v.y, v.z, v.w};
    __nv_bfloat162 h2[2], l2[2], q2[2];
#pragma unroll
    for (int k = 0; k < 4; k++) {
        bf16 hb = __float2bfloat16(e[k]);
        bf16 lb = __float2bfloat16(e[k] - __bfloat162float(hb));
        float qq = fminf(127.f, fmaxf(-128.f, rintf(e[k] / scale)));
        bf16 qv = __float2bfloat16(qq);
        if (k & 1) { h2[k>>1].y = hb; l2[k>>1].y = lb; q2[k>>1].y = qv; }
        else       { h2[k>>1].x = hb; l2[k>>1].x = lb; q2[k>>1].x = qv; }
    }
    size_t o = (size_t)p * DIN + tid * 4;
    *(uint2*)(g_whi + o) = make_uint2(*(uint32_t*)&h2[0], *(uint32_t*)&h2[1]);
    *(uint2*)(g_wlo + o) = make_uint2(*(uint32_t*)&l2[0], *(uint32_t*)&l2[1]);
    *(uint2*)(g_wq  + o) = make_uint2(*(uint32_t*)&q2[0], *(uint32_t*)&q2[1]);
}

__global__ void prep_w2_kernel(const float* __restrict__ W2) {
    int row = blockIdx.x, tid = threadIdx.x;
    const float* r = W2 + (size_t)row * HID;
#pragma unroll
    for (int j = 0; j < 4; j++) {
        int nc = (tid + 256 * j) * 4;
        float e[4];
#pragma unroll
        for (int k = 0; k < 4; k++) e[k] = r[g_inv[nc + k]];
        __nv_bfloat162 h2[2], l2[2];
#pragma unroll
        for (int k = 0; k < 4; k++) {
            bf16 hb = __float2bfloat16(e[k]);
            bf16 lb = __float2bfloat16(e[k] - __bfloat162float(hb));
            if (k & 1) { h2[k>>1].y = hb; l2[k>>1].y = lb; }
            else       { h2[k>>1].x = hb; l2[k>>1].x = lb; }
        }
        size_t o = (size_t)row * HID + nc;
        *(uint2*)(g_w2hi + o) = make_uint2(*(uint32_t*)&h2[0], *(uint32_t*)&h2[1]);
        *(uint2*)(g_w2lo + o) = make_uint2(*(uint32_t*)&l2[0], *(uint32_t*)&l2[1]);
    }
}

__global__ void prep_b1_kernel(const float* __restrict__ b1) {
    __shared__ float red[256];
    int tid = threadIdx.x;
    float amax = 0.f;
    for (int i = tid; i < HID; i += 256) amax = fmaxf(amax, fabsf(b1[i]));
    red[tid] = amax; __syncthreads();
    for (int s = 128; s; s >>= 1) {
        if (tid < s) red[tid] = fmaxf(red[tid], red[tid + s]);
        __syncthreads();
    }
    float scale = fmaxf(red[0], 1e-5f) / 127.f;
    for (int i = tid; i < HID; i += 256) {
        g_qb[i] = fminf(127.f, fmaxf(-128.f, rintf(b1[i] / scale))) * scale;
        g_counts[i] = 0;
    }
}

// ---------------- launch -----------------------------------------------------------
extern "C" void kernel_launch(void* const* d_in, const int* in_sizes, int n_in,
                              void* d_out, int out_size) {
    const float* x  = (const float*)d_in[0];
    const float* W1 = (const float*)d_in[1];
    const float* b1 = (const float*)d_in[2];
    const float* W2 = (const float*)d_in[3];
    const float* b2 = (const float*)d_in[4];
    float* out = (float*)d_out;

    const int SM_G1 = 3 * 6 * BUF32 + 256;   // 184576
    const int SM_TK = 2 * 4 * BUF + 256;     // 147712
    const int SM_G2 = 3 * 4 * BUF + 256;     // 221440
    cudaFuncSetAttribute(g1_kernel,   cudaFuncAttributeMaxDynamicSharedMemorySize, SM_G1);
    cudaFuncSetAttribute(topk_kernel, cudaFuncAttributeMaxDynamicSharedMemorySize, SM_TK);
    cudaFuncSetAttribute(g2_kernel,   cudaFuncAttributeMaxDynamicSharedMemorySize, SM_G2);

    prep_b1_kernel<<<1, 256>>>(b1);
    prep_x_kernel<<<NTOK, 256>>>(x);
    prep_w1t_kernel<<<HID, 128>>>(W1);

    dim3 gt(HID / 128, NTOK / 128);          // (32, 64)
    topk_kernel<<<gt, 512, SM_TK>>>(b1);

    perm_build_kernel<<<1, 1024>>>();
    prep_w1_kernel<<<HID, 256>>>(W1, b1);
    prep_w2_kernel<<<DIN, 256>>>(W2);

    g1_kernel<<<gt, 512, SM_G1>>>();
    dim3 gg2(DIN / 128, NTOK / 128);         // (8, 64)
    g2_kernel<<<gg2, 512, SM_G2>>>(b2, out);
}

// round 13
// speedup vs baseline: 1.2082x; 1.1681x over previous
#include <cuda_runtime.h>
#include <cuda_bf16.h>
#include <cuda_fp16.h>
#include <math.h>
#include <stdint.h>

#define NTOK 8192
#define DIN  1024
#define HID  4096
#define TOPKC 103
#define KTP  128
#define THRESH 2048

typedef __nv_bfloat16 bf16;

// ---------------- scratch ----------------------------------------------------
__device__ __align__(16) bf16 g_xhi[(size_t)NTOK*DIN];
__device__ __align__(16) bf16 g_xlo[(size_t)NTOK*DIN];
__device__ __align__(16) bf16 g_xq [(size_t)NTOK*DIN];
__device__ __align__(16) bf16 g_whi[(size_t)HID*DIN];   // permuted rows
__device__ __align__(16) bf16 g_wlo[(size_t)HID*DIN];
__device__ __align__(16) bf16 g_wq [(size_t)HID*DIN];
__device__ __align__(16) bf16 g_xthi[(size_t)NTOK*KTP];
__device__ __align__(16) bf16 g_xtlo[(size_t)NTOK*KTP];
__device__ __align__(16) bf16 g_wthi[(size_t)HID*KTP];
__device__ __align__(16) bf16 g_wtlo[(size_t)HID*KTP];
__device__ __align__(16) __half g_w2h[(size_t)DIN*HID]; // permuted cols, fp16 hi
__device__ __align__(16) __half g_w2l[(size_t)DIN*HID]; // permuted cols, fp16 lo
__device__ __align__(16) __half g_hf [(size_t)NTOK*HID];// permuted cols, fp16
__device__ float g_sx[NTOK];
__device__ float g_qb[HID];
__device__ int   g_counts[HID];
__device__ int   g_nfp;
__device__ int   g_perm[HID];
__device__ int   g_inv[HID];
__device__ float g_b1p[HID], g_swp[HID], g_qbp[HID];
__device__ int   g_cntp[HID];

// ---------------- helpers ------------------------------------------------------
__device__ __forceinline__ uint32_t smem_u32(const void* p) {
    uint32_t a;
    asm("{ .reg .u64 t; cvta.to.shared.u64 t, %1; cvt.u32.u64 %0, t; }" : "=r"(a) : "l"(p));
    return a;
}
__device__ __forceinline__ void cpa(uint32_t s, const void* g) {
    asm volatile("cp.async.cg.shared.global [%0], [%1], 16;" :: "r"(s), "l"(g));
}
#define CP_COMMIT() asm volatile("cp.async.commit_group;" ::: "memory")
#define CP_WAIT(N)  asm volatile("cp.async.wait_group %0;" :: "n"(N) : "memory")

__device__ __forceinline__ void ldsm4(uint32_t* r, uint32_t addr) {
    asm volatile("ldmatrix.sync.aligned.m8n8.x4.shared.b16 {%0,%1,%2,%3}, [%4];"
        : "=r"(r[0]), "=r"(r[1]), "=r"(r[2]), "=r"(r[3]) : "r"(addr));
}
__device__ __forceinline__ void mma_bf16(float* c, const uint32_t* a, const uint32_t* b) {
    asm volatile("mma.sync.aligned.m16n8k16.row.col.f32.bf16.bf16.f32 "
        "{%0,%1,%2,%3}, {%4,%5,%6,%7}, {%8,%9}, {%0,%1,%2,%3};"
        : "+f"(c[0]), "+f"(c[1]), "+f"(c[2]), "+f"(c[3])
        : "r"(a[0]), "r"(a[1]), "r"(a[2]), "r"(a[3]), "r"(b[0]), "r"(b[1]));
}
__device__ __forceinline__ void mma_f16(float* c, const uint32_t* a, const uint32_t* b) {
    asm volatile("mma.sync.aligned.m16n8k16.row.col.f32.f16.f16.f32 "
        "{%0,%1,%2,%3}, {%4,%5,%6,%7}, {%8,%9}, {%0,%1,%2,%3};"
        : "+f"(c[0]), "+f"(c[1]), "+f"(c[2]), "+f"(c[3])
        : "r"(a[0]), "r"(a[1]), "r"(a[2]), "r"(a[3]), "r"(b[0]), "r"(b[1]));
}
__device__ __forceinline__ float gelu_exact(float v) {
    return 0.5f * v * (1.0f + erff(v * 0.70710678118654752440f));
}

#define ROWB 144
#define BUF  (128 * ROWB)      // BK=64 b16 tiles (topk, g2)
#define ROWB32 80
#define BUF32  (128 * ROWB32)  // BK=32 b16 tiles (g1)

// ================= G1: 512 threads, 16 warps (identical to passing R12,
//                  except epilogue stores h as single fp16) ====================
__global__ void __launch_bounds__(512, 1)
g1_kernel() {
    extern __shared__ char dsm[];
    uint32_t sbase = (smem_u32(dsm) + 127u) & ~127u;
    const int i0 = blockIdx.y * 128, n0 = blockIdx.x * 128;
    const int tid = threadIdx.x, w = tid >> 5, lane = tid & 31;
    const int wm = w & 3, wn = w >> 2;
    const int NT = DIN / 32;
    const int STG = 6 * BUF32;

    const int nfp = g_nfp;
    const bool tfp = (n0 < nfp);
    const bool tq  = (n0 + 128 > nfp);

    auto load_tile = [&](int kt, int st) {
        uint32_t sb = sbase + st * STG;
        int row = tid >> 2, c16 = tid & 3;
        uint32_t so = (uint32_t)(row * ROWB32 + c16 * 16);
        size_t ga = (size_t)(i0 + row) * DIN + kt * 32 + c16 * 8;
        size_t gb = (size_t)(n0 + row) * DIN + kt * 32 + c16 * 8;
        if (tfp) {
            cpa(sb + 0 * BUF32 + so, g_xhi + ga);
            cpa(sb + 1 * BUF32 + so, g_xlo + ga);
            cpa(sb + 3 * BUF32 + so, g_whi + gb);
            cpa(sb + 4 * BUF32 + so, g_wlo + gb);
        }
        if (tq) {
            cpa(sb + 2 * BUF32 + so, g_xq + ga);
            cpa(sb + 5 * BUF32 + so, g_wq + gb);
        }
        CP_COMMIT();
    };

    uint32_t aRow[2], bRow[2];
#pragma unroll
    for (int mt = 0; mt < 2; mt++)
        aRow[mt] = (uint32_t)((wm * 32 + mt * 16 + (lane & 15)) * ROWB32);
#pragma unroll
    for (int p = 0; p < 2; p++)
        bRow[p] = (uint32_t)((wn * 32 + p * 16 + ((lane >> 4) << 3) + (lane & 7)) * ROWB32);
    uint32_t aK = (uint32_t)((lane >> 4) * 16);
    uint32_t bK = (uint32_t)(((lane >> 3) & 1) * 16);

    float accF[2][4][4], accQ[2][4][4];
#pragma unroll
    for (int mt = 0; mt < 2; mt++)
#pragma unroll
        for (int nt = 0; nt < 4; nt++)
#pragma unroll
            for (int r = 0; r < 4; r++) { accF[mt][nt][r] = 0.f; accQ[mt][nt][r] = 0.f; }

    load_tile(0, 0);
    load_tile(1, 1);
    int st = 0, stL = 2;
    for (int kt = 0; kt < NT; kt++) {
        if (kt + 1 < NT) CP_WAIT(1); else CP_WAIT(0);
        __syncthreads();
        if (kt + 2 < NT) load_tile(kt + 2, stL);
        uint32_t sb = sbase + st * STG;
#pragma unroll
        for (int kk = 0; kk < 2; kk++) {
            uint32_t ka = aK + kk * 32;
            uint32_t kb = bK + kk * 32;
            if (tfp) {
                uint32_t ah[2][4], al[2][4];
#pragma unroll
                for (int mt = 0; mt < 2; mt++) {
                    ldsm4(ah[mt], sb + 0 * BUF32 + aRow[mt] + ka);
                    ldsm4(al[mt], sb + 1 * BUF32 + aRow[mt] + ka);
                }
                uint32_t bh[4][2], bl[4][2];
#pragma unroll
                for (int p = 0; p < 2; p++) {
                    uint32_t t[4];
                    ldsm4(t, sb + 3 * BUF32 + bRow[p] + kb);
                    bh[2*p][0]=t[0]; bh[2*p][1]=t[1]; bh[2*p+1][0]=t[2]; bh[2*p+1][1]=t[3];
                    ldsm4(t, sb + 4 * BUF32 + bRow[p] + kb);
                    bl[2*p][0]=t[0]; bl[2*p][1]=t[1]; bl[2*p+1][0]=t[2]; bl[2*p+1][1]=t[3];
                }
#pragma unroll
                for (int mt = 0; mt < 2; mt++)
#pragma unroll
                    for (int nt = 0; nt < 4; nt++)
                        mma_bf16(accF[mt][nt], ah[mt], bh[nt]);
#pragma unroll
                for (int mt = 0; mt < 2; mt++)
#pragma unroll
                    for (int nt = 0; nt < 4; nt++)
                        mma_bf16(accF[mt][nt], ah[mt], bl[nt]);
#pragma unroll
                for (int mt = 0; mt < 2; mt++)
#pragma unroll
                    for (int nt = 0; nt < 4; nt++)
                        mma_bf16(accF[mt][nt], al[mt], bh[nt]);
            }
            if (tq) {
                uint32_t aq[2][4];
#pragma unroll
                for (int mt = 0; mt < 2; mt++)
                    ldsm4(aq[mt], sb + 2 * BUF32 + aRow[mt] + ka);
                uint32_t bq[4][2];
#pragma unroll
                for (int p = 0; p < 2; p++) {
                    uint32_t t[4];
                    ldsm4(t, sb + 5 * BUF32 + bRow[p] + kb);
                    bq[2*p][0]=t[0]; bq[2*p][1]=t[1]; bq[2*p+1][0]=t[2]; bq[2*p+1][1]=t[3];
                }
#pragma unroll
                for (int mt = 0; mt < 2; mt++)
#pragma unroll
                    for (int nt = 0; nt < 4; nt++)
                        mma_bf16(accQ[mt][nt], aq[mt], bq[nt]);
            }
        }
        st = (st == 2) ? 0 : st + 1;
        stL = (stL == 2) ? 0 : stL + 1;
    }
    __syncthreads();

    __shared__ float sb1[128], ssw[128], sqb[128], ssx[128];
    __shared__ int scnt[128];
    if (tid < 128) {
        int h = n0 + tid;
        sb1[tid] = g_b1p[h]; ssw[tid] = g_swp[h]; sqb[tid] = g_qbp[h];
        scnt[tid] = g_cntp[h];
        ssx[tid] = g_sx[i0 + tid];
    }
    __syncthreads();

    int gq = lane >> 2, q4 = lane & 3;
#pragma unroll
    for (int mt = 0; mt < 2; mt++)
#pragma unroll
        for (int half = 0; half < 2; half++) {
            int rl = wm * 32 + mt * 16 + gq + half * 8;
            float sxv = ssx[rl];
            size_t ro = (size_t)(i0 + rl) * HID + n0;
#pragma unroll
            for (int nt = 0; nt < 4; nt++) {
                int cl = wn * 32 + nt * 8 + q4 * 2;
                float f0 = accF[mt][nt][half*2+0], f1 = accF[mt][nt][half*2+1];
                float q0 = accQ[mt][nt][half*2+0], q1 = accQ[mt][nt][half*2+1];
                float v0 = (scnt[cl]   > THRESH) ? (f0 + sb1[cl])
                          : fmaf(sxv * ssw[cl],   q0, sqb[cl]);
                float v1 = (scnt[cl+1] > THRESH) ? (f1 + sb1[cl+1])
                          : fmaf(sxv * ssw[cl+1], q1, sqb[cl+1]);
                float g0 = gelu_exact(v0), g1 = gelu_exact(v1);
                __half2 hp;
                hp.x = __float2half(g0); hp.y = __float2half(g1);
                *(uint32_t*)(g_hf + ro + cl) = *(uint32_t*)&hp;
            }
        }
}

// ================= topk: 512 threads (identical to passing R12) =================
__global__ void __launch_bounds__(512, 1)
topk_kernel(const float* __restrict__ b1) {
    extern __shared__ char dsm[];
    uint32_t sbase = (smem_u32(dsm) + 127u) & ~127u;
    const int i0 = blockIdx.y * 128, n0 = blockIdx.x * 128;
    const int tid = threadIdx.x, w = tid >> 5, lane = tid & 31;
    const int wm = w & 3, wn = w >> 2;
    const int NT = 2;
    const int STG = 4 * BUF;

    auto load_tile = [&](int kt, int st) {
        uint32_t sb = sbase + st * STG;
#pragma unroll
        for (int c = 0; c < 2; c++) {
            int idx = tid + c * 512, row = idx >> 3, c16 = idx & 7;
            uint32_t so = (uint32_t)(row * ROWB + c16 * 16);
            size_t ga = (size_t)(i0 + row) * KTP + kt * 64 + c16 * 8;
            size_t gb = (size_t)(n0 + row) * KTP + kt * 64 + c16 * 8;
            cpa(sb + 0 * BUF + so, g_xthi + ga);
            cpa(sb + 1 * BUF + so, g_xtlo + ga);
            cpa(sb + 2 * BUF + so, g_wthi + gb);
            cpa(sb + 3 * BUF + so, g_wtlo + gb);
        }
        CP_COMMIT();
    };

    uint32_t aRow[2], bRow[2];
#pragma unroll
    for (int mt = 0; mt < 2; mt++)
        aRow[mt] = (uint32_t)((wm * 32 + mt * 16 + (lane & 15)) * ROWB);
#pragma unroll
    for (int p = 0; p < 2; p++)
        bRow[p] = (uint32_t)((wn * 32 + p * 16 + ((lane >> 4) << 3) + (lane & 7)) * ROWB);
    uint32_t aK = (uint32_t)((lane >> 4) * 16);
    uint32_t bK = (uint32_t)(((lane >> 3) & 1) * 16);

    float acc[2][4][4];
#pragma unroll
    for (int mt = 0; mt < 2; mt++)
#pragma unroll
        for (int nt = 0; nt < 4; nt++)
#pragma unroll
            for (int r = 0; r < 4; r++) acc[mt][nt][r] = 0.f;

    load_tile(0, 0);
    load_tile(1, 1);
    for (int kt = 0; kt < NT; kt++) {
        int st = kt & 1;
        CP_WAIT(0);
        __syncthreads();
        uint32_t sb = sbase + st * STG;
#pragma unroll
        for (int kk = 0; kk < 4; kk++) {
            uint32_t ka = aK + kk * 32;
            uint32_t kb = bK + kk * 32;
            uint32_t ah[2][4], al[2][4];
#pragma unroll
            for (int mt = 0; mt < 2; mt++) {
                ldsm4(ah[mt], sb + 0 * BUF + aRow[mt] + ka);
                ldsm4(al[mt], sb + 1 * BUF + aRow[mt] + ka);
            }
            uint32_t bh[4][2], bl[4][2];
#pragma unroll
            for (int p = 0; p < 2; p++) {
                uint32_t t[4];
                ldsm4(t, sb + 2 * BUF + bRow[p] + kb);
                bh[2*p][0]=t[0]; bh[2*p][1]=t[1]; bh[2*p+1][0]=t[2]; bh[2*p+1][1]=t[3];
                ldsm4(t, sb + 3 * BUF + bRow[p] + kb);
                bl[2*p][0]=t[0]; bl[2*p][1]=t[1]; bl[2*p+1][0]=t[2]; bl[2*p+1][1]=t[3];
            }
#pragma unroll
            for (int mt = 0; mt < 2; mt++)
#pragma unroll
                for (int nt = 0; nt < 4; nt++)
                    mma_bf16(acc[mt][nt], ah[mt], bh[nt]);
#pragma unroll
            for (int mt = 0; mt < 2; mt++)
#pragma unroll
                for (int nt = 0; nt < 4; nt++)
                    mma_bf16(acc[mt][nt], ah[mt], bl[nt]);
#pragma unroll
            for (int mt = 0; mt < 2; mt++)
#pragma unroll
                for (int nt = 0; nt < 4; nt++)
                    mma_bf16(acc[mt][nt], al[mt], bh[nt]);
        }
        __syncthreads();
    }

    __shared__ float sb1[128];
    __shared__ int scnt[128];
    if (tid < 128) { sb1[tid] = b1[n0 + tid]; scnt[tid] = 0; }
    __syncthreads();

    int q4 = lane & 3;
#pragma unroll
    for (int nt = 0; nt < 4; nt++) {
        int cl = wn * 32 + nt * 8 + q4 * 2;
        int c0 = 0, c1 = 0;
#pragma unroll
        for (int mt = 0; mt < 2; mt++)
#pragma unroll
            for (int half = 0; half < 2; half++) {
                c0 += (acc[mt][nt][half*2+0] + sb1[cl]   > 0.f);
                c1 += (acc[mt][nt][half*2+1] + sb1[cl+1] > 0.f);
            }
        atomicAdd(&scnt[cl],     c0);
        atomicAdd(&scnt[cl + 1], c1);
    }
    __syncthreads();
    if (tid < 128) atomicAdd(&g_counts[n0 + tid], scnt[tid]);
}

// ================= G2: 2-pass fp16 (h single, W2 hi/lo), 3-buffer stages ========
__global__ void __launch_bounds__(512, 1)
g2_kernel(const float* __restrict__ b2, float* __restrict__ out) {
    extern __shared__ char dsm[];
    uint32_t sbase = (smem_u32(dsm) + 127u) & ~127u;
    const int i0 = blockIdx.y * 128, d0 = blockIdx.x * 128;
    const int tid = threadIdx.x, w = tid >> 5, lane = tid & 31;
    const int wm = w & 3, wn = w >> 2;
    const int NT = HID / 64;
    const int STG = 3 * BUF;   // hf, w2h, w2l

    auto load_tile = [&](int kt, int st) {
        uint32_t sb = sbase + st * STG;
#pragma unroll
        for (int c = 0; c < 2; c++) {
            int idx = tid + c * 512, row = idx >> 3, c16 = idx & 7;
            uint32_t so = (uint32_t)(row * ROWB + c16 * 16);
            size_t ga = (size_t)(i0 + row) * HID + kt * 64 + c16 * 8;
            size_t gb = (size_t)(d0 + row) * HID + kt * 64 + c16 * 8;
            cpa(sb + 0 * BUF + so, g_hf  + ga);
            cpa(sb + 1 * BUF + so, g_w2h + gb);
            cpa(sb + 2 * BUF + so, g_w2l + gb);
        }
        CP_COMMIT();
    };

    uint32_t aRow[2], bRow[2];
#pragma unroll
    for (int mt = 0; mt < 2; mt++)
        aRow[mt] = (uint32_t)((wm * 32 + mt * 16 + (lane & 15)) * ROWB);
#pragma unroll
    for (int p = 0; p < 2; p++)
        bRow[p] = (uint32_t)((wn * 32 + p * 16 + ((lane >> 4) << 3) + (lane & 7)) * ROWB);
    uint32_t aK = (uint32_t)((lane >> 4) * 16);
    uint32_t bK = (uint32_t)(((lane >> 3) & 1) * 16);

    float acc[2][4][4];
#pragma unroll
    for (int mt = 0; mt < 2; mt++)
#pragma unroll
        for (int nt = 0; nt < 4; nt++)
#pragma unroll
            for (int r = 0; r < 4; r++) acc[mt][nt][r] = 0.f;

    load_tile(0, 0);
    load_tile(1, 1);
    int st = 0, stL = 2;
    for (int kt = 0; kt < NT; kt++) {
        if (kt + 1 < NT) CP_WAIT(1); else CP_WAIT(0);
        __syncthreads();
        if (kt + 2 < NT) load_tile(kt + 2, stL);
        uint32_t sb = sbase + st * STG;
#pragma unroll
        for (int kk = 0; kk < 4; kk++) {
            uint32_t ka = aK + kk * 32;
            uint32_t kb = bK + kk * 32;
            uint32_t ah[2][4];
#pragma unroll
            for (int mt = 0; mt < 2; mt++)
                ldsm4(ah[mt], sb + 0 * BUF + aRow[mt] + ka);
            uint32_t bh[4][2], bl[4][2];
#pragma unroll
            for (int p = 0; p < 2; p++) {
                uint32_t t[4];
                ldsm4(t, sb + 1 * BUF + bRow[p] + kb);
                bh[2*p][0]=t[0]; bh[2*p][1]=t[1]; bh[2*p+1][0]=t[2]; bh[2*p+1][1]=t[3];
                ldsm4(t, sb + 2 * BUF + bRow[p] + kb);
                bl[2*p][0]=t[0]; bl[2*p][1]=t[1]; bl[2*p+1][0]=t[2]; bl[2*p+1][1]=t[3];
            }
#pragma unroll
            for (int mt = 0; mt < 2; mt++)
#pragma unroll
                for (int nt = 0; nt < 4; nt++)
                    mma_f16(acc[mt][nt], ah[mt], bh[nt]);
#pragma unroll
            for (int mt = 0; mt < 2; mt++)
#pragma unroll
                for (int nt = 0; nt < 4; nt++)
                    mma_f16(acc[mt][nt], ah[mt], bl[nt]);
        }
        st = (st == 2) ? 0 : st + 1;
        stL = (stL == 2) ? 0 : stL + 1;
    }
    __syncthreads();

    __shared__ float sbb[128];
    if (tid < 128) sbb[tid] = b2[d0 + tid];
    __syncthreads();

    int gq = lane >> 2, q4 = lane & 3;
#pragma unroll
    for (int mt = 0; mt < 2; mt++)
#pragma unroll
        for (int half = 0; half < 2; half++) {
            int rl = wm * 32 + mt * 16 + gq + half * 8;
            float* dst = out + (size_t)(i0 + rl) * DIN + d0;
#pragma unroll
            for (int nt = 0; nt < 4; nt++) {
                int cl = wn * 32 + nt * 8 + q4 * 2;
                float2 o = make_float2(acc[mt][nt][half*2+0] + sbb[cl],
                                       acc[mt][nt][half*2+1] + sbb[cl+1]);
                *(float2*)(dst + cl) = o;
            }
        }
}

// ---------------- prep kernels ---------------------------------------------------
__global__ void prep_x_kernel(const float* __restrict__ src) {
    int row = blockIdx.x, tid = threadIdx.x;
    const float* r = src + (size_t)row * DIN;
    float4 v = ((const float4*)r)[tid];
    float amax = fmaxf(fmaxf(fabsf(v.x), fabsf(v.y)), fmaxf(fabsf(v.z), fabsf(v.w)));
    __shared__ float red[256];
    red[tid] = amax; __syncthreads();
    for (int s = 128; s; s >>= 1) {
        if (tid < s) red[tid] = fmaxf(red[tid], red[tid + s]);
        __syncthreads();
    }
    float scale = fmaxf(red[0], 1e-5f) / 127.f;
    if (tid == 0) g_sx[row] = scale;
    float e[4] = {v.x, v.y, v.z, v.w};
    __nv_bfloat162 h2[2], l2[2], q2[2];
#pragma unroll
    for (int k = 0; k < 4; k++) {
        bf16 hb = __float2bfloat16(e[k]);
        bf16 lb = __float2bfloat16(e[k] - __bfloat162float(hb));
        float qq = fminf(127.f, fmaxf(-128.f, rintf(e[k] / scale)));
        bf16 qv = __float2bfloat16(qq);
        if (k & 1) { h2[k>>1].y = hb; l2[k>>1].y = lb; q2[k>>1].y = qv; }
        else       { h2[k>>1].x = hb; l2[k>>1].x = lb; q2[k>>1].x = qv; }
    }
    size_t o = (size_t)row * DIN + tid * 4;
    *(uint2*)(g_xhi + o) = make_uint2(*(uint32_t*)&h2[0], *(uint32_t*)&h2[1]);
    *(uint2*)(g_xlo + o) = make_uint2(*(uint32_t*)&l2[0], *(uint32_t*)&l2[1]);
    *(uint2*)(g_xq  + o) = make_uint2(*(uint32_t*)&q2[0], *(uint32_t*)&q2[1]);
    if (tid < KTP) {
        float val = (tid < TOPKC) ? r[tid] : 0.f;
        bf16 hb = __float2bfloat16(val);
        g_xthi[(size_t)row * KTP + tid] = hb;
        g_xtlo[(size_t)row * KTP + tid] = __float2bfloat16(val - __bfloat162float(hb));
    }
}

__global__ void prep_w1t_kernel(const float* __restrict__ W1) {
    int row = blockIdx.x, tid = threadIdx.x;  // 128 threads
    float val = (tid < TOPKC) ? W1[(size_t)row * DIN + tid] : 0.f;
    bf16 hb = __float2bfloat16(val);
    g_wthi[(size_t)row * KTP + tid] = hb;
    g_wtlo[(size_t)row * KTP + tid] = __float2bfloat16(val - __bfloat162float(hb));
}

__global__ void perm_build_kernel() {
    __shared__ int warpsum[32];
    int tid = threadIdx.x;
    int base = tid * 4;
    int f[4], s = 0;
#pragma unroll
    for (int k = 0; k < 4; k++) { f[k] = g_counts[base + k] > THRESH; s += f[k]; }
    int lane = tid & 31, wid = tid >> 5;
    int v = s;
#pragma unroll
    for (int o = 1; o < 32; o <<= 1) {
        int t = __shfl_up_sync(0xFFFFFFFF, v, o);
        if (lane >= o) v += t;
    }
    if (lane == 31) warpsum[wid] = v;
    __syncthreads();
    if (wid == 0) {
        int wv = warpsum[lane];
#pragma unroll
        for (int o = 1; o < 32; o <<= 1) {
            int t = __shfl_up_sync(0xFFFFFFFF, wv, o);
            if (lane >= o) wv += t;
        }
        warpsum[lane] = wv;
    }
    __syncthreads();
    int excl = v - s + (wid ? warpsum[wid - 1] : 0);
    int total = warpsum[31];
    if (tid == 0) g_nfp = total;
    int run = excl;
#pragma unroll
    for (int k = 0; k < 4; k++) {
        int r = base + k;
        int p = f[k] ? run : total + (r - run);
        g_perm[r] = p;
        g_inv[p] = r;
        run += f[k];
    }
}

__global__ void prep_w1_kernel(const float* __restrict__ W1, const float* __restrict__ b1) {
    int row = blockIdx.x, tid = threadIdx.x;
    int p = g_perm[row];
    const float* r = W1 + (size_t)row * DIN;
    float4 v = ((const float4*)r)[tid];
    float amax = fmaxf(fmaxf(fabsf(v.x), fabsf(v.y)), fmaxf(fabsf(v.z), fabsf(v.w)));
    __shared__ float red[256];
    red[tid] = amax; __syncthreads();
    for (int s = 128; s; s >>= 1) {
        if (tid < s) red[tid] = fmaxf(red[tid], red[tid + s]);
        __syncthreads();
    }
    float scale = fmaxf(red[0], 1e-5f) / 127.f;
    if (tid == 0) {
        g_swp[p] = scale;
        g_b1p[p] = b1[row];
        g_qbp[p] = g_qb[row];
        g_cntp[p] = g_counts[row];
    }
    float e[4] = {v.x, v.y, v.z, v.w};
    __nv_bfloat162 h2[2], l2[2], q2[2];
#pragma unroll
    for (int k = 0; k < 4; k++) {
        bf16 hb = __float2bfloat16(e[k]);
        bf16 lb = __float2bfloat16(e[k] - __bfloat162float(hb));
        float qq = fminf(127.f, fmaxf(-128.f, rintf(e[k] / scale)));
        bf16 qv = __float2bfloat16(qq);
        if (k & 1) { h2[k>>1].y = hb; l2[k>>1].y = lb; q2[k>>1].y = qv; }
        else       { h2[k>>1].x = hb; l2[k>>1].x = lb; q2[k>>1].x = qv; }
    }
    size_t o = (size_t)p * DIN + tid * 4;
    *(uint2*)(g_whi + o) = make_uint2(*(uint32_t*)&h2[0], *(uint32_t*)&h2[1]);
    *(uint2*)(g_wlo + o) = make_uint2(*(uint32_t*)&l2[0], *(uint32_t*)&l2[1]);
    *(uint2*)(g_wq  + o) = make_uint2(*(uint32_t*)&q2[0], *(uint32_t*)&q2[1]);
}

// W2 prep: permuted columns, fp16 hi/lo split
__global__ void prep_w2_kernel(const float* __restrict__ W2) {
    int row = blockIdx.x, tid = threadIdx.x;
    const float* r = W2 + (size_t)row * HID;
#pragma unroll
    for (int j = 0; j < 4; j++) {
        int nc = (tid + 256 * j) * 4;
        float e[4];
#pragma unroll
        for (int k = 0; k < 4; k++) e[k] = r[g_inv[nc + k]];
        __half2 h2[2], l2[2];
#pragma unroll
        for (int k = 0; k < 4; k++) {
            __half hb = __float2half(e[k]);
            __half lb = __float2half(e[k] - __half2float(hb));
            if (k & 1) { h2[k>>1].y = hb; l2[k>>1].y = lb; }
            else       { h2[k>>1].x = hb; l2[k>>1].x = lb; }
        }
        size_t o = (size_t)row * HID + nc;
        *(uint2*)(g_w2h + o) = make_uint2(*(uint32_t*)&h2[0], *(uint32_t*)&h2[1]);
        *(uint2*)(g_w2l + o) = make_uint2(*(uint32_t*)&l2[0], *(uint32_t*)&l2[1]);
    }
}

__global__ void prep_b1_kernel(const float* __restrict__ b1) {
    __shared__ float red[256];
    int tid = threadIdx.x;
    float amax = 0.f;
    for (int i = tid; i < HID; i += 256) amax = fmaxf(amax, fabsf(b1[i]));
    red[tid] = amax; __syncthreads();
    for (int s = 128; s; s >>= 1) {
        if (tid < s) red[tid] = fmaxf(red[tid], red[tid + s]);
        __syncthreads();
    }
    float scale = fmaxf(red[0], 1e-5f) / 127.f;
    for (int i = tid; i < HID; i += 256) {
        g_qb[i] = fminf(127.f, fmaxf(-128.f, rintf(b1[i] / scale))) * scale;
        g_counts[i] = 0;
    }
}

// ---------------- launch -----------------------------------------------------------
extern "C" void kernel_launch(void* const* d_in, const int* in_sizes, int n_in,
                              void* d_out, int out_size) {
    const float* x  = (const float*)d_in[0];
    const float* W1 = (const float*)d_in[1];
    const float* b1 = (const float*)d_in[2];
    const float* W2 = (const float*)d_in[3];
    const float* b2 = (const float*)d_in[4];
    float* out = (float*)d_out;

    const int SM_G1 = 3 * 6 * BUF32 + 256;   // 184576
    const int SM_TK = 2 * 4 * BUF + 256;     // 147712
    const int SM_G2 = 3 * 3 * BUF + 256;     // 166144
    cudaFuncSetAttribute(g1_kernel,   cudaFuncAttributeMaxDynamicSharedMemorySize, SM_G1);
    cudaFuncSetAttribute(topk_kernel, cudaFuncAttributeMaxDynamicSharedMemorySize, SM_TK);
    cudaFuncSetAttribute(g2_kernel,   cudaFuncAttributeMaxDynamicSharedMemorySize, SM_G2);

    prep_b1_kernel<<<1, 256>>>(b1);
    prep_x_kernel<<<NTOK, 256>>>(x);
    prep_w1t_kernel<<<HID, 128>>>(W1);

    dim3 gt(HID / 128, NTOK / 128);          // (32, 64)
    topk_kernel<<<gt, 512, SM_TK>>>(b1);

    perm_build_kernel<<<1, 1024>>>();
    prep_w1_kernel<<<HID, 256>>>(W1, b1);
    prep_w2_kernel<<<DIN, 256>>>(W2);

    g1_kernel<<<gt, 512, SM_G1>>>();
    dim3 gg2(DIN / 128, NTOK / 128);         // (8, 64)
    g2_kernel<<<gg2, 512, SM_G2>>>(b2, out);
}

// round 14
// speedup vs baseline: 1.4296x; 1.1832x over previous
#include <cuda_runtime.h>
#include <cuda_bf16.h>
#include <cuda_fp16.h>
#include <math.h>
#include <stdint.h>

#define NTOK 8192
#define DIN  1024
#define HID  4096
#define TOPKC 103
#define KTP  128
#define THRESH 2048

typedef __nv_bfloat16 bf16;

// ---------------- scratch ----------------------------------------------------
__device__ __align__(16) __half g_xf [(size_t)NTOK*DIN];  // x fp16
__device__ __align__(16) __half g_xq [(size_t)NTOK*DIN];  // quantized x (fp16, exact)
__device__ __align__(16) __half g_w1h[(size_t)HID*DIN];   // permuted W1 fp16 hi
__device__ __align__(16) __half g_w1l[(size_t)HID*DIN];   // permuted W1 fp16 lo
__device__ __align__(16) __half g_wq [(size_t)HID*DIN];   // permuted quantized W1
__device__ __align__(16) bf16 g_xthi[(size_t)NTOK*KTP];   // topk: exact bf16 split
__device__ __align__(16) bf16 g_xtlo[(size_t)NTOK*KTP];
__device__ __align__(16) bf16 g_wthi[(size_t)HID*KTP];
__device__ __align__(16) bf16 g_wtlo[(size_t)HID*KTP];
__device__ __align__(16) __half g_w2h[(size_t)DIN*HID];   // permuted cols, fp16 hi
__device__ __align__(16) __half g_w2l[(size_t)DIN*HID];   // permuted cols, fp16 lo
__device__ __align__(16) __half g_hf [(size_t)NTOK*HID];  // permuted cols, fp16
__device__ float g_sx[NTOK];
__device__ float g_qb[HID];
__device__ int   g_counts[HID];
__device__ int   g_nfp;
__device__ int   g_perm[HID];
__device__ int   g_inv[HID];
__device__ float g_b1p[HID], g_swp[HID], g_qbp[HID];
__device__ int   g_cntp[HID];

// ---------------- helpers ------------------------------------------------------
__device__ __forceinline__ uint32_t smem_u32(const void* p) {
    uint32_t a;
    asm("{ .reg .u64 t; cvta.to.shared.u64 t, %1; cvt.u32.u64 %0, t; }" : "=r"(a) : "l"(p));
    return a;
}
__device__ __forceinline__ void cpa(uint32_t s, const void* g) {
    asm volatile("cp.async.cg.shared.global [%0], [%1], 16;" :: "r"(s), "l"(g));
}
#define CP_COMMIT() asm volatile("cp.async.commit_group;" ::: "memory")
#define CP_WAIT(N)  asm volatile("cp.async.wait_group %0;" :: "n"(N) : "memory")

__device__ __forceinline__ void ldsm4(uint32_t* r, uint32_t addr) {
    asm volatile("ldmatrix.sync.aligned.m8n8.x4.shared.b16 {%0,%1,%2,%3}, [%4];"
        : "=r"(r[0]), "=r"(r[1]), "=r"(r[2]), "=r"(r[3]) : "r"(addr));
}
__device__ __forceinline__ void mma_bf16(float* c, const uint32_t* a, const uint32_t* b) {
    asm volatile("mma.sync.aligned.m16n8k16.row.col.f32.bf16.bf16.f32 "
        "{%0,%1,%2,%3}, {%4,%5,%6,%7}, {%8,%9}, {%0,%1,%2,%3};"
        : "+f"(c[0]), "+f"(c[1]), "+f"(c[2]), "+f"(c[3])
        : "r"(a[0]), "r"(a[1]), "r"(a[2]), "r"(a[3]), "r"(b[0]), "r"(b[1]));
}
__device__ __forceinline__ void mma_f16(float* c, const uint32_t* a, const uint32_t* b) {
    asm volatile("mma.sync.aligned.m16n8k16.row.col.f32.f16.f16.f32 "
        "{%0,%1,%2,%3}, {%4,%5,%6,%7}, {%8,%9}, {%0,%1,%2,%3};"
        : "+f"(c[0]), "+f"(c[1]), "+f"(c[2]), "+f"(c[3])
        : "r"(a[0]), "r"(a[1]), "r"(a[2]), "r"(a[3]), "r"(b[0]), "r"(b[1]));
}
__device__ __forceinline__ float gelu_exact(float v) {
    return 0.5f * v * (1.0f + erff(v * 0.70710678118654752440f));
}

#define ROWB 144
#define BUF  (128 * ROWB)      // BK=64 b16 tiles (topk, g2)
#define ROWB32 80
#define BUF32  (128 * ROWB32)  // BK=32 b16 tiles (g1)

// ================= G1: fp16 2-pass fp path + fp16 exact-q, 512 threads ==========
// buffers: 0 xf, 1 w1h, 2 w1l, 3 xq, 4 wq
__global__ void __launch_bounds__(512, 1)
g1_kernel() {
    extern __shared__ char dsm[];
    uint32_t sbase = (smem_u32(dsm) + 127u) & ~127u;
    const int i0 = blockIdx.y * 128, n0 = blockIdx.x * 128;
    const int tid = threadIdx.x, w = tid >> 5, lane = tid & 31;
    const int wm = w & 3, wn = w >> 2;
    const int NT = DIN / 32;
    const int STG = 5 * BUF32;   // 51200

    const int nfp = g_nfp;
    const bool tfp = (n0 < nfp);
    const bool tq  = (n0 + 128 > nfp);

    auto load_tile = [&](int kt, int st) {
        uint32_t sb = sbase + st * STG;
        int row = tid >> 2, c16 = tid & 3;
        uint32_t so = (uint32_t)(row * ROWB32 + c16 * 16);
        size_t ga = (size_t)(i0 + row) * DIN + kt * 32 + c16 * 8;
        size_t gb = (size_t)(n0 + row) * DIN + kt * 32 + c16 * 8;
        if (tfp) {
            cpa(sb + 0 * BUF32 + so, g_xf  + ga);
            cpa(sb + 1 * BUF32 + so, g_w1h + gb);
            cpa(sb + 2 * BUF32 + so, g_w1l + gb);
        }
        if (tq) {
            cpa(sb + 3 * BUF32 + so, g_xq + ga);
            cpa(sb + 4 * BUF32 + so, g_wq + gb);
        }
        CP_COMMIT();
    };

    uint32_t aRow[2], bRow[2];
#pragma unroll
    for (int mt = 0; mt < 2; mt++)
        aRow[mt] = (uint32_t)((wm * 32 + mt * 16 + (lane & 15)) * ROWB32);
#pragma unroll
    for (int p = 0; p < 2; p++)
        bRow[p] = (uint32_t)((wn * 32 + p * 16 + ((lane >> 4) << 3) + (lane & 7)) * ROWB32);
    uint32_t aK = (uint32_t)((lane >> 4) * 16);
    uint32_t bK = (uint32_t)(((lane >> 3) & 1) * 16);

    float accF[2][4][4], accQ[2][4][4];
#pragma unroll
    for (int mt = 0; mt < 2; mt++)
#pragma unroll
        for (int nt = 0; nt < 4; nt++)
#pragma unroll
            for (int r = 0; r < 4; r++) { accF[mt][nt][r] = 0.f; accQ[mt][nt][r] = 0.f; }

    load_tile(0, 0);
    load_tile(1, 1);
    int st = 0, stL = 2;
    for (int kt = 0; kt < NT; kt++) {
        if (kt + 1 < NT) CP_WAIT(1); else CP_WAIT(0);
        __syncthreads();
        if (kt + 2 < NT) load_tile(kt + 2, stL);
        uint32_t sb = sbase + st * STG;
#pragma unroll
        for (int kk = 0; kk < 2; kk++) {
            uint32_t ka = aK + kk * 32;
            uint32_t kb = bK + kk * 32;
            if (tfp) {
                uint32_t ax[2];
                uint32_t axf[2][4];
#pragma unroll
                for (int mt = 0; mt < 2; mt++)
                    ldsm4(axf[mt], sb + 0 * BUF32 + aRow[mt] + ka);
                (void)ax;
                uint32_t bh[4][2], bl[4][2];
#pragma unroll
                for (int p = 0; p < 2; p++) {
                    uint32_t t[4];
                    ldsm4(t, sb + 1 * BUF32 + bRow[p] + kb);
                    bh[2*p][0]=t[0]; bh[2*p][1]=t[1]; bh[2*p+1][0]=t[2]; bh[2*p+1][1]=t[3];
                    ldsm4(t, sb + 2 * BUF32 + bRow[p] + kb);
                    bl[2*p][0]=t[0]; bl[2*p][1]=t[1]; bl[2*p+1][0]=t[2]; bl[2*p+1][1]=t[3];
                }
#pragma unroll
                for (int mt = 0; mt < 2; mt++)
#pragma unroll
                    for (int nt = 0; nt < 4; nt++)
                        mma_f16(accF[mt][nt], axf[mt], bh[nt]);
#pragma unroll
                for (int mt = 0; mt < 2; mt++)
#pragma unroll
                    for (int nt = 0; nt < 4; nt++)
                        mma_f16(accF[mt][nt], axf[mt], bl[nt]);
            }
            if (tq) {
                uint32_t aq[2][4];
#pragma unroll
                for (int mt = 0; mt < 2; mt++)
                    ldsm4(aq[mt], sb + 3 * BUF32 + aRow[mt] + ka);
                uint32_t bq[4][2];
#pragma unroll
                for (int p = 0; p < 2; p++) {
                    uint32_t t[4];
                    ldsm4(t, sb + 4 * BUF32 + bRow[p] + kb);
                    bq[2*p][0]=t[0]; bq[2*p][1]=t[1]; bq[2*p+1][0]=t[2]; bq[2*p+1][1]=t[3];
                }
#pragma unroll
                for (int mt = 0; mt < 2; mt++)
#pragma unroll
                    for (int nt = 0; nt < 4; nt++)
                        mma_f16(accQ[mt][nt], aq[mt], bq[nt]);
            }
        }
        st = (st == 2) ? 0 : st + 1;
        stL = (stL == 2) ? 0 : stL + 1;
    }
    __syncthreads();

    __shared__ float sb1[128], ssw[128], sqb[128], ssx[128];
    __shared__ int scnt[128];
    if (tid < 128) {
        int h = n0 + tid;
        sb1[tid] = g_b1p[h]; ssw[tid] = g_swp[h]; sqb[tid] = g_qbp[h];
        scnt[tid] = g_cntp[h];
        ssx[tid] = g_sx[i0 + tid];
    }
    __syncthreads();

    int gq = lane >> 2, q4 = lane & 3;
#pragma unroll
    for (int mt = 0; mt < 2; mt++)
#pragma unroll
        for (int half = 0; half < 2; half++) {
            int rl = wm * 32 + mt * 16 + gq + half * 8;
            float sxv = ssx[rl];
            size_t ro = (size_t)(i0 + rl) * HID + n0;
#pragma unroll
            for (int nt = 0; nt < 4; nt++) {
                int cl = wn * 32 + nt * 8 + q4 * 2;
                float f0 = accF[mt][nt][half*2+0], f1 = accF[mt][nt][half*2+1];
                float q0 = accQ[mt][nt][half*2+0], q1 = accQ[mt][nt][half*2+1];
                float v0 = (scnt[cl]   > THRESH) ? (f0 + sb1[cl])
                          : fmaf(sxv * ssw[cl],   q0, sqb[cl]);
                float v1 = (scnt[cl+1] > THRESH) ? (f1 + sb1[cl+1])
                          : fmaf(sxv * ssw[cl+1], q1, sqb[cl+1]);
                float g0 = gelu_exact(v0), g1 = gelu_exact(v1);
                __half2 hp;
                hp.x = __float2half(g0); hp.y = __float2half(g1);
                *(uint32_t*)(g_hf + ro + cl) = *(uint32_t*)&hp;
            }
        }
}

// ================= topk: exact bf16 split, 512 threads (unchanged R12/R13) ======
__global__ void __launch_bounds__(512, 1)
topk_kernel(const float* __restrict__ b1) {
    extern __shared__ char dsm[];
    uint32_t sbase = (smem_u32(dsm) + 127u) & ~127u;
    const int i0 = blockIdx.y * 128, n0 = blockIdx.x * 128;
    const int tid = threadIdx.x, w = tid >> 5, lane = tid & 31;
    const int wm = w & 3, wn = w >> 2;
    const int NT = 2;
    const int STG = 4 * BUF;

    auto load_tile = [&](int kt, int st) {
        uint32_t sb = sbase + st * STG;
#pragma unroll
        for (int c = 0; c < 2; c++) {
            int idx = tid + c * 512, row = idx >> 3, c16 = idx & 7;
            uint32_t so = (uint32_t)(row * ROWB + c16 * 16);
            size_t ga = (size_t)(i0 + row) * KTP + kt * 64 + c16 * 8;
            size_t gb = (size_t)(n0 + row) * KTP + kt * 64 + c16 * 8;
            cpa(sb + 0 * BUF + so, g_xthi + ga);
            cpa(sb + 1 * BUF + so, g_xtlo + ga);
            cpa(sb + 2 * BUF + so, g_wthi + gb);
            cpa(sb + 3 * BUF + so, g_wtlo + gb);
        }
        CP_COMMIT();
    };

    uint32_t aRow[2], bRow[2];
#pragma unroll
    for (int mt = 0; mt < 2; mt++)
        aRow[mt] = (uint32_t)((wm * 32 + mt * 16 + (lane & 15)) * ROWB);
#pragma unroll
    for (int p = 0; p < 2; p++)
        bRow[p] = (uint32_t)((wn * 32 + p * 16 + ((lane >> 4) << 3) + (lane & 7)) * ROWB);
    uint32_t aK = (uint32_t)((lane >> 4) * 16);
    uint32_t bK = (uint32_t)(((lane >> 3) & 1) * 16);

    float acc[2][4][4];
#pragma unroll
    for (int mt = 0; mt < 2; mt++)
#pragma unroll
        for (int nt = 0; nt < 4; nt++)
#pragma unroll
            for (int r = 0; r < 4; r++) acc[mt][nt][r] = 0.f;

    load_tile(0, 0);
    load_tile(1, 1);
    for (int kt = 0; kt < NT; kt++) {
        int st = kt & 1;
        CP_WAIT(0);
        __syncthreads();
        uint32_t sb = sbase + st * STG;
#pragma unroll
        for (int kk = 0; kk < 4; kk++) {
            uint32_t ka = aK + kk * 32;
            uint32_t kb = bK + kk * 32;
            uint32_t ah[2][4], al[2][4];
#pragma unroll
            for (int mt = 0; mt < 2; mt++) {
                ldsm4(ah[mt], sb + 0 * BUF + aRow[mt] + ka);
                ldsm4(al[mt], sb + 1 * BUF + aRow[mt] + ka);
            }
            uint32_t bh[4][2], bl[4][2];
#pragma unroll
            for (int p = 0; p < 2; p++) {
                uint32_t t[4];
                ldsm4(t, sb + 2 * BUF + bRow[p] + kb);
                bh[2*p][0]=t[0]; bh[2*p][1]=t[1]; bh[2*p+1][0]=t[2]; bh[2*p+1][1]=t[3];
                ldsm4(t, sb + 3 * BUF + bRow[p] + kb);
                bl[2*p][0]=t[0]; bl[2*p][1]=t[1]; bl[2*p+1][0]=t[2]; bl[2*p+1][1]=t[3];
            }
#pragma unroll
            for (int mt = 0; mt < 2; mt++)
#pragma unroll
                for (int nt = 0; nt < 4; nt++)
                    mma_bf16(acc[mt][nt], ah[mt], bh[nt]);
#pragma unroll
            for (int mt = 0; mt < 2; mt++)
#pragma unroll
                for (int nt = 0; nt < 4; nt++)
                    mma_bf16(acc[mt][nt], ah[mt], bl[nt]);
#pragma unroll
            for (int mt = 0; mt < 2; mt++)
#pragma unroll
                for (int nt = 0; nt < 4; nt++)
                    mma_bf16(acc[mt][nt], al[mt], bh[nt]);
        }
        __syncthreads();
    }

    __shared__ float sb1[128];
    __shared__ int scnt[128];
    if (tid < 128) { sb1[tid] = b1[n0 + tid]; scnt[tid] = 0; }
    __syncthreads();

    int q4 = lane & 3;
#pragma unroll
    for (int nt = 0; nt < 4; nt++) {
        int cl = wn * 32 + nt * 8 + q4 * 2;
        int c0 = 0, c1 = 0;
#pragma unroll
        for (int mt = 0; mt < 2; mt++)
#pragma unroll
            for (int half = 0; half < 2; half++) {
                c0 += (acc[mt][nt][half*2+0] + sb1[cl]   > 0.f);
                c1 += (acc[mt][nt][half*2+1] + sb1[cl+1] > 0.f);
            }
        atomicAdd(&scnt[cl],     c0);
        atomicAdd(&scnt[cl + 1], c1);
    }
    __syncthreads();
    if (tid < 128) atomicAdd(&g_counts[n0 + tid], scnt[tid]);
}

// ================= G2: 2-pass fp16 (unchanged from passing R13) =================
__global__ void __launch_bounds__(512, 1)
g2_kernel(const float* __restrict__ b2, float* __restrict__ out) {
    extern __shared__ char dsm[];
    uint32_t sbase = (smem_u32(dsm) + 127u) & ~127u;
    const int i0 = blockIdx.y * 128, d0 = blockIdx.x * 128;
    const int tid = threadIdx.x, w = tid >> 5, lane = tid & 31;
    const int wm = w & 3, wn = w >> 2;
    const int NT = HID / 64;
    const int STG = 3 * BUF;

    auto load_tile = [&](int kt, int st) {
        uint32_t sb = sbase + st * STG;
#pragma unroll
        for (int c = 0; c < 2; c++) {
            int idx = tid + c * 512, row = idx >> 3, c16 = idx & 7;
            uint32_t so = (uint32_t)(row * ROWB + c16 * 16);
            size_t ga = (size_t)(i0 + row) * HID + kt * 64 + c16 * 8;
            size_t gb = (size_t)(d0 + row) * HID + kt * 64 + c16 * 8;
            cpa(sb + 0 * BUF + so, g_hf  + ga);
            cpa(sb + 1 * BUF + so, g_w2h + gb);
            cpa(sb + 2 * BUF + so, g_w2l + gb);
        }
        CP_COMMIT();
    };

    uint32_t aRow[2], bRow[2];
#pragma unroll
    for (int mt = 0; mt < 2; mt++)
        aRow[mt] = (uint32_t)((wm * 32 + mt * 16 + (lane & 15)) * ROWB);
#pragma unroll
    for (int p = 0; p < 2; p++)
        bRow[p] = (uint32_t)((wn * 32 + p * 16 + ((lane >> 4) << 3) + (lane & 7)) * ROWB);
    uint32_t aK = (uint32_t)((lane >> 4) * 16);
    uint32_t bK = (uint32_t)(((lane >> 3) & 1) * 16);

    float acc[2][4][4];
#pragma unroll
    for (int mt = 0; mt < 2; mt++)
#pragma unroll
        for (int nt = 0; nt < 4; nt++)
#pragma unroll
            for (int r = 0; r < 4; r++) acc[mt][nt][r] = 0.f;

    load_tile(0, 0);
    load_tile(1, 1);
    int st = 0, stL = 2;
    for (int kt = 0; kt < NT; kt++) {
        if (kt + 1 < NT) CP_WAIT(1); else CP_WAIT(0);
        __syncthreads();
        if (kt + 2 < NT) load_tile(kt + 2, stL);
        uint32_t sb = sbase + st * STG;
#pragma unroll
        for (int kk = 0; kk < 4; kk++) {
            uint32_t ka = aK + kk * 32;
            uint32_t kb = bK + kk * 32;
            uint32_t ah[2][4];
#pragma unroll
            for (int mt = 0; mt < 2; mt++)
                ldsm4(ah[mt], sb + 0 * BUF + aRow[mt] + ka);
            uint32_t bh[4][2], bl[4][2];
#pragma unroll
            for (int p = 0; p < 2; p++) {
                uint32_t t[4];
                ldsm4(t, sb + 1 * BUF + bRow[p] + kb);
                bh[2*p][0]=t[0]; bh[2*p][1]=t[1]; bh[2*p+1][0]=t[2]; bh[2*p+1][1]=t[3];
                ldsm4(t, sb + 2 * BUF + bRow[p] + kb);
                bl[2*p][0]=t[0]; bl[2*p][1]=t[1]; bl[2*p+1][0]=t[2]; bl[2*p+1][1]=t[3];
            }
#pragma unroll
            for (int mt = 0; mt < 2; mt++)
#pragma unroll
                for (int nt = 0; nt < 4; nt++)
                    mma_f16(acc[mt][nt], ah[mt], bh[nt]);
#pragma unroll
            for (int mt = 0; mt < 2; mt++)
#pragma unroll
                for (int nt = 0; nt < 4; nt++)
                    mma_f16(acc[mt][nt], ah[mt], bl[nt]);
        }
        st = (st == 2) ? 0 : st + 1;
        stL = (stL == 2) ? 0 : stL + 1;
    }
    __syncthreads();

    __shared__ float sbb[128];
    if (tid < 128) sbb[tid] = b2[d0 + tid];
    __syncthreads();

    int gq = lane >> 2, q4 = lane & 3;
#pragma unroll
    for (int mt = 0; mt < 2; mt++)
#pragma unroll
        for (int half = 0; half < 2; half++) {
            int rl = wm * 32 + mt * 16 + gq + half * 8;
            float* dst = out + (size_t)(i0 + rl) * DIN + d0;
#pragma unroll
            for (int nt = 0; nt < 4; nt++) {
                int cl = wn * 32 + nt * 8 + q4 * 2;
                float2 o = make_float2(acc[mt][nt][half*2+0] + sbb[cl],
                                       acc[mt][nt][half*2+1] + sbb[cl+1]);
                *(float2*)(dst + cl) = o;
            }
        }
}

// ---------------- prep kernels ---------------------------------------------------
__global__ void prep_x_kernel(const float* __restrict__ src) {
    int row = blockIdx.x, tid = threadIdx.x;
    const float* r = src + (size_t)row * DIN;
    float4 v = ((const float4*)r)[tid];
    float amax = fmaxf(fmaxf(fabsf(v.x), fabsf(v.y)), fmaxf(fabsf(v.z), fabsf(v.w)));
    __shared__ float red[256];
    red[tid] = amax; __syncthreads();
    for (int s = 128; s; s >>= 1) {
        if (tid < s) red[tid] = fmaxf(red[tid], red[tid + s]);
        __syncthreads();
    }
    float scale = fmaxf(red[0], 1e-5f) / 127.f;
    if (tid == 0) g_sx[row] = scale;
    float e[4] = {v.x, v.y, v.z, v.w};
    __half2 f2[2], q2[2];
#pragma unroll
    for (int k = 0; k < 4; k++) {
        __half fb = __float2half(e[k]);
        float qq = fminf(127.f, fmaxf(-128.f, rintf(e[k] / scale)));
        __half qv = __float2half(qq);
        if (k & 1) { f2[k>>1].y = fb; q2[k>>1].y = qv; }
        else       { f2[k>>1].x = fb; q2[k>>1].x = qv; }
    }
    size_t o = (size_t)row * DIN + tid * 4;
    *(uint2*)(g_xf + o) = make_uint2(*(uint32_t*)&f2[0], *(uint32_t*)&f2[1]);
    *(uint2*)(g_xq + o) = make_uint2(*(uint32_t*)&q2[0], *(uint32_t*)&q2[1]);
    if (tid < KTP) {
        float val = (tid < TOPKC) ? r[tid] : 0.f;
        bf16 hb = __float2bfloat16(val);
        g_xthi[(size_t)row * KTP + tid] = hb;
        g_xtlo[(size_t)row * KTP + tid] = __float2bfloat16(val - __bfloat162float(hb));
    }
}

__global__ void prep_w1t_kernel(const float* __restrict__ W1) {
    int row = blockIdx.x, tid = threadIdx.x;  // 128 threads
    float val = (tid < TOPKC) ? W1[(size_t)row * DIN + tid] : 0.f;
    bf16 hb = __float2bfloat16(val);
    g_wthi[(size_t)row * KTP + tid] = hb;
    g_wtlo[(size_t)row * KTP + tid] = __float2bfloat16(val - __bfloat162float(hb));
}

__global__ void perm_build_kernel() {
    __shared__ int warpsum[32];
    int tid = threadIdx.x;
    int base = tid * 4;
    int f[4], s = 0;
#pragma unroll
    for (int k = 0; k < 4; k++) { f[k] = g_counts[base + k] > THRESH; s += f[k]; }
    int lane = tid & 31, wid = tid >> 5;
    int v = s;
#pragma unroll
    for (int o = 1; o < 32; o <<= 1) {
        int t = __shfl_up_sync(0xFFFFFFFF, v, o);
        if (lane >= o) v += t;
    }
    if (lane == 31) warpsum[wid] = v;
    __syncthreads();
    if (wid == 0) {
        int wv = warpsum[lane];
#pragma unroll
        for (int o = 1; o < 32; o <<= 1) {
            int t = __shfl_up_sync(0xFFFFFFFF, wv, o);
            if (lane >= o) wv += t;
        }
        warpsum[lane] = wv;
    }
    __syncthreads();
    int excl = v - s + (wid ? warpsum[wid - 1] : 0);
    int total = warpsum[31];
    if (tid == 0) g_nfp = total;
    int run = excl;
#pragma unroll
    for (int k = 0; k < 4; k++) {
        int r = base + k;
        int p = f[k] ? run : total + (r - run);
        g_perm[r] = p;
        g_inv[p] = r;
        run += f[k];
    }
}

__global__ void prep_w1_kernel(const float* __restrict__ W1, const float* __restrict__ b1) {
    int row = blockIdx.x, tid = threadIdx.x;
    int p = g_perm[row];
    const float* r = W1 + (size_t)row * DIN;
    float4 v = ((const float4*)r)[tid];
    float amax = fmaxf(fmaxf(fabsf(v.x), fabsf(v.y)), fmaxf(fabsf(v.z), fabsf(v.w)));
    __shared__ float red[256];
    red[tid] = amax; __syncthreads();
    for (int s = 128; s; s >>= 1) {
        if (tid < s) red[tid] = fmaxf(red[tid], red[tid + s]);
        __syncthreads();
    }
    float scale = fmaxf(red[0], 1e-5f) / 127.f;
    if (tid == 0) {
        g_swp[p] = scale;
        g_b1p[p] = b1[row];
        g_qbp[p] = g_qb[row];
        g_cntp[p] = g_counts[row];
    }
    float e[4] = {v.x, v.y, v.z, v.w};
    __half2 h2[2], l2[2], q2[2];
#pragma unroll
    for (int k = 0; k < 4; k++) {
        __half hb = __float2half(e[k]);
        __half lb = __float2half(e[k] - __half2float(hb));
        float qq = fminf(127.f, fmaxf(-128.f, rintf(e[k] / scale)));
        __half qv = __float2half(qq);
        if (k & 1) { h2[k>>1].y = hb; l2[k>>1].y = lb; q2[k>>1].y = qv; }
        else       { h2[k>>1].x = hb; l2[k>>1].x = lb; q2[k>>1].x = qv; }
    }
    size_t o = (size_t)p * DIN + tid * 4;
    *(uint2*)(g_w1h + o) = make_uint2(*(uint32_t*)&h2[0], *(uint32_t*)&h2[1]);
    *(uint2*)(g_w1l + o) = make_uint2(*(uint32_t*)&l2[0], *(uint32_t*)&l2[1]);
    *(uint2*)(g_wq  + o) = make_uint2(*(uint32_t*)&q2[0], *(uint32_t*)&q2[1]);
}

__global__ void prep_w2_kernel(const float* __restrict__ W2) {
    int row = blockIdx.x, tid = threadIdx.x;
    const float* r = W2 + (size_t)row * HID;
#pragma unroll
    for (int j = 0; j < 4; j++) {
        int nc = (tid + 256 * j) * 4;
        float e[4];
#pragma unroll
        for (int k = 0; k < 4; k++) e[k] = r[g_inv[nc + k]];
        __half2 h2[2], l2[2];
#pragma unroll
        for (int k = 0; k < 4; k++) {
            __half hb = __float2half(e[k]);
            __half lb = __float2half(e[k] - __half2float(hb));
            if (k & 1) { h2[k>>1].y = hb; l2[k>>1].y = lb; }
            else       { h2[k>>1].x = hb; l2[k>>1].x = lb; }
        }
        size_t o = (size_t)row * HID + nc;
        *(uint2*)(g_w2h + o) = make_uint2(*(uint32_t*)&h2[0], *(uint32_t*)&h2[1]);
        *(uint2*)(g_w2l + o) = make_uint2(*(uint32_t*)&l2[0], *(uint32_t*)&l2[1]);
    }
}

__global__ void prep_b1_kernel(const float* __restrict__ b1) {
    __shared__ float red[256];
    int tid = threadIdx.x;
    float amax = 0.f;
    for (int i = tid; i < HID; i += 256) amax = fmaxf(amax, fabsf(b1[i]));
    red[tid] = amax; __syncthreads();
    for (int s = 128; s; s >>= 1) {
        if (tid < s) red[tid] = fmaxf(red[tid], red[tid + s]);
        __syncthreads();
    }
    float scale = fmaxf(red[0], 1e-5f) / 127.f;
    for (int i = tid; i < HID; i += 256) {
        g_qb[i] = fminf(127.f, fmaxf(-128.f, rintf(b1[i] / scale))) * scale;
        g_counts[i] = 0;
    }
}

// ---------------- launch -----------------------------------------------------------
extern "C" void kernel_launch(void* const* d_in, const int* in_sizes, int n_in,
                              void* d_out, int out_size) {
    const float* x  = (const float*)d_in[0];
    const float* W1 = (const float*)d_in[1];
    const float* b1 = (const float*)d_in[2];
    const float* W2 = (const float*)d_in[3];
    const float* b2 = (const float*)d_in[4];
    float* out = (float*)d_out;

    const int SM_G1 = 3 * 5 * BUF32 + 256;   // 153856
    const int SM_TK = 2 * 4 * BUF + 256;     // 147712
    const int SM_G2 = 3 * 3 * BUF + 256;     // 166144
    cudaFuncSetAttribute(g1_kernel,   cudaFuncAttributeMaxDynamicSharedMemorySize, SM_G1);
    cudaFuncSetAttribute(topk_kernel, cudaFuncAttributeMaxDynamicSharedMemorySize, SM_TK);
    cudaFuncSetAttribute(g2_kernel,   cudaFuncAttributeMaxDynamicSharedMemorySize, SM_G2);

    prep_b1_kernel<<<1, 256>>>(b1);
    prep_x_kernel<<<NTOK, 256>>>(x);
    prep_w1t_kernel<<<HID, 128>>>(W1);

    dim3 gt(HID / 128, NTOK / 128);          // (32, 64)
    topk_kernel<<<gt, 512, SM_TK>>>(b1);

    perm_build_kernel<<<1, 1024>>>();
    prep_w1_kernel<<<HID, 256>>>(W1, b1);
    prep_w2_kernel<<<DIN, 256>>>(W2);

    g1_kernel<<<gt, 512, SM_G1>>>();
    dim3 gg2(DIN / 128, NTOK / 128);         // (8, 64)
    g2_kernel<<<gg2, 512, SM_G2>>>(b2, out);
}

// round 15
// speedup vs baseline: 1.6890x; 1.1814x over previous
#include <cuda_runtime.h>
#include <cuda_bf16.h>
#include <cuda_fp16.h>
#include <math.h>
#include <stdint.h>

#define NTOK 8192
#define DIN  1024
#define HID  4096
#define TOPKC 103
#define KTP  128
#define THRESH 2048

typedef __nv_bfloat16 bf16;

// ---------------- scratch ----------------------------------------------------
__device__ __align__(16) __half g_xf [(size_t)NTOK*DIN];  // x fp16
__device__ __align__(16) __half g_xq [(size_t)NTOK*DIN];  // quantized x (fp16, exact)
__device__ __align__(16) __half g_w1h[(size_t)HID*DIN];   // permuted W1 fp16 hi
__device__ __align__(16) __half g_w1l[(size_t)HID*DIN];   // permuted W1 fp16 lo
__device__ __align__(16) __half g_wq [(size_t)HID*DIN];   // permuted quantized W1
__device__ __align__(16) bf16 g_xthi[(size_t)NTOK*KTP];   // topk: exact bf16 split
__device__ __align__(16) bf16 g_xtlo[(size_t)NTOK*KTP];
__device__ __align__(16) bf16 g_wthi[(size_t)HID*KTP];
__device__ __align__(16) bf16 g_wtlo[(size_t)HID*KTP];
__device__ __align__(16) __half g_w2h[(size_t)DIN*HID];   // permuted cols, fp16
__device__ __align__(16) __half g_hf [(size_t)NTOK*HID];  // permuted cols, fp16
__device__ float g_sx[NTOK];
__device__ float g_qb[HID];
__device__ int   g_counts[HID];
__device__ int   g_nfp;
__device__ int   g_perm[HID];
__device__ int   g_inv[HID];
__device__ float g_b1p[HID], g_swp[HID], g_qbp[HID];
__device__ int   g_cntp[HID];

// ---------------- helpers ------------------------------------------------------
__device__ __forceinline__ uint32_t smem_u32(const void* p) {
    uint32_t a;
    asm("{ .reg .u64 t; cvta.to.shared.u64 t, %1; cvt.u32.u64 %0, t; }" : "=r"(a) : "l"(p));
    return a;
}
__device__ __forceinline__ void cpa(uint32_t s, const void* g) {
    asm volatile("cp.async.cg.shared.global [%0], [%1], 16;" :: "r"(s), "l"(g));
}
#define CP_COMMIT() asm volatile("cp.async.commit_group;" ::: "memory")
#define CP_WAIT(N)  asm volatile("cp.async.wait_group %0;" :: "n"(N) : "memory")

__device__ __forceinline__ void ldsm4(uint32_t* r, uint32_t addr) {
    asm volatile("ldmatrix.sync.aligned.m8n8.x4.shared.b16 {%0,%1,%2,%3}, [%4];"
        : "=r"(r[0]), "=r"(r[1]), "=r"(r[2]), "=r"(r[3]) : "r"(addr));
}
__device__ __forceinline__ void mma_bf16(float* c, const uint32_t* a, const uint32_t* b) {
    asm volatile("mma.sync.aligned.m16n8k16.row.col.f32.bf16.bf16.f32 "
        "{%0,%1,%2,%3}, {%4,%5,%6,%7}, {%8,%9}, {%0,%1,%2,%3};"
        : "+f"(c[0]), "+f"(c[1]), "+f"(c[2]), "+f"(c[3])
        : "r"(a[0]), "r"(a[1]), "r"(a[2]), "r"(a[3]), "r"(b[0]), "r"(b[1]));
}
__device__ __forceinline__ void mma_f16(float* c, const uint32_t* a, const uint32_t* b) {
    asm volatile("mma.sync.aligned.m16n8k16.row.col.f32.f16.f16.f32 "
        "{%0,%1,%2,%3}, {%4,%5,%6,%7}, {%8,%9}, {%0,%1,%2,%3};"
        : "+f"(c[0]), "+f"(c[1]), "+f"(c[2]), "+f"(c[3])
        : "r"(a[0]), "r"(a[1]), "r"(a[2]), "r"(a[3]), "r"(b[0]), "r"(b[1]));
}
__device__ __forceinline__ float gelu_exact(float v) {
    return 0.5f * v * (1.0f + erff(v * 0.70710678118654752440f));
}

#define ROWB 144
#define BUF  (128 * ROWB)      // BK=64 b16 tiles (topk, g2)
#define ROWB32 80
#define BUF32  (128 * ROWB32)  // BK=32 b16 tiles (g1)

// ================= G1: fp16 2-pass fp path + fp16 exact-q (passing R14) =========
__global__ void __launch_bounds__(512, 1)
g1_kernel() {
    extern __shared__ char dsm[];
    uint32_t sbase = (smem_u32(dsm) + 127u) & ~127u;
    const int i0 = blockIdx.y * 128, n0 = blockIdx.x * 128;
    const int tid = threadIdx.x, w = tid >> 5, lane = tid & 31;
    const int wm = w & 3, wn = w >> 2;
    const int NT = DIN / 32;
    const int STG = 5 * BUF32;

    const int nfp = g_nfp;
    const bool tfp = (n0 < nfp);
    const bool tq  = (n0 + 128 > nfp);

    auto load_tile = [&](int kt, int st) {
        uint32_t sb = sbase + st * STG;
        int row = tid >> 2, c16 = tid & 3;
        uint32_t so = (uint32_t)(row * ROWB32 + c16 * 16);
        size_t ga = (size_t)(i0 + row) * DIN + kt * 32 + c16 * 8;
        size_t gb = (size_t)(n0 + row) * DIN + kt * 32 + c16 * 8;
        if (tfp) {
            cpa(sb + 0 * BUF32 + so, g_xf  + ga);
            cpa(sb + 1 * BUF32 + so, g_w1h + gb);
            cpa(sb + 2 * BUF32 + so, g_w1l + gb);
        }
        if (tq) {
            cpa(sb + 3 * BUF32 + so, g_xq + ga);
            cpa(sb + 4 * BUF32 + so, g_wq + gb);
        }
        CP_COMMIT();
    };

    uint32_t aRow[2], bRow[2];
#pragma unroll
    for (int mt = 0; mt < 2; mt++)
        aRow[mt] = (uint32_t)((wm * 32 + mt * 16 + (lane & 15)) * ROWB32);
#pragma unroll
    for (int p = 0; p < 2; p++)
        bRow[p] = (uint32_t)((wn * 32 + p * 16 + ((lane >> 4) << 3) + (lane & 7)) * ROWB32);
    uint32_t aK = (uint32_t)((lane >> 4) * 16);
    uint32_t bK = (uint32_t)(((lane >> 3) & 1) * 16);

    float accF[2][4][4], accQ[2][4][4];
#pragma unroll
    for (int mt = 0; mt < 2; mt++)
#pragma unroll
        for (int nt = 0; nt < 4; nt++)
#pragma unroll
            for (int r = 0; r < 4; r++) { accF[mt][nt][r] = 0.f; accQ[mt][nt][r] = 0.f; }

    load_tile(0, 0);
    load_tile(1, 1);
    int st = 0, stL = 2;
    for (int kt = 0; kt < NT; kt++) {
        if (kt + 1 < NT) CP_WAIT(1); else CP_WAIT(0);
        __syncthreads();
        if (kt + 2 < NT) load_tile(kt + 2, stL);
        uint32_t sb = sbase + st * STG;
#pragma unroll
        for (int kk = 0; kk < 2; kk++) {
            uint32_t ka = aK + kk * 32;
            uint32_t kb = bK + kk * 32;
            if (tfp) {
                uint32_t axf[2][4];
#pragma unroll
                for (int mt = 0; mt < 2; mt++)
                    ldsm4(axf[mt], sb + 0 * BUF32 + aRow[mt] + ka);
                uint32_t bh[4][2], bl[4][2];
#pragma unroll
                for (int p = 0; p < 2; p++) {
                    uint32_t t[4];
                    ldsm4(t, sb + 1 * BUF32 + bRow[p] + kb);
                    bh[2*p][0]=t[0]; bh[2*p][1]=t[1]; bh[2*p+1][0]=t[2]; bh[2*p+1][1]=t[3];
                    ldsm4(t, sb + 2 * BUF32 + bRow[p] + kb);
                    bl[2*p][0]=t[0]; bl[2*p][1]=t[1]; bl[2*p+1][0]=t[2]; bl[2*p+1][1]=t[3];
                }
#pragma unroll
                for (int mt = 0; mt < 2; mt++)
#pragma unroll
                    for (int nt = 0; nt < 4; nt++)
                        mma_f16(accF[mt][nt], axf[mt], bh[nt]);
#pragma unroll
                for (int mt = 0; mt < 2; mt++)
#pragma unroll
                    for (int nt = 0; nt < 4; nt++)
                        mma_f16(accF[mt][nt], axf[mt], bl[nt]);
            }
            if (tq) {
                uint32_t aq[2][4];
#pragma unroll
                for (int mt = 0; mt < 2; mt++)
                    ldsm4(aq[mt], sb + 3 * BUF32 + aRow[mt] + ka);
                uint32_t bq[4][2];
#pragma unroll
                for (int p = 0; p < 2; p++) {
                    uint32_t t[4];
                    ldsm4(t, sb + 4 * BUF32 + bRow[p] + kb);
                    bq[2*p][0]=t[0]; bq[2*p][1]=t[1]; bq[2*p+1][0]=t[2]; bq[2*p+1][1]=t[3];
                }
#pragma unroll
                for (int mt = 0; mt < 2; mt++)
#pragma unroll
                    for (int nt = 0; nt < 4; nt++)
                        mma_f16(accQ[mt][nt], aq[mt], bq[nt]);
            }
        }
        st = (st == 2) ? 0 : st + 1;
        stL = (stL == 2) ? 0 : stL + 1;
    }
    __syncthreads();

    __shared__ float sb1[128], ssw[128], sqb[128], ssx[128];
    __shared__ int scnt[128];
    if (tid < 128) {
        int h = n0 + tid;
        sb1[tid] = g_b1p[h]; ssw[tid] = g_swp[h]; sqb[tid] = g_qbp[h];
        scnt[tid] = g_cntp[h];
        ssx[tid] = g_sx[i0 + tid];
    }
    __syncthreads();

    int gq = lane >> 2, q4 = lane & 3;
#pragma unroll
    for (int mt = 0; mt < 2; mt++)
#pragma unroll
        for (int half = 0; half < 2; half++) {
            int rl = wm * 32 + mt * 16 + gq + half * 8;
            float sxv = ssx[rl];
            size_t ro = (size_t)(i0 + rl) * HID + n0;
#pragma unroll
            for (int nt = 0; nt < 4; nt++) {
                int cl = wn * 32 + nt * 8 + q4 * 2;
                float f0 = accF[mt][nt][half*2+0], f1 = accF[mt][nt][half*2+1];
                float q0 = accQ[mt][nt][half*2+0], q1 = accQ[mt][nt][half*2+1];
                float v0 = (scnt[cl]   > THRESH) ? (f0 + sb1[cl])
                          : fmaf(sxv * ssw[cl],   q0, sqb[cl]);
                float v1 = (scnt[cl+1] > THRESH) ? (f1 + sb1[cl+1])
                          : fmaf(sxv * ssw[cl+1], q1, sqb[cl+1]);
                float g0 = gelu_exact(v0), g1 = gelu_exact(v1);
                __half2 hp;
                hp.x = __float2half(g0); hp.y = __float2half(g1);
                *(uint32_t*)(g_hf + ro + cl) = *(uint32_t*)&hp;
            }
        }
}

// ================= topk: exact bf16 split (unchanged, passing) ==================
__global__ void __launch_bounds__(512, 1)
topk_kernel(const float* __restrict__ b1) {
    extern __shared__ char dsm[];
    uint32_t sbase = (smem_u32(dsm) + 127u) & ~127u;
    const int i0 = blockIdx.y * 128, n0 = blockIdx.x * 128;
    const int tid = threadIdx.x, w = tid >> 5, lane = tid & 31;
    const int wm = w & 3, wn = w >> 2;
    const int NT = 2;
    const int STG = 4 * BUF;

    auto load_tile = [&](int kt, int st) {
        uint32_t sb = sbase + st * STG;
#pragma unroll
        for (int c = 0; c < 2; c++) {
            int idx = tid + c * 512, row = idx >> 3, c16 = idx & 7;
            uint32_t so = (uint32_t)(row * ROWB + c16 * 16);
            size_t ga = (size_t)(i0 + row) * KTP + kt * 64 + c16 * 8;
            size_t gb = (size_t)(n0 + row) * KTP + kt * 64 + c16 * 8;
            cpa(sb + 0 * BUF + so, g_xthi + ga);
            cpa(sb + 1 * BUF + so, g_xtlo + ga);
            cpa(sb + 2 * BUF + so, g_wthi + gb);
            cpa(sb + 3 * BUF + so, g_wtlo + gb);
        }
        CP_COMMIT();
    };

    uint32_t aRow[2], bRow[2];
#pragma unroll
    for (int mt = 0; mt < 2; mt++)
        aRow[mt] = (uint32_t)((wm * 32 + mt * 16 + (lane & 15)) * ROWB);
#pragma unroll
    for (int p = 0; p < 2; p++)
        bRow[p] = (uint32_t)((wn * 32 + p * 16 + ((lane >> 4) << 3) + (lane & 7)) * ROWB);
    uint32_t aK = (uint32_t)((lane >> 4) * 16);
    uint32_t bK = (uint32_t)(((lane >> 3) & 1) * 16);

    float acc[2][4][4];
#pragma unroll
    for (int mt = 0; mt < 2; mt++)
#pragma unroll
        for (int nt = 0; nt < 4; nt++)
#pragma unroll
            for (int r = 0; r < 4; r++) acc[mt][nt][r] = 0.f;

    load_tile(0, 0);
    load_tile(1, 1);
    for (int kt = 0; kt < NT; kt++) {
        int st = kt & 1;
        CP_WAIT(0);
        __syncthreads();
        uint32_t sb = sbase + st * STG;
#pragma unroll
        for (int kk = 0; kk < 4; kk++) {
            uint32_t ka = aK + kk * 32;
            uint32_t kb = bK + kk * 32;
            uint32_t ah[2][4], al[2][4];
#pragma unroll
            for (int mt = 0; mt < 2; mt++) {
                ldsm4(ah[mt], sb + 0 * BUF + aRow[mt] + ka);
                ldsm4(al[mt], sb + 1 * BUF + aRow[mt] + ka);
            }
            uint32_t bh[4][2], bl[4][2];
#pragma unroll
            for (int p = 0; p < 2; p++) {
                uint32_t t[4];
                ldsm4(t, sb + 2 * BUF + bRow[p] + kb);
                bh[2*p][0]=t[0]; bh[2*p][1]=t[1]; bh[2*p+1][0]=t[2]; bh[2*p+1][1]=t[3];
                ldsm4(t, sb + 3 * BUF + bRow[p] + kb);
                bl[2*p][0]=t[0]; bl[2*p][1]=t[1]; bl[2*p+1][0]=t[2]; bl[2*p+1][1]=t[3];
            }
#pragma unroll
            for (int mt = 0; mt < 2; mt++)
#pragma unroll
                for (int nt = 0; nt < 4; nt++)
                    mma_bf16(acc[mt][nt], ah[mt], bh[nt]);
#pragma unroll
            for (int mt = 0; mt < 2; mt++)
#pragma unroll
                for (int nt = 0; nt < 4; nt++)
                    mma_bf16(acc[mt][nt], ah[mt], bl[nt]);
#pragma unroll
            for (int mt = 0; mt < 2; mt++)
#pragma unroll
                for (int nt = 0; nt < 4; nt++)
                    mma_bf16(acc[mt][nt], al[mt], bh[nt]);
        }
        __syncthreads();
    }

    __shared__ float sb1[128];
    __shared__ int scnt[128];
    if (tid < 128) { sb1[tid] = b1[n0 + tid]; scnt[tid] = 0; }
    __syncthreads();

    int q4 = lane & 3;
#pragma unroll
    for (int nt = 0; nt < 4; nt++) {
        int cl = wn * 32 + nt * 8 + q4 * 2;
        int c0 = 0, c1 = 0;
#pragma unroll
        for (int mt = 0; mt < 2; mt++)
#pragma unroll
            for (int half = 0; half < 2; half++) {
                c0 += (acc[mt][nt][half*2+0] + sb1[cl]   > 0.f);
                c1 += (acc[mt][nt][half*2+1] + sb1[cl+1] > 0.f);
            }
        atomicAdd(&scnt[cl],     c0);
        atomicAdd(&scnt[cl + 1], c1);
    }
    __syncthreads();
    if (tid < 128) atomicAdd(&g_counts[n0 + tid], scnt[tid]);
}

// ================= G2: SINGLE-pass fp16 (h_f16 . w2_f16), 2-buffer stages =======
__global__ void __launch_bounds__(512, 1)
g2_kernel(const float* __restrict__ b2, float* __restrict__ out) {
    extern __shared__ char dsm[];
    uint32_t sbase = (smem_u32(dsm) + 127u) & ~127u;
    const int i0 = blockIdx.y * 128, d0 = blockIdx.x * 128;
    const int tid = threadIdx.x, w = tid >> 5, lane = tid & 31;
    const int wm = w & 3, wn = w >> 2;
    const int NT = HID / 64;
    const int STG = 2 * BUF;   // hf, w2h

    auto load_tile = [&](int kt, int st) {
        uint32_t sb = sbase + st * STG;
#pragma unroll
        for (int c = 0; c < 2; c++) {
            int idx = tid + c * 512, row = idx >> 3, c16 = idx & 7;
            uint32_t so = (uint32_t)(row * ROWB + c16 * 16);
            size_t ga = (size_t)(i0 + row) * HID + kt * 64 + c16 * 8;
            size_t gb = (size_t)(d0 + row) * HID + kt * 64 + c16 * 8;
            cpa(sb + 0 * BUF + so, g_hf  + ga);
            cpa(sb + 1 * BUF + so, g_w2h + gb);
        }
        CP_COMMIT();
    };

    uint32_t aRow[2], bRow[2];
#pragma unroll
    for (int mt = 0; mt < 2; mt++)
        aRow[mt] = (uint32_t)((wm * 32 + mt * 16 + (lane & 15)) * ROWB);
#pragma unroll
    for (int p = 0; p < 2; p++)
        bRow[p] = (uint32_t)((wn * 32 + p * 16 + ((lane >> 4) << 3) + (lane & 7)) * ROWB);
    uint32_t aK = (uint32_t)((lane >> 4) * 16);
    uint32_t bK = (uint32_t)(((lane >> 3) & 1) * 16);

    float acc[2][4][4];
#pragma unroll
    for (int mt = 0; mt < 2; mt++)
#pragma unroll
        for (int nt = 0; nt < 4; nt++)
#pragma unroll
            for (int r = 0; r < 4; r++) acc[mt][nt][r] = 0.f;

    load_tile(0, 0);
    load_tile(1, 1);
    int st = 0, stL = 2;
    for (int kt = 0; kt < NT; kt++) {
        if (kt + 1 < NT) CP_WAIT(1); else CP_WAIT(0);
        __syncthreads();
        if (kt + 2 < NT) load_tile(kt + 2, stL);
        uint32_t sb = sbase + st * STG;
#pragma unroll
        for (int kk = 0; kk < 4; kk++) {
            uint32_t ka = aK + kk * 32;
            uint32_t kb = bK + kk * 32;
            uint32_t ah[2][4];
#pragma unroll
            for (int mt = 0; mt < 2; mt++)
                ldsm4(ah[mt], sb + 0 * BUF + aRow[mt] + ka);
            uint32_t bh[4][2];
#pragma unroll
            for (int p = 0; p < 2; p++) {
                uint32_t t[4];
                ldsm4(t, sb + 1 * BUF + bRow[p] + kb);
                bh[2*p][0]=t[0]; bh[2*p][1]=t[1]; bh[2*p+1][0]=t[2]; bh[2*p+1][1]=t[3];
            }
#pragma unroll
            for (int mt = 0; mt < 2; mt++)
#pragma unroll
                for (int nt = 0; nt < 4; nt++)
                    mma_f16(acc[mt][nt], ah[mt], bh[nt]);
        }
        st = (st == 2) ? 0 : st + 1;
        stL = (stL == 2) ? 0 : stL + 1;
    }
    __syncthreads();

    __shared__ float sbb[128];
    if (tid < 128) sbb[tid] = b2[d0 + tid];
    __syncthreads();

    int gq = lane >> 2, q4 = lane & 3;
#pragma unroll
    for (int mt = 0; mt < 2; mt++)
#pragma unroll
        for (int half = 0; half < 2; half++) {
            int rl = wm * 32 + mt * 16 + gq + half * 8;
            float* dst = out + (size_t)(i0 + rl) * DIN + d0;
#pragma unroll
            for (int nt = 0; nt < 4; nt++) {
                int cl = wn * 32 + nt * 8 + q4 * 2;
                float2 o = make_float2(acc[mt][nt][half*2+0] + sbb[cl],
                                       acc[mt][nt][half*2+1] + sbb[cl+1]);
                *(float2*)(dst + cl) = o;
            }
        }
}

// ---------------- prep kernels ---------------------------------------------------
__global__ void prep_x_kernel(const float* __restrict__ src) {
    int row = blockIdx.x, tid = threadIdx.x;
    const float* r = src + (size_t)row * DIN;
    float4 v = ((const float4*)r)[tid];
    float amax = fmaxf(fmaxf(fabsf(v.x), fabsf(v.y)), fmaxf(fabsf(v.z), fabsf(v.w)));
    __shared__ float red[256];
    red[tid] = amax; __syncthreads();
    for (int s = 128; s; s >>= 1) {
        if (tid < s) red[tid] = fmaxf(red[tid], red[tid + s]);
        __syncthreads();
    }
    float scale = fmaxf(red[0], 1e-5f) / 127.f;
    if (tid == 0) g_sx[row] = scale;
    float e[4] = {v.x, v.y, v.z, v.w};
    __half2 f2[2], q2[2];
#pragma unroll
    for (int k = 0; k < 4; k++) {
        __half fb = __float2half(e[k]);
        float qq = fminf(127.f, fmaxf(-128.f, rintf(e[k] / scale)));
        __half qv = __float2half(qq);
        if (k & 1) { f2[k>>1].y = fb; q2[k>>1].y = qv; }
        else       { f2[k>>1].x = fb; q2[k>>1].x = qv; }
    }
    size_t o = (size_t)row * DIN + tid * 4;
    *(uint2*)(g_xf + o) = make_uint2(*(uint32_t*)&f2[0], *(uint32_t*)&f2[1]);
    *(uint2*)(g_xq + o) = make_uint2(*(uint32_t*)&q2[0], *(uint32_t*)&q2[1]);
    if (tid < KTP) {
        float val = (tid < TOPKC) ? r[tid] : 0.f;
        bf16 hb = __float2bfloat16(val);
        g_xthi[(size_t)row * KTP + tid] = hb;
        g_xtlo[(size_t)row * KTP + tid] = __float2bfloat16(val - __bfloat162float(hb));
    }
}

__global__ void prep_w1t_kernel(const float* __restrict__ W1) {
    int row = blockIdx.x, tid = threadIdx.x;  // 128 threads
    float val = (tid < TOPKC) ? W1[(size_t)row * DIN + tid] : 0.f;
    bf16 hb = __float2bfloat16(val);
    g_wthi[(size_t)row * KTP + tid] = hb;
    g_wtlo[(size_t)row * KTP + tid] = __float2bfloat16(val - __bfloat162float(hb));
}

__global__ void perm_build_kernel() {
    __shared__ int warpsum[32];
    int tid = threadIdx.x;
    int base = tid * 4;
    int f[4], s = 0;
#pragma unroll
    for (int k = 0; k < 4; k++) { f[k] = g_counts[base + k] > THRESH; s += f[k]; }
    int lane = tid & 31, wid = tid >> 5;
    int v = s;
#pragma unroll
    for (int o = 1; o < 32; o <<= 1) {
        int t = __shfl_up_sync(0xFFFFFFFF, v, o);
        if (lane >= o) v += t;
    }
    if (lane == 31) warpsum[wid] = v;
    __syncthreads();
    if (wid == 0) {
        int wv = warpsum[lane];
#pragma unroll
        for (int o = 1; o < 32; o <<= 1) {
            int t = __shfl_up_sync(0xFFFFFFFF, wv, o);
            if (lane >= o) wv += t;
        }
        warpsum[lane] = wv;
    }
    __syncthreads();
    int excl = v - s + (wid ? warpsum[wid - 1] : 0);
    int total = warpsum[31];
    if (tid == 0) g_nfp = total;
    int run = excl;
#pragma unroll
    for (int k = 0; k < 4; k++) {
        int r = base + k;
        int p = f[k] ? run : total + (r - run);
        g_perm[r] = p;
        g_inv[p] = r;
        run += f[k];
    }
}

__global__ void prep_w1_kernel(const float* __restrict__ W1, const float* __restrict__ b1) {
    int row = blockIdx.x, tid = threadIdx.x;
    int p = g_perm[row];
    const float* r = W1 + (size_t)row * DIN;
    float4 v = ((const float4*)r)[tid];
    float amax = fmaxf(fmaxf(fabsf(v.x), fabsf(v.y)), fmaxf(fabsf(v.z), fabsf(v.w)));
    __shared__ float red[256];
    red[tid] = amax; __syncthreads();
    for (int s = 128; s; s >>= 1) {
        if (tid < s) red[tid] = fmaxf(red[tid], red[tid + s]);
        __syncthreads();
    }
    float scale = fmaxf(red[0], 1e-5f) / 127.f;
    if (tid == 0) {
        g_swp[p] = scale;
        g_b1p[p] = b1[row];
        g_qbp[p] = g_qb[row];
        g_cntp[p] = g_counts[row];
    }
    float e[4] = {v.x, v.y, v.z, v.w};
    __half2 h2[2], l2[2], q2[2];
#pragma unroll
    for (int k = 0; k < 4; k++) {
        __half hb = __float2half(e[k]);
        __half lb = __float2half(e[k] - __half2float(hb));
        float qq = fminf(127.f, fmaxf(-128.f, rintf(e[k] / scale)));
        __half qv = __float2half(qq);
        if (k & 1) { h2[k>>1].y = hb; l2[k>>1].y = lb; q2[k>>1].y = qv; }
        else       { h2[k>>1].x = hb; l2[k>>1].x = lb; q2[k>>1].x = qv; }
    }
    size_t o = (size_t)p * DIN + tid * 4;
    *(uint2*)(g_w1h + o) = make_uint2(*(uint32_t*)&h2[0], *(uint32_t*)&h2[1]);
    *(uint2*)(g_w1l + o) = make_uint2(*(uint32_t*)&l2[0], *(uint32_t*)&l2[1]);
    *(uint2*)(g_wq  + o) = make_uint2(*(uint32_t*)&q2[0], *(uint32_t*)&q2[1]);
}

__global__ void prep_w2_kernel(const float* __restrict__ W2) {
    int row = blockIdx.x, tid = threadIdx.x;
    const float* r = W2 + (size_t)row * HID;
#pragma unroll
    for (int j = 0; j < 4; j++) {
        int nc = (tid + 256 * j) * 4;
        float e[4];
#pragma unroll
        for (int k = 0; k < 4; k++) e[k] = r[g_inv[nc + k]];
        __half2 h2[2];
#pragma unroll
        for (int k = 0; k < 4; k++) {
            __half hb = __float2half(e[k]);
            if (k & 1) h2[k>>1].y = hb;
            else       h2[k>>1].x = hb;
        }
        size_t o = (size_t)row * HID + nc;
        *(uint2*)(g_w2h + o) = make_uint2(*(uint32_t*)&h2[0], *(uint32_t*)&h2[1]);
    }
}

__global__ void prep_b1_kernel(const float* __restrict__ b1) {
    __shared__ float red[256];
    int tid = threadIdx.x;
    float amax = 0.f;
    for (int i = tid; i < HID; i += 256) amax = fmaxf(amax, fabsf(b1[i]));
    red[tid] = amax; __syncthreads();
    for (int s = 128; s; s >>= 1) {
        if (tid < s) red[tid] = fmaxf(red[tid], red[tid + s]);
        __syncthreads();
    }
    float scale = fmaxf(red[0], 1e-5f) / 127.f;
    for (int i = tid; i < HID; i += 256) {
        g_qb[i] = fminf(127.f, fmaxf(-128.f, rintf(b1[i] / scale))) * scale;
        g_counts[i] = 0;
    }
}

// ---------------- launch -----------------------------------------------------------
extern "C" void kernel_launch(void* const* d_in, const int* in_sizes, int n_in,
                              void* d_out, int out_size) {
    const float* x  = (const float*)d_in[0];
    const float* W1 = (const float*)d_in[1];
    const float* b1 = (const float*)d_in[2];
    const float* W2 = (const float*)d_in[3];
    const float* b2 = (const float*)d_in[4];
    float* out = (float*)d_out;

    const int SM_G1 = 3 * 5 * BUF32 + 256;   // 153856
    const int SM_TK = 2 * 4 * BUF + 256;     // 147712
    const int SM_G2 = 3 * 2 * BUF + 256;     // 110848
    cudaFuncSetAttribute(g1_kernel,   cudaFuncAttributeMaxDynamicSharedMemorySize, SM_G1);
    cudaFuncSetAttribute(topk_kernel, cudaFuncAttributeMaxDynamicSharedMemorySize, SM_TK);
    cudaFuncSetAttribute(g2_kernel,   cudaFuncAttributeMaxDynamicSharedMemorySize, SM_G2);

    prep_b1_kernel<<<1, 256>>>(b1);
    prep_x_kernel<<<NTOK, 256>>>(x);
    prep_w1t_kernel<<<HID, 128>>>(W1);

    dim3 gt(HID / 128, NTOK / 128);          // (32, 64)
    topk_kernel<<<gt, 512, SM_TK>>>(b1);

    perm_build_kernel<<<1, 1024>>>();
    prep_w1_kernel<<<HID, 256>>>(W1, b1);
    prep_w2_kernel<<<DIN, 256>>>(W2);

    g1_kernel<<<gt, 512, SM_G1>>>();
    dim3 gg2(DIN / 128, NTOK / 128);         // (8, 64)
    g2_kernel<<<gg2, 512, SM_G2>>>(b2, out);
}

// round 16
// speedup vs baseline: 2.0255x; 1.1992x over previous
#include <cuda_runtime.h>
#include <cuda_bf16.h>
#include <cuda_fp16.h>
#include <math.h>
#include <stdint.h>

#define NTOK 8192
#define DIN  1024
#define HID  4096
#define TOPKC 103
#define KTP  128
#define THRESH 2048

typedef __nv_bfloat16 bf16;

// ---------------- scratch ----------------------------------------------------
__device__ __align__(16) __half g_xf [(size_t)NTOK*DIN];  // x fp16
__device__ __align__(16) __half g_xq [(size_t)NTOK*DIN];  // quantized x (fp16, exact)
__device__ __align__(16) __half g_w1h[(size_t)HID*DIN];   // permuted W1 fp16
__device__ __align__(16) __half g_wq [(size_t)HID*DIN];   // permuted quantized W1
__device__ __align__(16) bf16 g_xthi[(size_t)NTOK*KTP];   // topk: exact bf16 split
__device__ __align__(16) bf16 g_xtlo[(size_t)NTOK*KTP];
__device__ __align__(16) bf16 g_wthi[(size_t)HID*KTP];
__device__ __align__(16) bf16 g_wtlo[(size_t)HID*KTP];
__device__ __align__(16) __half g_w2h[(size_t)DIN*HID];   // permuted cols, fp16
__device__ __align__(16) __half g_hf [(size_t)NTOK*HID];  // permuted cols, fp16
__device__ float g_sx[NTOK];
__device__ float g_qb[HID];
__device__ int   g_counts[HID];
__device__ int   g_nfp;
__device__ int   g_perm[HID];
__device__ int   g_inv[HID];
__device__ float g_b1p[HID], g_swp[HID], g_qbp[HID];
__device__ int   g_cntp[HID];

// ---------------- helpers ------------------------------------------------------
__device__ __forceinline__ uint32_t smem_u32(const void* p) {
    uint32_t a;
    asm("{ .reg .u64 t; cvta.to.shared.u64 t, %1; cvt.u32.u64 %0, t; }" : "=r"(a) : "l"(p));
    return a;
}
__device__ __forceinline__ void cpa(uint32_t s, const void* g) {
    asm volatile("cp.async.cg.shared.global [%0], [%1], 16;" :: "r"(s), "l"(g));
}
#define CP_COMMIT() asm volatile("cp.async.commit_group;" ::: "memory")
#define CP_WAIT(N)  asm volatile("cp.async.wait_group %0;" :: "n"(N) : "memory")

__device__ __forceinline__ void ldsm4(uint32_t* r, uint32_t addr) {
    asm volatile("ldmatrix.sync.aligned.m8n8.x4.shared.b16 {%0,%1,%2,%3}, [%4];"
        : "=r"(r[0]), "=r"(r[1]), "=r"(r[2]), "=r"(r[3]) : "r"(addr));
}
__device__ __forceinline__ void mma_bf16(float* c, const uint32_t* a, const uint32_t* b) {
    asm volatile("mma.sync.aligned.m16n8k16.row.col.f32.bf16.bf16.f32 "
        "{%0,%1,%2,%3}, {%4,%5,%6,%7}, {%8,%9}, {%0,%1,%2,%3};"
        : "+f"(c[0]), "+f"(c[1]), "+f"(c[2]), "+f"(c[3])
        : "r"(a[0]), "r"(a[1]), "r"(a[2]), "r"(a[3]), "r"(b[0]), "r"(b[1]));
}
__device__ __forceinline__ void mma_f16(float* c, const uint32_t* a, const uint32_t* b) {
    asm volatile("mma.sync.aligned.m16n8k16.row.col.f32.f16.f16.f32 "
        "{%0,%1,%2,%3}, {%4,%5,%6,%7}, {%8,%9}, {%0,%1,%2,%3};"
        : "+f"(c[0]), "+f"(c[1]), "+f"(c[2]), "+f"(c[3])
        : "r"(a[0]), "r"(a[1]), "r"(a[2]), "r"(a[3]), "r"(b[0]), "r"(b[1]));
}
__device__ __forceinline__ float gelu_exact(float v) {
    return 0.5f * v * (1.0f + erff(v * 0.70710678118654752440f));
}

#define ROWB 144
#define BUF  (128 * ROWB)      // BK=64 b16 tiles (topk, g2)
#define ROWB32 80
#define BUF32  (128 * ROWB32)  // BK=32 b16 tiles (g1)

// ================= G1: single-pass fp16 fp path + fp16 exact-q ==================
// buffers: 0 xf, 1 w1h, 2 xq, 3 wq
__global__ void __launch_bounds__(512, 1)
g1_kernel() {
    extern __shared__ char dsm[];
    uint32_t sbase = (smem_u32(dsm) + 127u) & ~127u;
    const int i0 = blockIdx.y * 128, n0 = blockIdx.x * 128;
    const int tid = threadIdx.x, w = tid >> 5, lane = tid & 31;
    const int wm = w & 3, wn = w >> 2;
    const int NT = DIN / 32;
    const int STG = 4 * BUF32;   // 40960

    const int nfp = g_nfp;
    const bool tfp = (n0 < nfp);
    const bool tq  = (n0 + 128 > nfp);

    auto load_tile = [&](int kt, int st) {
        uint32_t sb = sbase + st * STG;
        int row = tid >> 2, c16 = tid & 3;
        uint32_t so = (uint32_t)(row * ROWB32 + c16 * 16);
        size_t ga = (size_t)(i0 + row) * DIN + kt * 32 + c16 * 8;
        size_t gb = (size_t)(n0 + row) * DIN + kt * 32 + c16 * 8;
        if (tfp) {
            cpa(sb + 0 * BUF32 + so, g_xf  + ga);
            cpa(sb + 1 * BUF32 + so, g_w1h + gb);
        }
        if (tq) {
            cpa(sb + 2 * BUF32 + so, g_xq + ga);
            cpa(sb + 3 * BUF32 + so, g_wq + gb);
        }
        CP_COMMIT();
    };

    uint32_t aRow[2], bRow[2];
#pragma unroll
    for (int mt = 0; mt < 2; mt++)
        aRow[mt] = (uint32_t)((wm * 32 + mt * 16 + (lane & 15)) * ROWB32);
#pragma unroll
    for (int p = 0; p < 2; p++)
        bRow[p] = (uint32_t)((wn * 32 + p * 16 + ((lane >> 4) << 3) + (lane & 7)) * ROWB32);
    uint32_t aK = (uint32_t)((lane >> 4) * 16);
    uint32_t bK = (uint32_t)(((lane >> 3) & 1) * 16);

    float accF[2][4][4], accQ[2][4][4];
#pragma unroll
    for (int mt = 0; mt < 2; mt++)
#pragma unroll
        for (int nt = 0; nt < 4; nt++)
#pragma unroll
            for (int r = 0; r < 4; r++) { accF[mt][nt][r] = 0.f; accQ[mt][nt][r] = 0.f; }

    load_tile(0, 0);
    load_tile(1, 1);
    int st = 0, stL = 2;
    for (int kt = 0; kt < NT; kt++) {
        if (kt + 1 < NT) CP_WAIT(1); else CP_WAIT(0);
        __syncthreads();
        if (kt + 2 < NT) load_tile(kt + 2, stL);
        uint32_t sb = sbase + st * STG;
#pragma unroll
        for (int kk = 0; kk < 2; kk++) {
            uint32_t ka = aK + kk * 32;
            uint32_t kb = bK + kk * 32;
            if (tfp) {
                uint32_t axf[2][4];
#pragma unroll
                for (int mt = 0; mt < 2; mt++)
                    ldsm4(axf[mt], sb + 0 * BUF32 + aRow[mt] + ka);
                uint32_t bh[4][2];
#pragma unroll
                for (int p = 0; p < 2; p++) {
                    uint32_t t[4];
                    ldsm4(t, sb + 1 * BUF32 + bRow[p] + kb);
                    bh[2*p][0]=t[0]; bh[2*p][1]=t[1]; bh[2*p+1][0]=t[2]; bh[2*p+1][1]=t[3];
                }
#pragma unroll
                for (int mt = 0; mt < 2; mt++)
#pragma unroll
                    for (int nt = 0; nt < 4; nt++)
                        mma_f16(accF[mt][nt], axf[mt], bh[nt]);
            }
            if (tq) {
                uint32_t aq[2][4];
#pragma unroll
                for (int mt = 0; mt < 2; mt++)
                    ldsm4(aq[mt], sb + 2 * BUF32 + aRow[mt] + ka);
                uint32_t bq[4][2];
#pragma unroll
                for (int p = 0; p < 2; p++) {
                    uint32_t t[4];
                    ldsm4(t, sb + 3 * BUF32 + bRow[p] + kb);
                    bq[2*p][0]=t[0]; bq[2*p][1]=t[1]; bq[2*p+1][0]=t[2]; bq[2*p+1][1]=t[3];
                }
#pragma unroll
                for (int mt = 0; mt < 2; mt++)
#pragma unroll
                    for (int nt = 0; nt < 4; nt++)
                        mma_f16(accQ[mt][nt], aq[mt], bq[nt]);
            }
        }
        st = (st == 2) ? 0 : st + 1;
        stL = (stL == 2) ? 0 : stL + 1;
    }
    __syncthreads();

    __shared__ float sb1[128], ssw[128], sqb[128], ssx[128];
    __shared__ int scnt[128];
    if (tid < 128) {
        int h = n0 + tid;
        sb1[tid] = g_b1p[h]; ssw[tid] = g_swp[h]; sqb[tid] = g_qbp[h];
        scnt[tid] = g_cntp[h];
        ssx[tid] = g_sx[i0 + tid];
    }
    __syncthreads();

    int gq = lane >> 2, q4 = lane & 3;
#pragma unroll
    for (int mt = 0; mt < 2; mt++)
#pragma unroll
        for (int half = 0; half < 2; half++) {
            int rl = wm * 32 + mt * 16 + gq + half * 8;
            float sxv = ssx[rl];
            size_t ro = (size_t)(i0 + rl) * HID + n0;
#pragma unroll
            for (int nt = 0; nt < 4; nt++) {
                int cl = wn * 32 + nt * 8 + q4 * 2;
                float f0 = accF[mt][nt][half*2+0], f1 = accF[mt][nt][half*2+1];
                float q0 = accQ[mt][nt][half*2+0], q1 = accQ[mt][nt][half*2+1];
                float v0 = (scnt[cl]   > THRESH) ? (f0 + sb1[cl])
                          : fmaf(sxv * ssw[cl],   q0, sqb[cl]);
                float v1 = (scnt[cl+1] > THRESH) ? (f1 + sb1[cl+1])
                          : fmaf(sxv * ssw[cl+1], q1, sqb[cl+1]);
                float g0 = gelu_exact(v0), g1 = gelu_exact(v1);
                __half2 hp;
                hp.x = __float2half(g0); hp.y = __float2half(g1);
                *(uint32_t*)(g_hf + ro + cl) = *(uint32_t*)&hp;
            }
        }
}

// ================= topk: exact bf16 split (unchanged, passing) ==================
__global__ void __launch_bounds__(512, 1)
topk_kernel(const float* __restrict__ b1) {
    extern __shared__ char dsm[];
    uint32_t sbase = (smem_u32(dsm) + 127u) & ~127u;
    const int i0 = blockIdx.y * 128, n0 = blockIdx.x * 128;
    const int tid = threadIdx.x, w = tid >> 5, lane = tid & 31;
    const int wm = w & 3, wn = w >> 2;
    const int NT = 2;
    const int STG = 4 * BUF;

    auto load_tile = [&](int kt, int st) {
        uint32_t sb = sbase + st * STG;
#pragma unroll
        for (int c = 0; c < 2; c++) {
            int idx = tid + c * 512, row = idx >> 3, c16 = idx & 7;
            uint32_t so = (uint32_t)(row * ROWB + c16 * 16);
            size_t ga = (size_t)(i0 + row) * KTP + kt * 64 + c16 * 8;
            size_t gb = (size_t)(n0 + row) * KTP + kt * 64 + c16 * 8;
            cpa(sb + 0 * BUF + so, g_xthi + ga);
            cpa(sb + 1 * BUF + so, g_xtlo + ga);
            cpa(sb + 2 * BUF + so, g_wthi + gb);
            cpa(sb + 3 * BUF + so, g_wtlo + gb);
        }
        CP_COMMIT();
    };

    uint32_t aRow[2], bRow[2];
#pragma unroll
    for (int mt = 0; mt < 2; mt++)
        aRow[mt] = (uint32_t)((wm * 32 + mt * 16 + (lane & 15)) * ROWB);
#pragma unroll
    for (int p = 0; p < 2; p++)
        bRow[p] = (uint32_t)((wn * 32 + p * 16 + ((lane >> 4) << 3) + (lane & 7)) * ROWB);
    uint32_t aK = (uint32_t)((lane >> 4) * 16);
    uint32_t bK = (uint32_t)(((lane >> 3) & 1) * 16);

    float acc[2][4][4];
#pragma unroll
    for (int mt = 0; mt < 2; mt++)
#pragma unroll
        for (int nt = 0; nt < 4; nt++)
#pragma unroll
            for (int r = 0; r < 4; r++) acc[mt][nt][r] = 0.f;

    load_tile(0, 0);
    load_tile(1, 1);
    for (int kt = 0; kt < NT; kt++) {
        int st = kt & 1;
        CP_WAIT(0);
        __syncthreads();
        uint32_t sb = sbase + st * STG;
#pragma unroll
        for (int kk = 0; kk < 4; kk++) {
            uint32_t ka = aK + kk * 32;
            uint32_t kb = bK + kk * 32;
            uint32_t ah[2][4], al[2][4];
#pragma unroll
            for (int mt = 0; mt < 2; mt++) {
                ldsm4(ah[mt], sb + 0 * BUF + aRow[mt] + ka);
                ldsm4(al[mt], sb + 1 * BUF + aRow[mt] + ka);
            }
            uint32_t bh[4][2], bl[4][2];
#pragma unroll
            for (int p = 0; p < 2; p++) {
                uint32_t t[4];
                ldsm4(t, sb + 2 * BUF + bRow[p] + kb);
                bh[2*p][0]=t[0]; bh[2*p][1]=t[1]; bh[2*p+1][0]=t[2]; bh[2*p+1][1]=t[3];
                ldsm4(t, sb + 3 * BUF + bRow[p] + kb);
                bl[2*p][0]=t[0]; bl[2*p][1]=t[1]; bl[2*p+1][0]=t[2]; bl[2*p+1][1]=t[3];
            }
#pragma unroll
            for (int mt = 0; mt < 2; mt++)
#pragma unroll
                for (int nt = 0; nt < 4; nt++)
                    mma_bf16(acc[mt][nt], ah[mt], bh[nt]);
#pragma unroll
            for (int mt = 0; mt < 2; mt++)
#pragma unroll
                for (int nt = 0; nt < 4; nt++)
                    mma_bf16(acc[mt][nt], ah[mt], bl[nt]);
#pragma unroll
            for (int mt = 0; mt < 2; mt++)
#pragma unroll
                for (int nt = 0; nt < 4; nt++)
                    mma_bf16(acc[mt][nt], al[mt], bh[nt]);
        }
        __syncthreads();
    }

    __shared__ float sb1[128];
    __shared__ int scnt[128];
    if (tid < 128) { sb1[tid] = b1[n0 + tid]; scnt[tid] = 0; }
    __syncthreads();

    int q4 = lane & 3;
#pragma unroll
    for (int nt = 0; nt < 4; nt++) {
        int cl = wn * 32 + nt * 8 + q4 * 2;
        int c0 = 0, c1 = 0;
#pragma unroll
        for (int mt = 0; mt < 2; mt++)
#pragma unroll
            for (int half = 0; half < 2; half++) {
                c0 += (acc[mt][nt][half*2+0] + sb1[cl]   > 0.f);
                c1 += (acc[mt][nt][half*2+1] + sb1[cl+1] > 0.f);
            }
        atomicAdd(&scnt[cl],     c0);
        atomicAdd(&scnt[cl + 1], c1);
    }
    __syncthreads();
    if (tid < 128) atomicAdd(&g_counts[n0 + tid], scnt[tid]);
}

// ================= G2: single-pass fp16 (unchanged, passing R15) ================
__global__ void __launch_bounds__(512, 1)
g2_kernel(const float* __restrict__ b2, float* __restrict__ out) {
    extern __shared__ char dsm[];
    uint32_t sbase = (smem_u32(dsm) + 127u) & ~127u;
    const int i0 = blockIdx.y * 128, d0 = blockIdx.x * 128;
    const int tid = threadIdx.x, w = tid >> 5, lane = tid & 31;
    const int wm = w & 3, wn = w >> 2;
    const int NT = HID / 64;
    const int STG = 2 * BUF;

    auto load_tile = [&](int kt, int st) {
        uint32_t sb = sbase + st * STG;
#pragma unroll
        for (int c = 0; c < 2; c++) {
            int idx = tid + c * 512, row = idx >> 3, c16 = idx & 7;
            uint32_t so = (uint32_t)(row * ROWB + c16 * 16);
            size_t ga = (size_t)(i0 + row) * HID + kt * 64 + c16 * 8;
            size_t gb = (size_t)(d0 + row) * HID + kt * 64 + c16 * 8;
            cpa(sb + 0 * BUF + so, g_hf  + ga);
            cpa(sb + 1 * BUF + so, g_w2h + gb);
        }
        CP_COMMIT();
    };

    uint32_t aRow[2], bRow[2];
#pragma unroll
    for (int mt = 0; mt < 2; mt++)
        aRow[mt] = (uint32_t)((wm * 32 + mt * 16 + (lane & 15)) * ROWB);
#pragma unroll
    for (int p = 0; p < 2; p++)
        bRow[p] = (uint32_t)((wn * 32 + p * 16 + ((lane >> 4) << 3) + (lane & 7)) * ROWB);
    uint32_t aK = (uint32_t)((lane >> 4) * 16);
    uint32_t bK = (uint32_t)(((lane >> 3) & 1) * 16);

    float acc[2][4][4];
#pragma unroll
    for (int mt = 0; mt < 2; mt++)
#pragma unroll
        for (int nt = 0; nt < 4; nt++)
#pragma unroll
            for (int r = 0; r < 4; r++) acc[mt][nt][r] = 0.f;

    load_tile(0, 0);
    load_tile(1, 1);
    int st = 0, stL = 2;
    for (int kt = 0; kt < NT; kt++) {
        if (kt + 1 < NT) CP_WAIT(1); else CP_WAIT(0);
        __syncthreads();
        if (kt + 2 < NT) load_tile(kt + 2, stL);
        uint32_t sb = sbase + st * STG;
#pragma unroll
        for (int kk = 0; kk < 4; kk++) {
            uint32_t ka = aK + kk * 32;
            uint32_t kb = bK + kk * 32;
            uint32_t ah[2][4];
#pragma unroll
            for (int mt = 0; mt < 2; mt++)
                ldsm4(ah[mt], sb + 0 * BUF + aRow[mt] + ka);
            uint32_t bh[4][2];
#pragma unroll
            for (int p = 0; p < 2; p++) {
                uint32_t t[4];
                ldsm4(t, sb + 1 * BUF + bRow[p] + kb);
                bh[2*p][0]=t[0]; bh[2*p][1]=t[1]; bh[2*p+1][0]=t[2]; bh[2*p+1][1]=t[3];
            }
#pragma unroll
            for (int mt = 0; mt < 2; mt++)
#pragma unroll
                for (int nt = 0; nt < 4; nt++)
                    mma_f16(acc[mt][nt], ah[mt], bh[nt]);
        }
        st = (st == 2) ? 0 : st + 1;
        stL = (stL == 2) ? 0 : stL + 1;
    }
    __syncthreads();

    __shared__ float sbb[128];
    if (tid < 128) sbb[tid] = b2[d0 + tid];
    __syncthreads();

    int gq = lane >> 2, q4 = lane & 3;
#pragma unroll
    for (int mt = 0; mt < 2; mt++)
#pragma unroll
        for (int half = 0; half < 2; half++) {
            int rl = wm * 32 + mt * 16 + gq + half * 8;
            float* dst = out + (size_t)(i0 + rl) * DIN + d0;
#pragma unroll
            for (int nt = 0; nt < 4; nt++) {
                int cl = wn * 32 + nt * 8 + q4 * 2;
                float2 o = make_float2(acc[mt][nt][half*2+0] + sbb[cl],
                                       acc[mt][nt][half*2+1] + sbb[cl+1]);
                *(float2*)(dst + cl) = o;
            }
        }
}

// ---------------- prep kernels ---------------------------------------------------
__global__ void prep_x_kernel(const float* __restrict__ src) {
    int row = blockIdx.x, tid = threadIdx.x;
    const float* r = src + (size_t)row * DIN;
    float4 v = ((const float4*)r)[tid];
    float amax = fmaxf(fmaxf(fabsf(v.x), fabsf(v.y)), fmaxf(fabsf(v.z), fabsf(v.w)));
    __shared__ float red[256];
    red[tid] = amax; __syncthreads();
    for (int s = 128; s; s >>= 1) {
        if (tid < s) red[tid] = fmaxf(red[tid], red[tid + s]);
        __syncthreads();
    }
    float scale = fmaxf(red[0], 1e-5f) / 127.f;
    if (tid == 0) g_sx[row] = scale;
    float e[4] = {v.x, v.y, v.z, v.w};
    __half2 f2[2], q2[2];
#pragma unroll
    for (int k = 0; k < 4; k++) {
        __half fb = __float2half(e[k]);
        float qq = fminf(127.f, fmaxf(-128.f, rintf(e[k] / scale)));
        __half qv = __float2half(qq);
        if (k & 1) { f2[k>>1].y = fb; q2[k>>1].y = qv; }
        else       { f2[k>>1].x = fb; q2[k>>1].x = qv; }
    }
    size_t o = (size_t)row * DIN + tid * 4;
    *(uint2*)(g_xf + o) = make_uint2(*(uint32_t*)&f2[0], *(uint32_t*)&f2[1]);
    *(uint2*)(g_xq + o) = make_uint2(*(uint32_t*)&q2[0], *(uint32_t*)&q2[1]);
    if (tid < KTP) {
        float val = (tid < TOPKC) ? r[tid] : 0.f;
        bf16 hb = __float2bfloat16(val);
        g_xthi[(size_t)row * KTP + tid] = hb;
        g_xtlo[(size_t)row * KTP + tid] = __float2bfloat16(val - __bfloat162float(hb));
    }
}

__global__ void prep_w1t_kernel(const float* __restrict__ W1) {
    int row = blockIdx.x, tid = threadIdx.x;  // 128 threads
    float val = (tid < TOPKC) ? W1[(size_t)row * DIN + tid] : 0.f;
    bf16 hb = __float2bfloat16(val);
    g_wthi[(size_t)row * KTP + tid] = hb;
    g_wtlo[(size_t)row * KTP + tid] = __float2bfloat16(val - __bfloat162float(hb));
}

__global__ void perm_build_kernel() {
    __shared__ int warpsum[32];
    int tid = threadIdx.x;
    int base = tid * 4;
    int f[4], s = 0;
#pragma unroll
    for (int k = 0; k < 4; k++) { f[k] = g_counts[base + k] > THRESH; s += f[k]; }
    int lane = tid & 31, wid = tid >> 5;
    int v = s;
#pragma unroll
    for (int o = 1; o < 32; o <<= 1) {
        int t = __shfl_up_sync(0xFFFFFFFF, v, o);
        if (lane >= o) v += t;
    }
    if (lane == 31) warpsum[wid] = v;
    __syncthreads();
    if (wid == 0) {
        int wv = warpsum[lane];
#pragma unroll
        for (int o = 1; o < 32; o <<= 1) {
            int t = __shfl_up_sync(0xFFFFFFFF, wv, o);
            if (lane >= o) wv += t;
        }
        warpsum[lane] = wv;
    }
    __syncthreads();
    int excl = v - s + (wid ? warpsum[wid - 1] : 0);
    int total = warpsum[31];
    if (tid == 0) g_nfp = total;
    int run = excl;
#pragma unroll
    for (int k = 0; k < 4; k++) {
        int r = base + k;
        int p = f[k] ? run : total + (r - run);
        g_perm[r] = p;
        g_inv[p] = r;
        run += f[k];
    }
}

__global__ void prep_w1_kernel(const float* __restrict__ W1, const float* __restrict__ b1) {
    int row = blockIdx.x, tid = threadIdx.x;
    int p = g_perm[row];
    const float* r = W1 + (size_t)row * DIN;
    float4 v = ((const float4*)r)[tid];
    float amax = fmaxf(fmaxf(fabsf(v.x), fabsf(v.y)), fmaxf(fabsf(v.z), fabsf(v.w)));
    __shared__ float red[256];
    red[tid] = amax; __syncthreads();
    for (int s = 128; s; s >>= 1) {
        if (tid < s) red[tid] = fmaxf(red[tid], red[tid + s]);
        __syncthreads();
    }
    float scale = fmaxf(red[0], 1e-5f) / 127.f;
    if (tid == 0) {
        g_swp[p] = scale;
        g_b1p[p] = b1[row];
        g_qbp[p] = g_qb[row];
        g_cntp[p] = g_counts[row];
    }
    float e[4] = {v.x, v.y, v.z, v.w};
    __half2 h2[2], q2[2];
#pragma unroll
    for (int k = 0; k < 4; k++) {
        __half hb = __float2half(e[k]);
        float qq = fminf(127.f, fmaxf(-128.f, rintf(e[k] / scale)));
        __half qv = __float2half(qq);
        if (k & 1) { h2[k>>1].y = hb; q2[k>>1].y = qv; }
        else       { h2[k>>1].x = hb; q2[k>>1].x = qv; }
    }
    size_t o = (size_t)p * DIN + tid * 4;
    *(uint2*)(g_w1h + o) = make_uint2(*(uint32_t*)&h2[0], *(uint32_t*)&h2[1]);
    *(uint2*)(g_wq  + o) = make_uint2(*(uint32_t*)&q2[0], *(uint32_t*)&q2[1]);
}

__global__ void prep_w2_kernel(const float* __restrict__ W2) {
    int row = blockIdx.x, tid = threadIdx.x;
    const float* r = W2 + (size_t)row * HID;
#pragma unroll
    for (int j = 0; j < 4; j++) {
        int nc = (tid + 256 * j) * 4;
        float e[4];
#pragma unroll
        for (int k = 0; k < 4; k++) e[k] = r[g_inv[nc + k]];
        __half2 h2[2];
#pragma unroll
        for (int k = 0; k < 4; k++) {
            __half hb = __float2half(e[k]);
            if (k & 1) h2[k>>1].y = hb;
            else       h2[k>>1].x = hb;
        }
        size_t o = (size_t)row * HID + nc;
        *(uint2*)(g_w2h + o) = make_uint2(*(uint32_t*)&h2[0], *(uint32_t*)&h2[1]);
    }
}

__global__ void prep_b1_kernel(const float* __restrict__ b1) {
    __shared__ float red[256];
    int tid = threadIdx.x;
    float amax = 0.f;
    for (int i = tid; i < HID; i += 256) amax = fmaxf(amax, fabsf(b1[i]));
    red[tid] = amax; __syncthreads();
    for (int s = 128; s; s >>= 1) {
        if (tid < s) red[tid] = fmaxf(red[tid], red[tid + s]);
        __syncthreads();
    }
    float scale = fmaxf(red[0], 1e-5f) / 127.f;
    for (int i = tid; i < HID; i += 256) {
        g_qb[i] = fminf(127.f, fmaxf(-128.f, rintf(b1[i] / scale))) * scale;
        g_counts[i] = 0;
    }
}

// ---------------- launch -----------------------------------------------------------
extern "C" void kernel_launch(void* const* d_in, const int* in_sizes, int n_in,
                              void* d_out, int out_size) {
    const float* x  = (const float*)d_in[0];
    const float* W1 = (const float*)d_in[1];
    const float* b1 = (const float*)d_in[2];
    const float* W2 = (const float*)d_in[3];
    const float* b2 = (const float*)d_in[4];
    float* out = (float*)d_out;

    const int SM_G1 = 3 * 4 * BUF32 + 256;   // 123136
    const int SM_TK = 2 * 4 * BUF + 256;     // 147712
    const int SM_G2 = 3 * 2 * BUF + 256;     // 110848
    cudaFuncSetAttribute(g1_kernel,   cudaFuncAttributeMaxDynamicSharedMemorySize, SM_G1);
    cudaFuncSetAttribute(topk_kernel, cudaFuncAttributeMaxDynamicSharedMemorySize, SM_TK);
    cudaFuncSetAttribute(g2_kernel,   cudaFuncAttributeMaxDynamicSharedMemorySize, SM_G2);

    prep_b1_kernel<<<1, 256>>>(b1);
    prep_x_kernel<<<NTOK, 256>>>(x);
    prep_w1t_kernel<<<HID, 128>>>(W1);

    dim3 gt(HID / 128, NTOK / 128);          // (32, 64)
    topk_kernel<<<gt, 512, SM_TK>>>(b1);

    perm_build_kernel<<<1, 1024>>>();
    prep_w1_kernel<<<HID, 256>>>(W1, b1);
    prep_w2_kernel<<<DIN, 256>>>(W2);

    g1_kernel<<<gt, 512, SM_G1>>>();
    dim3 gg2(DIN / 128, NTOK / 128);         // (8, 64)
    g2_kernel<<<gg2, 512, SM_G2>>>(b2, out);
}

// round 17
// speedup vs baseline: 2.0417x; 1.0080x over previous
#include <cuda_runtime.h>
#include <cuda_bf16.h>
#include <cuda_fp16.h>
#include <math.h>
#include <stdint.h>

#define NTOK 8192
#define DIN  1024
#define HID  4096
#define TOPKC 103
#define KTP  128
#define THRESH 2048

typedef __nv_bfloat16 bf16;

// ---------------- scratch ----------------------------------------------------
__device__ __align__(16) __half g_xf [(size_t)NTOK*DIN];  // x fp16
__device__ __align__(16) signed char g_xq[(size_t)NTOK*DIN]; // quantized x int8
__device__ __align__(16) __half g_w1h[(size_t)HID*DIN];   // permuted W1 fp16
__device__ __align__(16) signed char g_wq[(size_t)HID*DIN]; // permuted quantized W1 int8
__device__ __align__(16) bf16 g_xthi[(size_t)NTOK*KTP];   // topk: exact bf16 split
__device__ __align__(16) bf16 g_xtlo[(size_t)NTOK*KTP];
__device__ __align__(16) bf16 g_wthi[(size_t)HID*KTP];
__device__ __align__(16) bf16 g_wtlo[(size_t)HID*KTP];
__device__ __align__(16) __half g_w2h[(size_t)DIN*HID];   // permuted cols, fp16
__device__ __align__(16) __half g_hf [(size_t)NTOK*HID];  // permuted cols, fp16
__device__ float g_sx[NTOK];
__device__ float g_qb[HID];
__device__ int   g_counts[HID];
__device__ int   g_nfp;
__device__ int   g_perm[HID];
__device__ int   g_inv[HID];
__device__ float g_b1p[HID], g_swp[HID], g_qbp[HID];
__device__ int   g_cntp[HID];

// ---------------- helpers ------------------------------------------------------
__device__ __forceinline__ uint32_t smem_u32(const void* p) {
    uint32_t a;
    asm("{ .reg .u64 t; cvta.to.shared.u64 t, %1; cvt.u32.u64 %0, t; }" : "=r"(a) : "l"(p));
    return a;
}
__device__ __forceinline__ void cpa(uint32_t s, const void* g) {
    asm volatile("cp.async.cg.shared.global [%0], [%1], 16;" :: "r"(s), "l"(g));
}
#define CP_COMMIT() asm volatile("cp.async.commit_group;" ::: "memory")
#define CP_WAIT(N)  asm volatile("cp.async.wait_group %0;" :: "n"(N) : "memory")

__device__ __forceinline__ void ldsm4(uint32_t* r, uint32_t addr) {
    asm volatile("ldmatrix.sync.aligned.m8n8.x4.shared.b16 {%0,%1,%2,%3}, [%4];"
        : "=r"(r[0]), "=r"(r[1]), "=r"(r[2]), "=r"(r[3]) : "r"(addr));
}
__device__ __forceinline__ void mma_bf16(float* c, const uint32_t* a, const uint32_t* b) {
    asm volatile("mma.sync.aligned.m16n8k16.row.col.f32.bf16.bf16.f32 "
        "{%0,%1,%2,%3}, {%4,%5,%6,%7}, {%8,%9}, {%0,%1,%2,%3};"
        : "+f"(c[0]), "+f"(c[1]), "+f"(c[2]), "+f"(c[3])
        : "r"(a[0]), "r"(a[1]), "r"(a[2]), "r"(a[3]), "r"(b[0]), "r"(b[1]));
}
__device__ __forceinline__ void mma_f16(float* c, const uint32_t* a, const uint32_t* b) {
    asm volatile("mma.sync.aligned.m16n8k16.row.col.f32.f16.f16.f32 "
        "{%0,%1,%2,%3}, {%4,%5,%6,%7}, {%8,%9}, {%0,%1,%2,%3};"
        : "+f"(c[0]), "+f"(c[1]), "+f"(c[2]), "+f"(c[3])
        : "r"(a[0]), "r"(a[1]), "r"(a[2]), "r"(a[3]), "r"(b[0]), "r"(b[1]));
}
__device__ __forceinline__ void mma_s8(int* c, const uint32_t* a, const uint32_t* b) {
    asm volatile("mma.sync.aligned.m16n8k32.row.col.s32.s8.s8.s32 "
        "{%0,%1,%2,%3}, {%4,%5,%6,%7}, {%8,%9}, {%0,%1,%2,%3};"
        : "+r"(c[0]), "+r"(c[1]), "+r"(c[2]), "+r"(c[3])
        : "r"(a[0]), "r"(a[1]), "r"(a[2]), "r"(a[3]), "r"(b[0]), "r"(b[1]));
}
__device__ __forceinline__ float gelu_exact(float v) {
    return 0.5f * v * (1.0f + erff(v * 0.70710678118654752440f));
}

#define ROWB 144
#define BUF  (128 * ROWB)      // BK=64 b16 tiles (topk, g2)
#define ROWB32 80
#define BUF32  (128 * ROWB32)  // BK=32 b16 tiles (g1 fp)
#define ROWQ 48
#define BUFQ (128 * ROWQ)      // BK=32 int8 tiles (g1 q): 32B data + 16 pad

// ================= G1: 1-pass fp16 fp path + 1-IMMA exact-q ====================
// buffers: 0 xf (BUF32), 1 w1h (BUF32), 2 xq (BUFQ), 3 wq (BUFQ)
#define G1_XQ  (2 * BUF32)
#define G1_WQ  (2 * BUF32 + BUFQ)
#define G1_STG (2 * BUF32 + 2 * BUFQ)   // 32768
__global__ void __launch_bounds__(512, 1)
g1_kernel() {
    extern __shared__ char dsm[];
    uint32_t sbase = (smem_u32(dsm) + 127u) & ~127u;
    const int i0 = blockIdx.y * 128, n0 = blockIdx.x * 128;
    const int tid = threadIdx.x, w = tid >> 5, lane = tid & 31;
    const int wm = w & 3, wn = w >> 2;
    const int NT = DIN / 32;

    const int nfp = g_nfp;
    const bool tfp = (n0 < nfp);
    const bool tq  = (n0 + 128 > nfp);

    auto load_tile = [&](int kt, int st) {
        uint32_t sb = sbase + st * G1_STG;
        {
            int row = tid >> 2, c16 = tid & 3;
            uint32_t so = (uint32_t)(row * ROWB32 + c16 * 16);
            size_t ga = (size_t)(i0 + row) * DIN + kt * 32 + c16 * 8;
            size_t gb = (size_t)(n0 + row) * DIN + kt * 32 + c16 * 8;
            if (tfp) {
                cpa(sb + 0 * BUF32 + so, g_xf  + ga);
                cpa(sb + 1 * BUF32 + so, g_w1h + gb);
            }
            if (tq && c16 < 2) {
                uint32_t soq = (uint32_t)(row * ROWQ + c16 * 16);
                size_t gqa = (size_t)(i0 + row) * DIN + kt * 32 + c16 * 16;
                size_t gqb = (size_t)(n0 + row) * DIN + kt * 32 + c16 * 16;
                cpa(sb + G1_XQ + soq, g_xq + gqa);
                cpa(sb + G1_WQ + soq, g_wq + gqb);
            }
        }
        CP_COMMIT();
    };

    uint32_t aRow[2], bRow[2], aRowQ[2], bRowQ[2];
#pragma unroll
    for (int mt = 0; mt < 2; mt++) {
        int r = wm * 32 + mt * 16 + (lane & 15);
        aRow[mt]  = (uint32_t)(r * ROWB32);
        aRowQ[mt] = (uint32_t)(r * ROWQ);
    }
#pragma unroll
    for (int p = 0; p < 2; p++) {
        int r = wn * 32 + p * 16 + ((lane >> 4) << 3) + (lane & 7);
        bRow[p]  = (uint32_t)(r * ROWB32);
        bRowQ[p] = (uint32_t)(r * ROWQ);
    }
    uint32_t aK = (uint32_t)((lane >> 4) * 16);
    uint32_t bK = (uint32_t)(((lane >> 3) & 1) * 16);

    float accF[2][4][4];
    int   accQ[2][4][4];
#pragma unroll
    for (int mt = 0; mt < 2; mt++)
#pragma unroll
        for (int nt = 0; nt < 4; nt++)
#pragma unroll
            for (int r = 0; r < 4; r++) { accF[mt][nt][r] = 0.f; accQ[mt][nt][r] = 0; }

    load_tile(0, 0);
    load_tile(1, 1);
    int st = 0, stL = 2;
    for (int kt = 0; kt < NT; kt++) {
        if (kt + 1 < NT) CP_WAIT(1); else CP_WAIT(0);
        __syncthreads();
        if (kt + 2 < NT) load_tile(kt + 2, stL);
        uint32_t sb = sbase + st * G1_STG;
        if (tfp) {
#pragma unroll
            for (int kk = 0; kk < 2; kk++) {
                uint32_t ka = aK + kk * 32;
                uint32_t kb = bK + kk * 32;
                uint32_t axf[2][4];
#pragma unroll
                for (int mt = 0; mt < 2; mt++)
                    ldsm4(axf[mt], sb + 0 * BUF32 + aRow[mt] + ka);
                uint32_t bh[4][2];
#pragma unroll
                for (int p = 0; p < 2; p++) {
                    uint32_t t[4];
                    ldsm4(t, sb + 1 * BUF32 + bRow[p] + kb);
                    bh[2*p][0]=t[0]; bh[2*p][1]=t[1]; bh[2*p+1][0]=t[2]; bh[2*p+1][1]=t[3];
                }
#pragma unroll
                for (int mt = 0; mt < 2; mt++)
#pragma unroll
                    for (int nt = 0; nt < 4; nt++)
                        mma_f16(accF[mt][nt], axf[mt], bh[nt]);
            }
        }
        if (tq) {
            // single m16n8k32 IMMA step consumes the whole BK=32 int8 tile
            uint32_t aq[2][4];
#pragma unroll
            for (int mt = 0; mt < 2; mt++)
                ldsm4(aq[mt], sb + G1_XQ + aRowQ[mt] + aK);
            uint32_t bq[4][2];
#pragma unroll
            for (int p = 0; p < 2; p++) {
                uint32_t t[4];
                ldsm4(t, sb + G1_WQ + bRowQ[p] + bK);
                bq[2*p][0]=t[0]; bq[2*p][1]=t[1]; bq[2*p+1][0]=t[2]; bq[2*p+1][1]=t[3];
            }
#pragma unroll
            for (int mt = 0; mt < 2; mt++)
#pragma unroll
                for (int nt = 0; nt < 4; nt++)
                    mma_s8(accQ[mt][nt], aq[mt], bq[nt]);
        }
        st = (st == 2) ? 0 : st + 1;
        stL = (stL == 2) ? 0 : stL + 1;
    }
    __syncthreads();

    __shared__ float sb1[128], ssw[128], sqb[128], ssx[128];
    __shared__ int scnt[128];
    if (tid < 128) {
        int h = n0 + tid;
        sb1[tid] = g_b1p[h]; ssw[tid] = g_swp[h]; sqb[tid] = g_qbp[h];
        scnt[tid] = g_cntp[h];
        ssx[tid] = g_sx[i0 + tid];
    }
    __syncthreads();

    int gq = lane >> 2, q4 = lane & 3;
#pragma unroll
    for (int mt = 0; mt < 2; mt++)
#pragma unroll
        for (int half = 0; half < 2; half++) {
            int rl = wm * 32 + mt * 16 + gq + half * 8;
            float sxv = ssx[rl];
            size_t ro = (size_t)(i0 + rl) * HID + n0;
#pragma unroll
            for (int nt = 0; nt < 4; nt++) {
                int cl = wn * 32 + nt * 8 + q4 * 2;
                float f0 = accF[mt][nt][half*2+0], f1 = accF[mt][nt][half*2+1];
                float q0 = (float)accQ[mt][nt][half*2+0];
                float q1 = (float)accQ[mt][nt][half*2+1];
                float v0 = (scnt[cl]   > THRESH) ? (f0 + sb1[cl])
                          : fmaf(sxv * ssw[cl],   q0, sqb[cl]);
                float v1 = (scnt[cl+1] > THRESH) ? (f1 + sb1[cl+1])
                          : fmaf(sxv * ssw[cl+1], q1, sqb[cl+1]);
                float g0 = gelu_exact(v0), g1 = gelu_exact(v1);
                __half2 hp;
                hp.x = __float2half(g0); hp.y = __float2half(g1);
                *(uint32_t*)(g_hf + ro + cl) = *(uint32_t*)&hp;
            }
        }
}

// ================= topk: exact bf16 split (unchanged, passing) ==================
__global__ void __launch_bounds__(512, 1)
topk_kernel(const float* __restrict__ b1) {
    extern __shared__ char dsm[];
    uint32_t sbase = (smem_u32(dsm) + 127u) & ~127u;
    const int i0 = blockIdx.y * 128, n0 = blockIdx.x * 128;
    const int tid = threadIdx.x, w = tid >> 5, lane = tid & 31;
    const int wm = w & 3, wn = w >> 2;
    const int NT = 2;
    const int STG = 4 * BUF;

    auto load_tile = [&](int kt, int st) {
        uint32_t sb = sbase + st * STG;
#pragma unroll
        for (int c = 0; c < 2; c++) {
            int idx = tid + c * 512, row = idx >> 3, c16 = idx & 7;
            uint32_t so = (uint32_t)(row * ROWB + c16 * 16);
            size_t ga = (size_t)(i0 + row) * KTP + kt * 64 + c16 * 8;
            size_t gb = (size_t)(n0 + row) * KTP + kt * 64 + c16 * 8;
            cpa(sb + 0 * BUF + so, g_xthi + ga);
            cpa(sb + 1 * BUF + so, g_xtlo + ga);
            cpa(sb + 2 * BUF + so, g_wthi + gb);
            cpa(sb + 3 * BUF + so, g_wtlo + gb);
        }
        CP_COMMIT();
    };

    uint32_t aRow[2], bRow[2];
#pragma unroll
    for (int mt = 0; mt < 2; mt++)
        aRow[mt] = (uint32_t)((wm * 32 + mt * 16 + (lane & 15)) * ROWB);
#pragma unroll
    for (int p = 0; p < 2; p++)
        bRow[p] = (uint32_t)((wn * 32 + p * 16 + ((lane >> 4) << 3) + (lane & 7)) * ROWB);
    uint32_t aK = (uint32_t)((lane >> 4) * 16);
    uint32_t bK = (uint32_t)(((lane >> 3) & 1) * 16);

    float acc[2][4][4];
#pragma unroll
    for (int mt = 0; mt < 2; mt++)
#pragma unroll
        for (int nt = 0; nt < 4; nt++)
#pragma unroll
            for (int r = 0; r < 4; r++) acc[mt][nt][r] = 0.f;

    load_tile(0, 0);
    load_tile(1, 1);
    for (int kt = 0; kt < NT; kt++) {
        int st = kt & 1;
        CP_WAIT(0);
        __syncthreads();
        uint32_t sb = sbase + st * STG;
#pragma unroll
        for (int kk = 0; kk < 4; kk++) {
            uint32_t ka = aK + kk * 32;
            uint32_t kb = bK + kk * 32;
            uint32_t ah[2][4], al[2][4];
#pragma unroll
            for (int mt = 0; mt < 2; mt++) {
                ldsm4(ah[mt], sb + 0 * BUF + aRow[mt] + ka);
                ldsm4(al[mt], sb + 1 * BUF + aRow[mt] + ka);
            }
            uint32_t bh[4][2], bl[4][2];
#pragma unroll
            for (int p = 0; p < 2; p++) {
                uint32_t t[4];
                ldsm4(t, sb + 2 * BUF + bRow[p] + kb);
                bh[2*p][0]=t[0]; bh[2*p][1]=t[1]; bh[2*p+1][0]=t[2]; bh[2*p+1][1]=t[3];
                ldsm4(t, sb + 3 * BUF + bRow[p] + kb);
                bl[2*p][0]=t[0]; bl[2*p][1]=t[1]; bl[2*p+1][0]=t[2]; bl[2*p+1][1]=t[3];
            }
#pragma unroll
            for (int mt = 0; mt < 2; mt++)
#pragma unroll
                for (int nt = 0; nt < 4; nt++)
                    mma_bf16(acc[mt][nt], ah[mt], bh[nt]);
#pragma unroll
            for (int mt = 0; mt < 2; mt++)
#pragma unroll
                for (int nt = 0; nt < 4; nt++)
                    mma_bf16(acc[mt][nt], ah[mt], bl[nt]);
#pragma unroll
            for (int mt = 0; mt < 2; mt++)
#pragma unroll
                for (int nt = 0; nt < 4; nt++)
                    mma_bf16(acc[mt][nt], al[mt], bh[nt]);
        }
        __syncthreads();
    }

    __shared__ float sb1[128];
    __shared__ int scnt[128];
    if (tid < 128) { sb1[tid] = b1[n0 + tid]; scnt[tid] = 0; }
    __syncthreads();

    int q4 = lane & 3;
#pragma unroll
    for (int nt = 0; nt < 4; nt++) {
        int cl = wn * 32 + nt * 8 + q4 * 2;
        int c0 = 0, c1 = 0;
#pragma unroll
        for (int mt = 0; mt < 2; mt++)
#pragma unroll
            for (int half = 0; half < 2; half++) {
                c0 += (acc[mt][nt][half*2+0] + sb1[cl]   > 0.f);
                c1 += (acc[mt][nt][half*2+1] + sb1[cl+1] > 0.f);
            }
        atomicAdd(&scnt[cl],     c0);
        atomicAdd(&scnt[cl + 1], c1);
    }
    __syncthreads();
    if (tid < 128) atomicAdd(&g_counts[n0 + tid], scnt[tid]);
}

// ================= G2: single-pass fp16 (unchanged, passing) ====================
__global__ void __launch_bounds__(512, 1)
g2_kernel(const float* __restrict__ b2, float* __restrict__ out) {
    extern __shared__ char dsm[];
    uint32_t sbase = (smem_u32(dsm) + 127u) & ~127u;
    const int i0 = blockIdx.y * 128, d0 = blockIdx.x * 128;
    const int tid = threadIdx.x, w = tid >> 5, lane = tid & 31;
    const int wm = w & 3, wn = w >> 2;
    const int NT = HID / 64;
    const int STG = 2 * BUF;

    auto load_tile = [&](int kt, int st) {
        uint32_t sb = sbase + st * STG;
#pragma unroll
        for (int c = 0; c < 2; c++) {
            int idx = tid + c * 512, row = idx >> 3, c16 = idx & 7;
            uint32_t so = (uint32_t)(row * ROWB + c16 * 16);
            size_t ga = (size_t)(i0 + row) * HID + kt * 64 + c16 * 8;
            size_t gb = (size_t)(d0 + row) * HID + kt * 64 + c16 * 8;
            cpa(sb + 0 * BUF + so, g_hf  + ga);
            cpa(sb + 1 * BUF + so, g_w2h + gb);
        }
        CP_COMMIT();
    };

    uint32_t aRow[2], bRow[2];
#pragma unroll
    for (int mt = 0; mt < 2; mt++)
        aRow[mt] = (uint32_t)((wm * 32 + mt * 16 + (lane & 15)) * ROWB);
#pragma unroll
    for (int p = 0; p < 2; p++)
        bRow[p] = (uint32_t)((wn * 32 + p * 16 + ((lane >> 4) << 3) + (lane & 7)) * ROWB);
    uint32_t aK = (uint32_t)((lane >> 4) * 16);
    uint32_t bK = (uint32_t)(((lane >> 3) & 1) * 16);

    float acc[2][4][4];
#pragma unroll
    for (int mt = 0; mt < 2; mt++)
#pragma unroll
        for (int nt = 0; nt < 4; nt++)
#pragma unroll
            for (int r = 0; r < 4; r++) acc[mt][nt][r] = 0.f;

    load_tile(0, 0);
    load_tile(1, 1);
    int st = 0, stL = 2;
    for (int kt = 0; kt < NT; kt++) {
        if (kt + 1 < NT) CP_WAIT(1); else CP_WAIT(0);
        __syncthreads();
        if (kt + 2 < NT) load_tile(kt + 2, stL);
        uint32_t sb = sbase + st * STG;
#pragma unroll
        for (int kk = 0; kk < 4; kk++) {
            uint32_t ka = aK + kk * 32;
            uint32_t kb = bK + kk * 32;
            uint32_t ah[2][4];
#pragma unroll
            for (int mt = 0; mt < 2; mt++)
                ldsm4(ah[mt], sb + 0 * BUF + aRow[mt] + ka);
            uint32_t bh[4][2];
#pragma unroll
            for (int p = 0; p < 2; p++) {
                uint32_t t[4];
                ldsm4(t, sb + 1 * BUF + bRow[p] + kb);
                bh[2*p][0]=t[0]; bh[2*p][1]=t[1]; bh[2*p+1][0]=t[2]; bh[2*p+1][1]=t[3];
            }
#pragma unroll
            for (int mt = 0; mt < 2; mt++)
#pragma unroll
                for (int nt = 0; nt < 4; nt++)
                    mma_f16(acc[mt][nt], ah[mt], bh[nt]);
        }
        st = (st == 2) ? 0 : st + 1;
        stL = (stL == 2) ? 0 : stL + 1;
    }
    __syncthreads();

    __shared__ float sbb[128];
    if (tid < 128) sbb[tid] = b2[d0 + tid];
    __syncthreads();

    int gq = lane >> 2, q4 = lane & 3;
#pragma unroll
    for (int mt = 0; mt < 2; mt++)
#pragma unroll
        for (int half = 0; half < 2; half++) {
            int rl = wm * 32 + mt * 16 + gq + half * 8;
            float* dst = out + (size_t)(i0 + rl) * DIN + d0;
#pragma unroll
            for (int nt = 0; nt < 4; nt++) {
                int cl = wn * 32 + nt * 8 + q4 * 2;
                float2 o = make_float2(acc[mt][nt][half*2+0] + sbb[cl],
                                       acc[mt][nt][half*2+1] + sbb[cl+1]);
                *(float2*)(dst + cl) = o;
            }
        }
}

// ---------------- prep kernels ---------------------------------------------------
__global__ void prep_x_kernel(const float* __restrict__ src) {
    int row = blockIdx.x, tid = threadIdx.x;
    const float* r = src + (size_t)row * DIN;
    float4 v = ((const float4*)r)[tid];
    float amax = fmaxf(fmaxf(fabsf(v.x), fabsf(v.y)), fmaxf(fabsf(v.z), fabsf(v.w)));
    __shared__ float red[256];
    red[tid] = amax; __syncthreads();
    for (int s = 128; s; s >>= 1) {
        if (tid < s) red[tid] = fmaxf(red[tid], red[tid + s]);
        __syncthreads();
    }
    float scale = fmaxf(red[0], 1e-5f) / 127.f;
    if (tid == 0) g_sx[row] = scale;
    float e[4] = {v.x, v.y, v.z, v.w};
    __half2 f2[2];
    uint32_t qp = 0;
#pragma unroll
    for (int k = 0; k < 4; k++) {
        __half fb = __float2half(e[k]);
        int iq = (int)fminf(127.f, fmaxf(-128.f, rintf(e[k] / scale)));
        qp |= ((uint32_t)(iq & 0xFF)) << (k * 8);
        if (k & 1) f2[k>>1].y = fb;
        else       f2[k>>1].x = fb;
    }
    size_t o = (size_t)row * DIN + tid * 4;
    *(uint2*)(g_xf + o) = make_uint2(*(uint32_t*)&f2[0], *(uint32_t*)&f2[1]);
    *(uint32_t*)(g_xq + o) = qp;
    if (tid < KTP) {
        float val = (tid < TOPKC) ? r[tid] : 0.f;
        bf16 hb = __float2bfloat16(val);
        g_xthi[(size_t)row * KTP + tid] = hb;
        g_xtlo[(size_t)row * KTP + tid] = __float2bfloat16(val - __bfloat162float(hb));
    }
}

__global__ void prep_w1t_kernel(const float* __restrict__ W1) {
    int row = blockIdx.x, tid = threadIdx.x;  // 128 threads
    float val = (tid < TOPKC) ? W1[(size_t)row * DIN + tid] : 0.f;
    bf16 hb = __float2bfloat16(val);
    g_wthi[(size_t)row * KTP + tid] = hb;
    g_wtlo[(size_t)row * KTP + tid] = __float2bfloat16(val - __bfloat162float(hb));
}

__global__ void perm_build_kernel() {
    __shared__ int warpsum[32];
    int tid = threadIdx.x;
    int base = tid * 4;
    int f[4], s = 0;
#pragma unroll
    for (int k = 0; k < 4; k++) { f[k] = g_counts[base + k] > THRESH; s += f[k]; }
    int lane = tid & 31, wid = tid >> 5;
    int v = s;
#pragma unroll
    for (int o = 1; o < 32; o <<= 1) {
        int t = __shfl_up_sync(0xFFFFFFFF, v, o);
        if (lane >= o) v += t;
    }
    if (lane == 31) warpsum[wid] = v;
    __syncthreads();
    if (wid == 0) {
        int wv = warpsum[lane];
#pragma unroll
        for (int o = 1; o < 32; o <<= 1) {
            int t = __shfl_up_sync(0xFFFFFFFF, wv, o);
            if (lane >= o) wv += t;
        }
        warpsum[lane] = wv;
    }
    __syncthreads();
    int excl = v - s + (wid ? warpsum[wid - 1] : 0);
    int total = warpsum[31];
    if (tid == 0) g_nfp = total;
    int run = excl;
#pragma unroll
    for (int k = 0; k < 4; k++) {
        int r = base + k;
        int p = f[k] ? run : total + (r - run);
        g_perm[r] = p;
        g_inv[p] = r;
        run += f[k];
    }
}

__global__ void prep_w1_kernel(const float* __restrict__ W1, const float* __restrict__ b1) {
    int row = blockIdx.x, tid = threadIdx.x;
    int p = g_perm[row];
    const float* r = W1 + (size_t)row * DIN;
    float4 v = ((const float4*)r)[tid];
    float amax = fmaxf(fmaxf(fabsf(v.x), fabsf(v.y)), fmaxf(fabsf(v.z), fabsf(v.w)));
    __shared__ float red[256];
    red[tid] = amax; __syncthreads();
    for (int s = 128; s; s >>= 1) {
        if (tid < s) red[tid] = fmaxf(red[tid], red[tid + s]);
        __syncthreads();
    }
    float scale = fmaxf(red[0], 1e-5f) / 127.f;
    if (tid == 0) {
        g_swp[p] = scale;
        g_b1p[p] = b1[row];
        g_qbp[p] = g_qb[row];
        g_cntp[p] = g_counts[row];
    }
    float e[4] = {v.x, v.y, v.z, v.w};
    __half2 h2[2];
    uint32_t qp = 0;
#pragma unroll
    for (int k = 0; k < 4; k++) {
        __half hb = __float2half(e[k]);
        int iq = (int)fminf(127.f, fmaxf(-128.f, rintf(e[k] / scale)));
        qp |= ((uint32_t)(iq & 0xFF)) << (k * 8);
        if (k & 1) h2[k>>1].y = hb;
        else       h2[k>>1].x = hb;
    }
    size_t o = (size_t)p * DIN + tid * 4;
    *(uint2*)(g_w1h + o) = make_uint2(*(uint32_t*)&h2[0], *(uint32_t*)&h2[1]);
    *(uint32_t*)(g_wq + o) = qp;
}

__global__ void prep_w2_kernel(const float* __restrict__ W2) {
    int row = blockIdx.x, tid = threadIdx.x;
    const float* r = W2 + (size_t)row * HID;
#pragma unroll
    for (int j = 0; j < 4; j++) {
        int nc = (tid + 256 * j) * 4;
        float e[4];
#pragma unroll
        for (int k = 0; k < 4; k++) e[k] = r[g_inv[nc + k]];
        __half2 h2[2];
#pragma unroll
        for (int k = 0; k < 4; k++) {
            __half hb = __float2half(e[k]);
            if (k & 1) h2[k>>1].y = hb;
            else       h2[k>>1].x = hb;
        }
        size_t o = (size_t)row * HID + nc;
        *(uint2*)(g_w2h + o) = make_uint2(*(uint32_t*)&h2[0], *(uint32_t*)&h2[1]);
    }
}

__global__ void prep_b1_kernel(const float* __restrict__ b1) {
    __shared__ float red[256];
    int tid = threadIdx.x;
    float amax = 0.f;
    for (int i = tid; i < HID; i += 256) amax = fmaxf(amax, fabsf(b1[i]));
    red[tid] = amax; __syncthreads();
    for (int s = 128; s; s >>= 1) {
        if (tid < s) red[tid] = fmaxf(red[tid], red[tid + s]);
        __syncthreads();
    }
    float scale = fmaxf(red[0], 1e-5f) / 127.f;
    for (int i = tid; i < HID; i += 256) {
        g_qb[i] = fminf(127.f, fmaxf(-128.f, rintf(b1[i] / scale))) * scale;
        g_counts[i] = 0;
    }
}

// ---------------- launch -----------------------------------------------------------
extern "C" void kernel_launch(void* const* d_in, const int* in_sizes, int n_in,
                              void* d_out, int out_size) {
    const float* x  = (const float*)d_in[0];
    const float* W1 = (const float*)d_in[1];
    const float* b1 = (const float*)d_in[2];
    const float* W2 = (const float*)d_in[3];
    const float* b2 = (const float*)d_in[4];
    float* out = (float*)d_out;

    const int SM_G1 = 3 * G1_STG + 256;    // 98560
    const int SM_TK = 2 * 4 * BUF + 256;   // 147712
    const int SM_G2 = 3 * 2 * BUF + 256;   // 110848
    cudaFuncSetAttribute(g1_kernel,   cudaFuncAttributeMaxDynamicSharedMemorySize, SM_G1);
    cudaFuncSetAttribute(topk_kernel, cudaFuncAttributeMaxDynamicSharedMemorySize, SM_TK);
    cudaFuncSetAttribute(g2_kernel,   cudaFuncAttributeMaxDynamicSharedMemorySize, SM_G2);

    prep_b1_kernel<<<1, 256>>>(b1);
    prep_x_kernel<<<NTOK, 256>>>(x);
    prep_w1t_kernel<<<HID, 128>>>(W1);

    dim3 gt(HID / 128, NTOK / 128);        // (32, 64)
    topk_kernel<<<gt, 512, SM_TK>>>(b1);

    perm_build_kernel<<<1, 1024>>>();
    prep_w1_kernel<<<HID, 256>>>(W1, b1);
    prep_w2_kernel<<<DIN, 256>>>(W2);

    g1_kernel<<<gt, 512, SM_G1>>>();
    dim3 gg2(DIN / 128, NTOK / 128);       // (8, 64)
    g2_kernel<<<gg2, 512, SM_G2>>>(b2, out);
}